// round 3
// baseline (speedup 1.0000x reference)
#include <cuda_runtime.h>
#include <math.h>

// Problem constants (dataset is fixed)
#define NMAX   200000
#define F      256
#define KGM    8         // K (gaussian mixture components)
#define M      128
#define KM     1024      // K*M
#define ATT    128

// kernel-1 tiling
#define TB     512       // threads per block
#define NODES  32        // nodes per block
#define KC     4         // k-chunk of g held in smem

// scratch (static device allocations are the sanctioned scratch mechanism)
__device__ float g_H[(size_t)NMAX * M];      // H[n, m]
__device__ float g_scores[NMAX];             // per-node attention score
__device__ int   g_is64;                     // batch dtype flag

// ---------------------------------------------------------------------------
// batch dtype sniffer: if batch is int64, int32-word at index n-1 (odd) is the
// high word of element (n-1)/2 == 0. If int32, it's the max graph id (!=0).
// ---------------------------------------------------------------------------
__global__ void sniff_kernel(const int* __restrict__ batch32, int n) {
    g_is64 = (batch32[n - 1] == 0) ? 1 : 0;
}

__device__ __forceinline__ int batch_at(const void* b, int i, int is64) {
    if (is64) return (int)((const long long*)b)[i];
    return ((const int*)b)[i];
}

// ---------------------------------------------------------------------------
// Kernel 1: per-node fused compute.
//   out[n,1024] = x[n,:] @ g            (fp32 GEMM, 32 nodes x 1024 cols/block)
//   gauss chain -> H[n,128]
//   a = tanh(H @ w1^T); score = a . w2
// Thread map (GEMM): tc = tid&63 (64 col threads), tn = tid>>6 (8 groups of 4
// rows). Thread owns cols {tc + 64*j, j=0..15}; since col = k*128+m, that is
// exactly k=0..7 for m=tc (j even) and m=tc+64 (j odd) -> gaussian sum over K
// is thread-local.
// ---------------------------------------------------------------------------
__global__ __launch_bounds__(TB, 1)
void node_kernel(const float* __restrict__ x,
                 const float* __restrict__ g,
                 const float* __restrict__ mu,
                 const float* __restrict__ sigma,
                 const float* __restrict__ w1,
                 const float* __restrict__ w2,
                 float* __restrict__ Hout,
                 float* __restrict__ scores,
                 int n)
{
    __shared__ float sbuf[4352];            // g chunk [KC][1024] (16KB) reused as w1 chunk [128][33]
    __shared__ float sx[NODES][KC];
    __shared__ float sH[NODES][M];

    const int tid = threadIdx.x;
    const int tc  = tid & 63;
    const int tn  = tid >> 6;               // 0..7
    const int node0 = blockIdx.x * NODES;

    float acc[4][16];
    #pragma unroll
    for (int ri = 0; ri < 4; ri++)
        #pragma unroll
        for (int j = 0; j < 16; j++) acc[ri][j] = 0.f;

    // ---- GEMM: out = x @ g over 64 k-chunks of KC=4 ----
    for (int kk = 0; kk < F; kk += KC) {
        __syncthreads();
        {   // load g chunk: KC*1024 floats = 1024 float4
            const float4* gsrc = (const float4*)(g + (size_t)kk * KM);
            float4* dst = (float4*)sbuf;
            #pragma unroll
            for (int i = 0; i < (KC * KM) / 4 / TB; i++)
                dst[tid + i * TB] = gsrc[tid + i * TB];
        }
        if (tid < NODES * KC) {             // load x tile 32 x 4
            int r = tid / KC, c = tid % KC;
            int nr = node0 + r;
            sx[r][c] = (nr < n) ? x[(size_t)nr * F + kk + c] : 0.f;
        }
        __syncthreads();

        #pragma unroll
        for (int k = 0; k < KC; k++) {
            float xv[4];
            #pragma unroll
            for (int ri = 0; ri < 4; ri++) xv[ri] = sx[tn * 4 + ri][k];
            float gv[16];
            #pragma unroll
            for (int j = 0; j < 16; j++) gv[j] = sbuf[k * KM + tc + 64 * j];
            #pragma unroll
            for (int ri = 0; ri < 4; ri++)
                #pragma unroll
                for (int j = 0; j < 16; j++)
                    acc[ri][j] = fmaf(xv[ri], gv[j], acc[ri][j]);
        }
    }

    // ---- Gaussian chain -> H (thread-local over K) ----
    float muv[16], s2v[16];
    #pragma unroll
    for (int j = 0; j < 16; j++) {
        int kk2 = j >> 1;
        int m   = tc + 64 * (j & 1);
        float s = sigma[kk2 * M + m];
        muv[j] = mu[kk2 * M + m];
        s2v[j] = 1e-15f + s * s;
    }
    #pragma unroll
    for (int ri = 0; ri < 4; ri++) {
        float Ha = 0.f, Hb = 0.f;
        #pragma unroll
        for (int j = 0; j < 16; j++) {
            float o = acc[ri][j];
            float d = o - muv[j];
            float gs = expf(-0.5f * d * d / s2v[j]);
            if (j & 1) Hb = fmaf(o, gs, Hb);
            else       Ha = fmaf(o, gs, Ha);
        }
        int r = tn * 4 + ri;
        sH[r][tc]      = Ha;
        sH[r][tc + 64] = Hb;
        int nr = node0 + r;
        if (nr < n) {
            Hout[(size_t)nr * M + tc]      = Ha;
            Hout[(size_t)nr * M + tc + 64] = Hb;
        }
    }

    // ---- attention score: a = tanh(H @ w1^T), score = a . w2 ----
    const int tt = tid & 15;                // 16 t-threads per node
    const int nd = tid >> 4;                // 0..31 node
    float part = 0.f;
    for (int c4 = 0; c4 < 4; c4++) {        // 4 chunks of 32 rows of w1
        __syncthreads();                    // previous sbuf readers done / sH visible
        const int t0 = c4 * 32;
        for (int i = tid; i < 32 * M; i += TB) {
            int tl = i >> 7, m = i & 127;
            sbuf[m * 33 + tl] = w1[(size_t)(t0 + tl) * M + m];   // transposed, pad 33
        }
        __syncthreads();
        #pragma unroll
        for (int u = 0; u < 2; u++) {
            int tl = tt * 2 + u;
            float dot = 0.f;
            #pragma unroll 8
            for (int m = 0; m < M; m++)
                dot = fmaf(sH[nd][m], sbuf[m * 33 + tl], dot);
            part += tanhf(dot) * w2[t0 + tl];
        }
    }
    // reduce 16 partials per node (lanes 0-15 / 16-31 are one node each)
    #pragma unroll
    for (int off = 8; off; off >>= 1)
        part += __shfl_down_sync(0xffffffffu, part, off, 16);
    if (tt == 0) {
        int nr = node0 + nd;
        if (nr < n) scores[nr] = part;
    }
}

// ---------------------------------------------------------------------------
// Kernel 2: per-graph segment softmax + weighted pooling. batch is sorted, so
// block g binary-searches its node range; no atomics.
// ---------------------------------------------------------------------------
__global__ __launch_bounds__(128)
void pool_kernel(const float* __restrict__ H,
                 const float* __restrict__ scores,
                 const void* __restrict__ batch,
                 int n,
                 float* __restrict__ out)
{
    const int gidx = blockIdx.x;
    const int tid  = threadIdx.x;           // 0..127 == m
    const int is64 = g_is64;

    // lower_bound(batch, gidx) and lower_bound(batch, gidx+1)
    int start, end;
    {
        int lo = 0, hi = n;
        while (lo < hi) { int mid = (lo + hi) >> 1; if (batch_at(batch, mid, is64) < gidx) lo = mid + 1; else hi = mid; }
        start = lo;
        hi = n;
        while (lo < hi) { int mid = (lo + hi) >> 1; if (batch_at(batch, mid, is64) < gidx + 1) lo = mid + 1; else hi = mid; }
        end = lo;
    }

    if (start >= end) { out[(size_t)gidx * M + tid] = 0.f; return; }

    __shared__ float red[128];

    // segment max
    float mx = -INFINITY;
    for (int i = start + tid; i < end; i += 128) mx = fmaxf(mx, scores[i]);
    red[tid] = mx; __syncthreads();
    #pragma unroll
    for (int s = 64; s; s >>= 1) { if (tid < s) red[tid] = fmaxf(red[tid], red[tid + s]); __syncthreads(); }
    mx = red[0]; __syncthreads();

    // segment sum of exp
    float sm = 0.f;
    for (int i = start + tid; i < end; i += 128) sm += expf(scores[i] - mx);
    red[tid] = sm; __syncthreads();
    #pragma unroll
    for (int s = 64; s; s >>= 1) { if (tid < s) red[tid] += red[tid + s]; __syncthreads(); }
    sm = red[0];
    const float inv = 1.f / (sm + 1e-16f);

    // weighted sum of H (thread = column m, coalesced rows)
    float acc = 0.f;
    for (int i = start; i < end; i++) {
        float w = expf(scores[i] - mx);
        acc = fmaf(w, H[(size_t)i * M + tid], acc);
    }
    out[(size_t)gidx * M + tid] = acc * inv;
}

// ---------------------------------------------------------------------------
extern "C" void kernel_launch(void* const* d_in, const int* in_sizes, int n_in,
                              void* d_out, int out_size)
{
    const float* x     = (const float*)d_in[0];
    const float* g     = (const float*)d_in[1];
    const float* mu    = (const float*)d_in[2];
    const float* sigma = (const float*)d_in[3];
    const float* w1    = (const float*)d_in[4];
    const float* w2    = (const float*)d_in[5];
    const void*  batch = d_in[6];

    int n = in_sizes[0] / F;
    if (n > NMAX) n = NMAX;
    int num_graphs = out_size / M;

    float* Hg; cudaGetSymbolAddress((void**)&Hg, g_H);
    float* Sg; cudaGetSymbolAddress((void**)&Sg, g_scores);

    node_kernel<<<(n + NODES - 1) / NODES, TB>>>(x, g, mu, sigma, w1, w2, Hg, Sg, n);
    sniff_kernel<<<1, 1>>>((const int*)batch, n);
    pool_kernel<<<num_graphs, 128>>>(Hg, Sg, batch, n, (float*)d_out);
}

// round 4
// speedup vs baseline: 1.0030x; 1.0030x over previous
#include <cuda_runtime.h>
#include <math.h>

// Problem constants (dataset is fixed)
#define NMAX   200000
#define F      256
#define KGM    8         // K (gaussian mixture components)
#define M      128
#define KM     1024      // K*M
#define ATT    128

// kernel-1 tiling
#define TB     512       // threads per block
#define NODES  32        // nodes per block
#define KC     4         // k-chunk of g held in smem

// scratch (static device allocations are the sanctioned scratch mechanism)
__device__ float g_H[(size_t)NMAX * M];      // H[n, m]
__device__ float g_scores[NMAX];             // per-node attention score
__device__ int   g_is64;                     // batch dtype flag

// ---------------------------------------------------------------------------
// batch dtype sniffer: if batch is int64, int32-word at index n-1 (odd) is the
// high word of element (n-1)/2 == 0. If int32, it's the max graph id (!=0).
// ---------------------------------------------------------------------------
__global__ void sniff_kernel(const int* __restrict__ batch32, int n) {
    g_is64 = (batch32[n - 1] == 0) ? 1 : 0;
}

__device__ __forceinline__ int batch_at(const void* b, int i, int is64) {
    if (is64) return (int)((const long long*)b)[i];
    return ((const int*)b)[i];
}

// ---------------------------------------------------------------------------
// Kernel 1: per-node fused compute.
//   out[n,1024] = x[n,:] @ g            (fp32 GEMM, 32 nodes x 1024 cols/block)
//   gauss chain -> H[n,128]
//   a = tanh(H @ w1^T); score = a . w2
// Thread map (GEMM): tc = tid&63 (64 col threads), tn = tid>>6 (8 groups of 4
// rows). Thread owns cols {tc + 64*j, j=0..15}; since col = k*128+m, that is
// exactly k=0..7 for m=tc (j even) and m=tc+64 (j odd) -> gaussian sum over K
// is thread-local.
// ---------------------------------------------------------------------------
__global__ __launch_bounds__(TB, 1)
void node_kernel(const float* __restrict__ x,
                 const float* __restrict__ g,
                 const float* __restrict__ mu,
                 const float* __restrict__ sigma,
                 const float* __restrict__ w1,
                 const float* __restrict__ w2,
                 float* __restrict__ Hout,
                 float* __restrict__ scores,
                 int n)
{
    __shared__ float sbuf[4352];            // g chunk [KC][1024] (16KB) reused as w1 chunk [128][33]
    __shared__ float sx[NODES][KC];
    __shared__ float sH[NODES][M];

    const int tid = threadIdx.x;
    const int tc  = tid & 63;
    const int tn  = tid >> 6;               // 0..7
    const int node0 = blockIdx.x * NODES;

    float acc[4][16];
    #pragma unroll
    for (int ri = 0; ri < 4; ri++)
        #pragma unroll
        for (int j = 0; j < 16; j++) acc[ri][j] = 0.f;

    // ---- GEMM: out = x @ g over 64 k-chunks of KC=4 ----
    for (int kk = 0; kk < F; kk += KC) {
        __syncthreads();
        {   // load g chunk: KC*1024 floats = 1024 float4
            const float4* gsrc = (const float4*)(g + (size_t)kk * KM);
            float4* dst = (float4*)sbuf;
            #pragma unroll
            for (int i = 0; i < (KC * KM) / 4 / TB; i++)
                dst[tid + i * TB] = gsrc[tid + i * TB];
        }
        if (tid < NODES * KC) {             // load x tile 32 x 4
            int r = tid / KC, c = tid % KC;
            int nr = node0 + r;
            sx[r][c] = (nr < n) ? x[(size_t)nr * F + kk + c] : 0.f;
        }
        __syncthreads();

        #pragma unroll
        for (int k = 0; k < KC; k++) {
            float xv[4];
            #pragma unroll
            for (int ri = 0; ri < 4; ri++) xv[ri] = sx[tn * 4 + ri][k];
            float gv[16];
            #pragma unroll
            for (int j = 0; j < 16; j++) gv[j] = sbuf[k * KM + tc + 64 * j];
            #pragma unroll
            for (int ri = 0; ri < 4; ri++)
                #pragma unroll
                for (int j = 0; j < 16; j++)
                    acc[ri][j] = fmaf(xv[ri], gv[j], acc[ri][j]);
        }
    }

    // ---- Gaussian chain -> H (thread-local over K) ----
    float muv[16], s2v[16];
    #pragma unroll
    for (int j = 0; j < 16; j++) {
        int kk2 = j >> 1;
        int m   = tc + 64 * (j & 1);
        float s = sigma[kk2 * M + m];
        muv[j] = mu[kk2 * M + m];
        s2v[j] = 1e-15f + s * s;
    }
    #pragma unroll
    for (int ri = 0; ri < 4; ri++) {
        float Ha = 0.f, Hb = 0.f;
        #pragma unroll
        for (int j = 0; j < 16; j++) {
            float o = acc[ri][j];
            float d = o - muv[j];
            float gs = expf(-0.5f * d * d / s2v[j]);
            if (j & 1) Hb = fmaf(o, gs, Hb);
            else       Ha = fmaf(o, gs, Ha);
        }
        int r = tn * 4 + ri;
        sH[r][tc]      = Ha;
        sH[r][tc + 64] = Hb;
        int nr = node0 + r;
        if (nr < n) {
            Hout[(size_t)nr * M + tc]      = Ha;
            Hout[(size_t)nr * M + tc + 64] = Hb;
        }
    }

    // ---- attention score: a = tanh(H @ w1^T), score = a . w2 ----
    const int tt = tid & 15;                // 16 t-threads per node
    const int nd = tid >> 4;                // 0..31 node
    float part = 0.f;
    for (int c4 = 0; c4 < 4; c4++) {        // 4 chunks of 32 rows of w1
        __syncthreads();                    // previous sbuf readers done / sH visible
        const int t0 = c4 * 32;
        for (int i = tid; i < 32 * M; i += TB) {
            int tl = i >> 7, m = i & 127;
            sbuf[m * 33 + tl] = w1[(size_t)(t0 + tl) * M + m];   // transposed, pad 33
        }
        __syncthreads();
        #pragma unroll
        for (int u = 0; u < 2; u++) {
            int tl = tt * 2 + u;
            float dot = 0.f;
            #pragma unroll 8
            for (int m = 0; m < M; m++)
                dot = fmaf(sH[nd][m], sbuf[m * 33 + tl], dot);
            part += tanhf(dot) * w2[t0 + tl];
        }
    }
    // reduce 16 partials per node (lanes 0-15 / 16-31 are one node each)
    #pragma unroll
    for (int off = 8; off; off >>= 1)
        part += __shfl_down_sync(0xffffffffu, part, off, 16);
    if (tt == 0) {
        int nr = node0 + nd;
        if (nr < n) scores[nr] = part;
    }
}

// ---------------------------------------------------------------------------
// Kernel 2: per-graph segment softmax + weighted pooling. batch is sorted, so
// block g binary-searches its node range; no atomics.
// ---------------------------------------------------------------------------
__global__ __launch_bounds__(128)
void pool_kernel(const float* __restrict__ H,
                 const float* __restrict__ scores,
                 const void* __restrict__ batch,
                 int n,
                 float* __restrict__ out)
{
    const int gidx = blockIdx.x;
    const int tid  = threadIdx.x;           // 0..127 == m
    const int is64 = g_is64;

    // lower_bound(batch, gidx) and lower_bound(batch, gidx+1)
    int start, end;
    {
        int lo = 0, hi = n;
        while (lo < hi) { int mid = (lo + hi) >> 1; if (batch_at(batch, mid, is64) < gidx) lo = mid + 1; else hi = mid; }
        start = lo;
        hi = n;
        while (lo < hi) { int mid = (lo + hi) >> 1; if (batch_at(batch, mid, is64) < gidx + 1) lo = mid + 1; else hi = mid; }
        end = lo;
    }

    if (start >= end) { out[(size_t)gidx * M + tid] = 0.f; return; }

    __shared__ float red[128];

    // segment max
    float mx = -INFINITY;
    for (int i = start + tid; i < end; i += 128) mx = fmaxf(mx, scores[i]);
    red[tid] = mx; __syncthreads();
    #pragma unroll
    for (int s = 64; s; s >>= 1) { if (tid < s) red[tid] = fmaxf(red[tid], red[tid + s]); __syncthreads(); }
    mx = red[0]; __syncthreads();

    // segment sum of exp
    float sm = 0.f;
    for (int i = start + tid; i < end; i += 128) sm += expf(scores[i] - mx);
    red[tid] = sm; __syncthreads();
    #pragma unroll
    for (int s = 64; s; s >>= 1) { if (tid < s) red[tid] += red[tid + s]; __syncthreads(); }
    sm = red[0];
    const float inv = 1.f / (sm + 1e-16f);

    // weighted sum of H (thread = column m, coalesced rows)
    float acc = 0.f;
    for (int i = start; i < end; i++) {
        float w = expf(scores[i] - mx);
        acc = fmaf(w, H[(size_t)i * M + tid], acc);
    }
    out[(size_t)gidx * M + tid] = acc * inv;
}

// ---------------------------------------------------------------------------
extern "C" void kernel_launch(void* const* d_in, const int* in_sizes, int n_in,
                              void* d_out, int out_size)
{
    const float* x     = (const float*)d_in[0];
    const float* g     = (const float*)d_in[1];
    const float* mu    = (const float*)d_in[2];
    const float* sigma = (const float*)d_in[3];
    const float* w1    = (const float*)d_in[4];
    const float* w2    = (const float*)d_in[5];
    const void*  batch = d_in[6];

    int n = in_sizes[0] / F;
    if (n > NMAX) n = NMAX;
    int num_graphs = out_size / M;

    float* Hg; cudaGetSymbolAddress((void**)&Hg, g_H);
    float* Sg; cudaGetSymbolAddress((void**)&Sg, g_scores);

    node_kernel<<<(n + NODES - 1) / NODES, TB>>>(x, g, mu, sigma, w1, w2, Hg, Sg, n);
    sniff_kernel<<<1, 1>>>((const int*)batch, n);
    pool_kernel<<<num_graphs, 128>>>(Hg, Sg, batch, n, (float*)d_out);
}

// round 6
// speedup vs baseline: 3.6845x; 3.6736x over previous
#include <cuda_runtime.h>
#include <math.h>
#include <stdint.h>

#define F      256
#define M      128
#define NMAX   200000
#define NB     64          // nodes per CTA
#define TPB    256

__device__ float g_H[(size_t)NMAX * M];
__device__ float g_scores[NMAX];
__device__ __align__(128) unsigned char g_Bimg[32 * 32768]; // [q][hi 16K|lo 16K], rows n:128 x 128B (64 bf16 k)
__device__ __align__(128) unsigned char g_W1img[65536];     // [hi 32K|lo 32K], rows att:128 x 256B (128 bf16 m)
__device__ int g_is64;

// smem layout (dynamic)
#define SO_A2   0
#define SO_B2   4096
#define SO_C2   8192
#define SO_W2   12288
#define SO_XA   13312      // A image: hi 64x528, lo at +33792
#define XA_LO   33792
#define SO_STG  80896      // 2 stages x 69632 (Bhi 128x272 | Blo)
#define STG_SZ  69632
#define BLO     34816
#define SMEM_BYTES 220160

__device__ __forceinline__ uint32_t smem_u32(const void* p) {
    uint32_t a;
    asm("{ .reg .u64 t; cvta.to.shared.u64 t, %1; cvt.u32.u64 %0, t; }" : "=r"(a) : "l"(p));
    return a;
}
__device__ __forceinline__ void cp16(uint32_t dst, const void* src) {
    asm volatile("cp.async.cg.shared.global [%0], [%1], 16;" :: "r"(dst), "l"(src) : "memory");
}
#define CP_COMMIT() asm volatile("cp.async.commit_group;" ::: "memory")
#define CP_WAIT0()  asm volatile("cp.async.wait_group 0;" ::: "memory")
#define CP_WAIT1()  asm volatile("cp.async.wait_group 1;" ::: "memory")

__device__ __forceinline__ void ldmx4(uint32_t r[4], uint32_t addr) {
    asm volatile("ldmatrix.sync.aligned.m8n8.x4.shared.b16 {%0,%1,%2,%3}, [%4];"
        : "=r"(r[0]), "=r"(r[1]), "=r"(r[2]), "=r"(r[3]) : "r"(addr));
}
__device__ __forceinline__ void mma_bf16(float* d, const uint32_t* a, uint32_t b0, uint32_t b1) {
    asm volatile("mma.sync.aligned.m16n8k16.row.col.f32.bf16.bf16.f32 "
        "{%0,%1,%2,%3}, {%4,%5,%6,%7}, {%8,%9}, {%0,%1,%2,%3};"
        : "+f"(d[0]), "+f"(d[1]), "+f"(d[2]), "+f"(d[3])
        : "r"(a[0]), "r"(a[1]), "r"(a[2]), "r"(a[3]), "r"(b0), "r"(b1));
}

__device__ __forceinline__ void hilo(float a, float b, uint32_t& ph, uint32_t& pl) {
    asm("cvt.rn.bf16x2.f32 %0, %1, %2;" : "=r"(ph) : "f"(b), "f"(a));   // low=a, high=b
    float r0 = a - __uint_as_float(ph << 16);
    float r1 = b - __uint_as_float(ph & 0xffff0000u);
    asm("cvt.rn.bf16x2.f32 %0, %1, %2;" : "=r"(pl) : "f"(r1), "f"(r0));
}

// 2^y for y <= 0, FMA-pipe only; magic-add round-to-nearest + deg-5 poly on [-.5,.5]
__device__ __forceinline__ float exp2p(float y) {
    y = fmaxf(y, -126.0f);
    float kf = __fadd_rn(y, 12582912.0f);
    int j = __float_as_int(kf) - 0x4B400000;
    float f = __fsub_rn(y, __fsub_rn(kf, 12582912.0f));
    float p = 1.3333558e-3f;
    p = fmaf(p, f, 9.6181291e-3f);
    p = fmaf(p, f, 5.5504109e-2f);
    p = fmaf(p, f, 2.4022651e-1f);
    p = fmaf(p, f, 6.9314718e-1f);
    p = fmaf(p, f, 1.0f);
    return p * __int_as_float((j + 127) << 23);
}
__device__ __forceinline__ float tanh_fast(float x) {
    float t = exp2p(-2.8853901f * fabsf(x));
    float a = 1.0f + t;
    float r = fmaf(-0.470588f, a, 1.411765f);
    r = r * (2.0f - a * r);
    r = r * (2.0f - a * r);
    r = r * (2.0f - a * r);
    return copysignf((1.0f - t) * r, x);
}

// ---- prep: B images of g (rows n, 64 bf16 k per image row), hi/lo split ----
__global__ void prep_g(const float* __restrict__ g) {
    int t = blockIdx.x * 256 + threadIdx.x;      // 131072
    int q = t >> 12, r = t & 4095;
    int kp = r >> 7, nr = r & 127;               // kp: k pair 0..31, nr: n row
    int kb = (q & 3) * 64 + kp * 2;
    int nn = (q >> 2) * 128 + nr;
    uint32_t ph, pl;
    hilo(g[(size_t)kb * 1024 + nn], g[(size_t)(kb + 1) * 1024 + nn], ph, pl);
    unsigned char* base = g_Bimg + (size_t)q * 32768;
    *(uint32_t*)(base + nr * 128 + kp * 4) = ph;
    *(uint32_t*)(base + 16384 + nr * 128 + kp * 4) = pl;
}
// ---- prep: w1 images (rows att, 128 bf16 m), hi/lo ----
__global__ void prep_w1(const float* __restrict__ w1) {
    int t = blockIdx.x * 256 + threadIdx.x;      // 8192
    int att = t >> 6, mp = t & 63;
    uint32_t ph, pl;
    hilo(w1[att * 128 + 2 * mp], w1[att * 128 + 2 * mp + 1], ph, pl);
    *(uint32_t*)(g_W1img + att * 256 + mp * 4) = ph;
    *(uint32_t*)(g_W1img + 32768 + att * 256 + mp * 4) = pl;
}
__global__ void sniff_kernel(const int* __restrict__ b32, int n) {
    g_is64 = (b32[n - 1] == 0) ? 1 : 0;
}
__device__ __forceinline__ int batch_at(const void* b, int i, int is64) {
    if (is64) return (int)((const long long*)b)[i];
    return ((const int*)b)[i];
}

#define COPY_CHUNK(q, s) do { \
    const unsigned char* _src = g_Bimg + (size_t)(q) * 32768; \
    uint32_t _dst = sb + SO_STG + (s) * STG_SZ; \
    _Pragma("unroll") \
    for (int _j = 0; _j < 8; _j++) { \
        int _i = tid + _j * 256; \
        int _h = _i >> 10, _r = (_i >> 3) & 127, _u = _i & 7; \
        cp16(_dst + _h * BLO + _r * 272 + _u * 16, _src + _h * 16384 + _r * 128 + _u * 16); \
    } } while (0)

__global__ __launch_bounds__(TPB, 1)
void node_kernel(const float* __restrict__ x,
                 const float* __restrict__ mu,
                 const float* __restrict__ sigma,
                 const float* __restrict__ w2g,
                 float* __restrict__ Hout,
                 float* __restrict__ scores, int n)
{
    extern __shared__ unsigned char smem[];
    float* sA2 = (float*)(smem + SO_A2);
    float* sB2 = (float*)(smem + SO_B2);
    float* sC2 = (float*)(smem + SO_C2);
    float* sW2 = (float*)(smem + SO_W2);
    const uint32_t sb = smem_u32(smem);
    const int tid = threadIdx.x, lane = tid & 31, wid = tid >> 5;
    const int mg = wid >> 1, cw = wid & 1;
    const int node0 = blockIdx.x * NB;

    // gaussian consts: exp(-.5 (o-mu)^2/s2) = 2^(A2 o^2 + B2 o + C2)
    for (int i = tid; i < 1024; i += TPB) {
        float s = sigma[i], m_ = mu[i];
        float cc = -0.72134752f / fmaf(s, s, 1e-15f);
        sA2[i] = cc; sB2[i] = -2.f * cc * m_; sC2[i] = cc * m_ * m_;
    }
    if (tid < 128) sW2[tid] = w2g[tid];

    // A image: x[64 nodes][256] -> bf16 hi/lo, padded rows (528B)
    #pragma unroll
    for (int j = 0; j < 32; j++) {
        int i = tid + j * 256;
        int node = i >> 7, kp = i & 127;
        int ng = node0 + node;
        float2 v = make_float2(0.f, 0.f);
        if (ng < n) v = *(const float2*)(x + (size_t)ng * F + kp * 2);
        uint32_t ph, pl; hilo(v.x, v.y, ph, pl);
        *(uint32_t*)(smem + SO_XA + node * 528 + kp * 4) = ph;
        *(uint32_t*)(smem + SO_XA + XA_LO + node * 528 + kp * 4) = pl;
    }
    COPY_CHUNK(0, 0); CP_COMMIT();
    COPY_CHUNK(1, 1); CP_COMMIT();
    __syncthreads();

    float H[32], D[32];
    #pragma unroll
    for (int i = 0; i < 32; i++) H[i] = 0.f;

    const int rsel = lane & 15, usel = lane >> 4;
    const uint32_t aRow = sb + SO_XA + (mg * 16 + rsel) * 528 + usel * 16;
    const uint32_t bRow = (cw * 64 + rsel) * 272 + usel * 16;

    for (int c = 0; c < 32; c++) {
        const int p = c >> 2, kc = c & 3, s = c & 1;
        if (c == 31) { CP_WAIT0(); } else { CP_WAIT1(); }
        __syncthreads();
        if (kc == 0) {
            #pragma unroll
            for (int i = 0; i < 32; i++) D[i] = 0.f;
        }
        const uint32_t sbase = sb + SO_STG + s * STG_SZ + bRow;
        #pragma unroll
        for (int kt = 0; kt < 4; kt++) {
            uint32_t ah[4], al[4];
            ldmx4(ah, aRow + (kc * 8 + kt * 2) * 16);
            ldmx4(al, aRow + XA_LO + (kc * 8 + kt * 2) * 16);
            #pragma unroll
            for (int nt16 = 0; nt16 < 4; nt16++) {
                uint32_t bh[4], bl[4];
                uint32_t ba = sbase + nt16 * (16 * 272) + kt * 32;
                ldmx4(bh, ba); ldmx4(bl, ba + BLO);
                #pragma unroll
                for (int e = 0; e < 2; e++) {
                    float* d = D + (nt16 * 2 + e) * 4;
                    mma_bf16(d, ah, bh[e], bh[2 + e]);
                    mma_bf16(d, ah, bl[e], bl[2 + e]);
                    mma_bf16(d, al, bh[e], bh[2 + e]);
                }
            }
        }
        __syncthreads();
        if (c + 2 < 32) { COPY_CHUNK(c + 2, s); CP_COMMIT(); }
        if (kc == 3) {
            #pragma unroll
            for (int t = 0; t < 8; t++) {
                int nidx = p * 128 + cw * 64 + t * 8 + (lane & 3) * 2;
                float2 a2 = *(float2*)(sA2 + nidx);
                float2 b2 = *(float2*)(sB2 + nidx);
                float2 c2 = *(float2*)(sC2 + nidx);
                float o;
                o = D[t*4+0]; H[t*4+0] = fmaf(o, exp2p(fmaf(fmaf(a2.x, o, b2.x), o, c2.x)), H[t*4+0]);
                o = D[t*4+1]; H[t*4+1] = fmaf(o, exp2p(fmaf(fmaf(a2.y, o, b2.y), o, c2.y)), H[t*4+1]);
                o = D[t*4+2]; H[t*4+2] = fmaf(o, exp2p(fmaf(fmaf(a2.x, o, b2.x), o, c2.x)), H[t*4+2]);
                o = D[t*4+3]; H[t*4+3] = fmaf(o, exp2p(fmaf(fmaf(a2.y, o, b2.y), o, c2.y)), H[t*4+3]);
            }
        }
    }

    // H -> gmem (fp32)
    {
        int r0 = node0 + mg * 16 + (lane >> 2);
        #pragma unroll
        for (int t = 0; t < 8; t++) {
            int colb = cw * 64 + t * 8 + (lane & 3) * 2;
            if (r0 < n)     *(float2*)(Hout + (size_t)r0 * M + colb)       = make_float2(H[t*4+0], H[t*4+1]);
            if (r0 + 8 < n) *(float2*)(Hout + (size_t)(r0 + 8) * M + colb) = make_float2(H[t*4+2], H[t*4+3]);
        }
    }
    __syncthreads();   // stage smem free for H/w1 images

    // H image (bf16 hi/lo) at SO_STG, w1 images at SO_STG+34816
    {
        int lr0 = mg * 16 + (lane >> 2);
        #pragma unroll
        for (int t = 0; t < 8; t++) {
            int colb = cw * 64 + t * 8 + (lane & 3) * 2;
            uint32_t ph, pl;
            hilo(H[t*4+0], H[t*4+1], ph, pl);
            *(uint32_t*)(smem + SO_STG + lr0 * 272 + colb * 2) = ph;
            *(uint32_t*)(smem + SO_STG + 17408 + lr0 * 272 + colb * 2) = pl;
            hilo(H[t*4+2], H[t*4+3], ph, pl);
            *(uint32_t*)(smem + SO_STG + (lr0 + 8) * 272 + colb * 2) = ph;
            *(uint32_t*)(smem + SO_STG + 17408 + (lr0 + 8) * 272 + colb * 2) = pl;
        }
    }
    #pragma unroll
    for (int j = 0; j < 16; j++) {
        int i = tid + j * 256;
        int h = i >> 11, r = (i >> 4) & 127, u = i & 15;
        cp16(sb + SO_STG + 34816 + h * 34816 + r * 272 + u * 16,
             g_W1img + h * 32768 + r * 256 + u * 16);
    }
    CP_COMMIT(); CP_WAIT0();
    __syncthreads();

    // attention GEMM: warps 0..3, each one 16-node group, full 128 att cols
    if (wid < 4) {
        float DA[64];
        #pragma unroll
        for (int i = 0; i < 64; i++) DA[i] = 0.f;
        const uint32_t aR = sb + SO_STG + (wid * 16 + rsel) * 272 + usel * 16;
        const uint32_t bR = sb + SO_STG + 34816 + rsel * 272 + usel * 16;
        #pragma unroll
        for (int kt = 0; kt < 8; kt++) {
            uint32_t ah[4], al[4];
            ldmx4(ah, aR + kt * 32);
            ldmx4(al, aR + 17408 + kt * 32);
            #pragma unroll
            for (int nt16 = 0; nt16 < 8; nt16++) {
                uint32_t bh[4], bl[4];
                uint32_t ba = bR + nt16 * (16 * 272) + kt * 32;
                ldmx4(bh, ba); ldmx4(bl, ba + 34816);
                #pragma unroll
                for (int e = 0; e < 2; e++) {
                    float* d = DA + (nt16 * 2 + e) * 4;
                    mma_bf16(d, ah, bh[e], bh[2 + e]);
                    mma_bf16(d, ah, bl[e], bl[2 + e]);
                    mma_bf16(d, al, bh[e], bh[2 + e]);
                }
            }
        }
        float p0 = 0.f, p1 = 0.f;
        #pragma unroll
        for (int t = 0; t < 16; t++) {
            float2 wv = *(float2*)(sW2 + t * 8 + (lane & 3) * 2);
            p0 = fmaf(tanh_fast(DA[t*4+0]), wv.x, p0);
            p0 = fmaf(tanh_fast(DA[t*4+1]), wv.y, p0);
            p1 = fmaf(tanh_fast(DA[t*4+2]), wv.x, p1);
            p1 = fmaf(tanh_fast(DA[t*4+3]), wv.y, p1);
        }
        p0 += __shfl_xor_sync(0xffffffffu, p0, 1);
        p0 += __shfl_xor_sync(0xffffffffu, p0, 2);
        p1 += __shfl_xor_sync(0xffffffffu, p1, 1);
        p1 += __shfl_xor_sync(0xffffffffu, p1, 2);
        if ((lane & 3) == 0) {
            int r = node0 + wid * 16 + (lane >> 2);
            if (r < n) scores[r] = p0;
            if (r + 8 < n) scores[r + 8] = p1;
        }
    }
}

__global__ __launch_bounds__(128)
void pool_kernel(const float* __restrict__ H,
                 const float* __restrict__ scores,
                 const void* __restrict__ batch,
                 int n, float* __restrict__ out)
{
    const int gidx = blockIdx.x, tid = threadIdx.x;
    const int is64 = g_is64;
    int start, end;
    {
        int lo = 0, hi = n;
        while (lo < hi) { int mid = (lo + hi) >> 1; if (batch_at(batch, mid, is64) < gidx) lo = mid + 1; else hi = mid; }
        start = lo; hi = n;
        while (lo < hi) { int mid = (lo + hi) >> 1; if (batch_at(batch, mid, is64) < gidx + 1) lo = mid + 1; else hi = mid; }
        end = lo;
    }
    if (start >= end) { out[(size_t)gidx * M + tid] = 0.f; return; }
    __shared__ float red[128];
    float mx = -INFINITY;
    for (int i = start + tid; i < end; i += 128) mx = fmaxf(mx, scores[i]);
    red[tid] = mx; __syncthreads();
    #pragma unroll
    for (int s = 64; s; s >>= 1) { if (tid < s) red[tid] = fmaxf(red[tid], red[tid + s]); __syncthreads(); }
    mx = red[0]; __syncthreads();
    float sm = 0.f;
    for (int i = start + tid; i < end; i += 128) sm += expf(scores[i] - mx);
    red[tid] = sm; __syncthreads();
    #pragma unroll
    for (int s = 64; s; s >>= 1) { if (tid < s) red[tid] += red[tid + s]; __syncthreads(); }
    const float inv = 1.f / (red[0] + 1e-16f);
    float acc = 0.f;
    for (int i = start; i < end; i++)
        acc = fmaf(expf(scores[i] - mx), H[(size_t)i * M + tid], acc);
    out[(size_t)gidx * M + tid] = acc * inv;
}

extern "C" void kernel_launch(void* const* d_in, const int* in_sizes, int n_in,
                              void* d_out, int out_size)
{
    const float* x     = (const float*)d_in[0];
    const float* g     = (const float*)d_in[1];
    const float* mu    = (const float*)d_in[2];
    const float* sigma = (const float*)d_in[3];
    const float* w1    = (const float*)d_in[4];
    const float* w2    = (const float*)d_in[5];
    const void*  batch = d_in[6];

    int n = in_sizes[0] / F;
    if (n > NMAX) n = NMAX;
    int num_graphs = out_size / M;

    cudaFuncSetAttribute(node_kernel, cudaFuncAttributeMaxDynamicSharedMemorySize, SMEM_BYTES);

    float* Hg; cudaGetSymbolAddress((void**)&Hg, g_H);
    float* Sg; cudaGetSymbolAddress((void**)&Sg, g_scores);

    prep_g<<<512, 256>>>(g);
    prep_w1<<<32, 256>>>(w1);
    sniff_kernel<<<1, 1>>>((const int*)batch, n);
    node_kernel<<<(n + NB - 1) / NB, TPB, SMEM_BYTES>>>(x, mu, sigma, w2, Hg, Sg, n);
    pool_kernel<<<num_graphs, 128>>>(Hg, Sg, batch, n, (float*)d_out);
}

// round 7
// speedup vs baseline: 4.3246x; 1.1737x over previous
#include <cuda_runtime.h>
#include <math.h>
#include <stdint.h>

#define F      256
#define M      128
#define NMAX   200000
#define NB     128         // nodes per CTA
#define TPB    256

__device__ float g_H[(size_t)NMAX * M];
__device__ float g_scores[NMAX];
// B images: [q=0..31] each 32KB = hi(16KB) + lo(16KB); rows n:128 x 128B (64 bf16 k), XOR-swizzled
__device__ __align__(128) unsigned char g_Bimg[32 * 32768];
// w1 image: hi 32KB + lo 32KB; rows att:128 x 256B (128 bf16 m), XOR-swizzled
__device__ __align__(128) unsigned char g_W1img[65536];
__device__ int g_is64;

// smem layout
#define SO_A2   0
#define SO_B2   4096
#define SO_C2   8192
#define SO_W2   12288
#define SO_XA   13312      // A image: hi 64KB, lo at +65536 (rows node:128 x 512B swizzled)
#define XA_LO   65536
#define SO_STG  144384     // 2 stages x 32768
#define STG_SZ  32768
#define B_LO    16384
#define SO_HI   SO_STG     // attention phase: H image hi 32KB, lo +32768
#define H_LO    32768
#define SMEM_BYTES 209920

__device__ __forceinline__ uint32_t smem_u32(const void* p) {
    uint32_t a;
    asm("{ .reg .u64 t; cvta.to.shared.u64 t, %1; cvt.u32.u64 %0, t; }" : "=r"(a) : "l"(p));
    return a;
}
__device__ __forceinline__ void cp16(uint32_t dst, const void* src) {
    asm volatile("cp.async.cg.shared.global [%0], [%1], 16;" :: "r"(dst), "l"(src) : "memory");
}
#define CP_COMMIT() asm volatile("cp.async.commit_group;" ::: "memory")
#define CP_WAIT0()  asm volatile("cp.async.wait_group 0;" ::: "memory")
#define CP_WAIT1()  asm volatile("cp.async.wait_group 1;" ::: "memory")

__device__ __forceinline__ void ldmx4(uint32_t r[4], uint32_t addr) {
    asm volatile("ldmatrix.sync.aligned.m8n8.x4.shared.b16 {%0,%1,%2,%3}, [%4];"
        : "=r"(r[0]), "=r"(r[1]), "=r"(r[2]), "=r"(r[3]) : "r"(addr));
}
__device__ __forceinline__ void mma_bf16(float* d, const uint32_t* a, uint32_t b0, uint32_t b1) {
    asm volatile("mma.sync.aligned.m16n8k16.row.col.f32.bf16.bf16.f32 "
        "{%0,%1,%2,%3}, {%4,%5,%6,%7}, {%8,%9}, {%0,%1,%2,%3};"
        : "+f"(d[0]), "+f"(d[1]), "+f"(d[2]), "+f"(d[3])
        : "r"(a[0]), "r"(a[1]), "r"(a[2]), "r"(a[3]), "r"(b0), "r"(b1));
}
__device__ __forceinline__ void hilo(float a, float b, uint32_t& ph, uint32_t& pl) {
    asm("cvt.rn.bf16x2.f32 %0, %1, %2;" : "=r"(ph) : "f"(b), "f"(a));
    float r0 = a - __uint_as_float(ph << 16);
    float r1 = b - __uint_as_float(ph & 0xffff0000u);
    asm("cvt.rn.bf16x2.f32 %0, %1, %2;" : "=r"(pl) : "f"(r1), "f"(r0));
}
// 2^y, y<=0, FMA pipe only
__device__ __forceinline__ float exp2p(float y) {
    y = fmaxf(y, -126.0f);
    float kf = __fadd_rn(y, 12582912.0f);
    int j = __float_as_int(kf) - 0x4B400000;
    float f = __fsub_rn(y, __fsub_rn(kf, 12582912.0f));
    float p = 1.3333558e-3f;
    p = fmaf(p, f, 9.6181291e-3f);
    p = fmaf(p, f, 5.5504109e-2f);
    p = fmaf(p, f, 2.4022651e-1f);
    p = fmaf(p, f, 6.9314718e-1f);
    p = fmaf(p, f, 1.0f);
    return p * __int_as_float((j + 127) << 23);
}
__device__ __forceinline__ float tanh_fast(float x) {
    float t = exp2p(-2.8853901f * fabsf(x));
    float a = 1.0f + t;
    float r = fmaf(-0.470588f, a, 1.411765f);
    r = r * (2.0f - a * r);
    r = r * (2.0f - a * r);
    r = r * (2.0f - a * r);
    return copysignf((1.0f - t) * r, x);
}

// ---- prep: swizzled B images of g ----
__global__ void prep_g(const float* __restrict__ g) {
    int t = blockIdx.x * 256 + threadIdx.x;      // 131072
    int q = t >> 12, r12 = t & 4095;
    int kp = r12 >> 7, nr = r12 & 127;           // kp: k-pair 0..31
    int kb = (q & 3) * 64 + kp * 2;
    int nn = (q >> 2) * 128 + nr;
    uint32_t ph, pl;
    hilo(g[(size_t)kb * 1024 + nn], g[(size_t)(kb + 1) * 1024 + nn], ph, pl);
    uint32_t off = nr * 128 + ((((uint32_t)(kp >> 2)) ^ (nr & 7)) << 4) + (kp & 3) * 4;
    unsigned char* base = g_Bimg + (size_t)q * 32768;
    *(uint32_t*)(base + off) = ph;
    *(uint32_t*)(base + B_LO + off) = pl;
}
// ---- prep: swizzled w1 image ----
__global__ void prep_w1(const float* __restrict__ w1) {
    int t = blockIdx.x * 256 + threadIdx.x;      // 8192
    int att = t >> 6, mp = t & 63;
    uint32_t ph, pl;
    hilo(w1[att * 128 + 2 * mp], w1[att * 128 + 2 * mp + 1], ph, pl);
    uint32_t off = att * 256 + ((((uint32_t)(mp >> 2)) ^ (att & 7)) << 4) + (mp & 3) * 4;
    *(uint32_t*)(g_W1img + off) = ph;
    *(uint32_t*)(g_W1img + H_LO + off) = pl;
}
__global__ void sniff_kernel(const int* __restrict__ b32, int n) {
    g_is64 = (b32[n - 1] == 0) ? 1 : 0;
}
__device__ __forceinline__ int batch_at(const void* b, int i, int is64) {
    if (is64) return (int)((const long long*)b)[i];
    return ((const int*)b)[i];
}

__global__ __launch_bounds__(TPB, 1)
void node_kernel(const float* __restrict__ x,
                 const float* __restrict__ mu,
                 const float* __restrict__ sigma,
                 const float* __restrict__ w2g,
                 float* __restrict__ Hout,
                 float* __restrict__ scores, int n)
{
    extern __shared__ unsigned char smem[];
    float* sA2 = (float*)(smem + SO_A2);
    float* sB2 = (float*)(smem + SO_B2);
    float* sC2 = (float*)(smem + SO_C2);
    float* sW2 = (float*)(smem + SO_W2);
    const uint32_t sb = smem_u32(smem);
    const int tid = threadIdx.x, lane = tid & 31, wid = tid >> 5;
    const int mg = wid >> 1, cw = wid & 1;       // 4 row-groups x 2 col-halves
    const int rsel = lane & 15, usel = lane >> 4;
    const uint32_t xs = (uint32_t)(rsel & 7);
    const int node0 = blockIdx.x * NB;

    // gaussian consts: exp stage as 2^(A2 o^2 + B2 o + C2)
    for (int i = tid; i < 1024; i += TPB) {
        float s = sigma[i], m_ = mu[i];
        float cc = -0.72134752f / fmaf(s, s, 1e-15f);
        sA2[i] = cc; sB2[i] = -2.f * cc * m_; sC2[i] = cc * m_ * m_;
    }
    if (tid < 128) sW2[tid] = w2g[tid];

    // A image: x[128 nodes][256] -> bf16 hi/lo, swizzled 512B rows
    #pragma unroll
    for (int j = 0; j < 64; j++) {
        int i = tid + j * 256;
        int node = i >> 7, kp = i & 127;
        int ng = node0 + node;
        float2 v = make_float2(0.f, 0.f);
        if (ng < n) v = *(const float2*)(x + (size_t)ng * F + kp * 2);
        uint32_t ph, pl; hilo(v.x, v.y, ph, pl);
        uint32_t off = node * 512 + ((((uint32_t)(kp >> 2)) ^ (node & 7)) << 4) + (kp & 3) * 4;
        *(uint32_t*)(smem + SO_XA + off) = ph;
        *(uint32_t*)(smem + SO_XA + XA_LO + off) = pl;
    }

    // prologue B copies (pure linear: image layout == stage layout)
    {
        const unsigned char* s0 = g_Bimg + tid * 16;
        const unsigned char* s1 = g_Bimg + 32768 + tid * 16;
        uint32_t d0 = sb + SO_STG + tid * 16, d1 = d0 + STG_SZ;
        #pragma unroll
        for (int j2 = 0; j2 < 8; j2++) cp16(d0 + j2 * 4096, s0 + j2 * 4096);
        CP_COMMIT();
        #pragma unroll
        for (int j2 = 0; j2 < 8; j2++) cp16(d1 + j2 * 4096, s1 + j2 * 4096);
        CP_COMMIT();
    }

    float H[64], D[64];
    #pragma unroll
    for (int i = 0; i < 64; i++) H[i] = 0.f;

    // loop-invariant addresses
    uint32_t aBase0 = sb + SO_XA + (mg * 32 + rsel) * 512;
    uint32_t aBase1 = aBase0 + 16 * 512;
    uint32_t bRow[4];
    #pragma unroll
    for (int nt = 0; nt < 4; nt++) bRow[nt] = (uint32_t)((cw * 64 + nt * 16 + rsel) * 128);
    const uint32_t stg0 = sb + SO_STG, stg1 = sb + SO_STG + STG_SZ;
    const float* pa = sA2 + cw * 64 + (lane & 3) * 2;
    const float* pb = sB2 + cw * 64 + (lane & 3) * 2;
    const float* pc = sC2 + cw * 64 + (lane & 3) * 2;

    for (int c = 0; c < 32; c++) {
        const int kc = c & 3;
        if (c == 31) { CP_WAIT0(); } else { CP_WAIT1(); }
        __syncthreads();
        if (kc == 0) {
            #pragma unroll
            for (int i = 0; i < 64; i++) D[i] = 0.f;
        }
        const uint32_t sbase = (c & 1) ? stg1 : stg0;
        #pragma unroll
        for (int kt = 0; kt < 4; kt++) {
            uint32_t offA = ((((uint32_t)(kc * 8 + kt * 2 + usel)) ^ xs) << 4);
            uint32_t offB = ((((uint32_t)(kt * 2 + usel)) ^ xs) << 4);
            uint32_t ah0[4], al0[4], ah1[4], al1[4];
            ldmx4(ah0, aBase0 + offA); ldmx4(al0, aBase0 + offA + XA_LO);
            ldmx4(ah1, aBase1 + offA); ldmx4(al1, aBase1 + offA + XA_LO);
            #pragma unroll
            for (int nt = 0; nt < 4; nt++) {
                uint32_t bh[4], bl[4];
                uint32_t ba = sbase + bRow[nt] + offB;
                ldmx4(bh, ba); ldmx4(bl, ba + B_LO);
                #pragma unroll
                for (int e = 0; e < 2; e++) {
                    float* d0 = D + (nt * 2 + e) * 4;
                    float* d1 = d0 + 32;
                    mma_bf16(d0, ah0, bh[e], bh[2 + e]);
                    mma_bf16(d0, ah0, bl[e], bl[2 + e]);
                    mma_bf16(d0, al0, bh[e], bh[2 + e]);
                    mma_bf16(d1, ah1, bh[e], bh[2 + e]);
                    mma_bf16(d1, ah1, bl[e], bl[2 + e]);
                    mma_bf16(d1, al1, bh[e], bh[2 + e]);
                }
            }
        }
        __syncthreads();
        if (c + 2 < 32) {
            const unsigned char* src = g_Bimg + (size_t)(c + 2) * 32768 + tid * 16;
            uint32_t dst = ((c & 1) ? stg1 : stg0) + tid * 16;
            #pragma unroll
            for (int j2 = 0; j2 < 8; j2++) cp16(dst + j2 * 4096, src + j2 * 4096);
            CP_COMMIT();
        }
        if (kc == 3) {
            const int p = c >> 2;
            #pragma unroll
            for (int n8 = 0; n8 < 8; n8++) {
                float2 a2 = *(const float2*)(pa + p * 128 + n8 * 8);
                float2 b2 = *(const float2*)(pb + p * 128 + n8 * 8);
                float2 c2 = *(const float2*)(pc + p * 128 + n8 * 8);
                #pragma unroll
                for (int g2 = 0; g2 < 2; g2++) {
                    float* d = D + g2 * 32 + n8 * 4;
                    float* h = H + g2 * 32 + n8 * 4;
                    float o;
                    o = d[0]; h[0] = fmaf(o, exp2p(fmaf(fmaf(a2.x, o, b2.x), o, c2.x)), h[0]);
                    o = d[1]; h[1] = fmaf(o, exp2p(fmaf(fmaf(a2.y, o, b2.y), o, c2.y)), h[1]);
                    o = d[2]; h[2] = fmaf(o, exp2p(fmaf(fmaf(a2.x, o, b2.x), o, c2.x)), h[2]);
                    o = d[3]; h[3] = fmaf(o, exp2p(fmaf(fmaf(a2.y, o, b2.y), o, c2.y)), h[3]);
                }
            }
        }
    }

    // H -> gmem
    {
        #pragma unroll
        for (int g2 = 0; g2 < 2; g2++) {
            int r0 = node0 + mg * 32 + g2 * 16 + (lane >> 2);
            #pragma unroll
            for (int n8 = 0; n8 < 8; n8++) {
                int i = g2 * 32 + n8 * 4;
                int m = cw * 64 + n8 * 8 + (lane & 3) * 2;
                if (r0 < n)     *(float2*)(Hout + (size_t)r0 * M + m)       = make_float2(H[i], H[i + 1]);
                if (r0 + 8 < n) *(float2*)(Hout + (size_t)(r0 + 8) * M + m) = make_float2(H[i + 2], H[i + 3]);
            }
        }
    }
    __syncthreads();   // stages free

    // H image (swizzled 256B rows) + w1 via cp.async into A region
    {
        #pragma unroll
        for (int g2 = 0; g2 < 2; g2++) {
            int row0 = mg * 32 + g2 * 16 + (lane >> 2);
            uint32_t rx = (uint32_t)(row0 & 7);
            #pragma unroll
            for (int n8 = 0; n8 < 8; n8++) {
                int i = g2 * 32 + n8 * 4;
                uint32_t unit = (uint32_t)(cw * 8 + n8);
                uint32_t off = row0 * 256 + ((unit ^ rx) << 4) + (lane & 3) * 4;
                uint32_t ph, pl;
                hilo(H[i], H[i + 1], ph, pl);
                *(uint32_t*)(smem + SO_HI + off) = ph;
                *(uint32_t*)(smem + SO_HI + H_LO + off) = pl;
                hilo(H[i + 2], H[i + 3], ph, pl);
                *(uint32_t*)(smem + SO_HI + off + 8 * 256) = ph;
                *(uint32_t*)(smem + SO_HI + H_LO + off + 8 * 256) = pl;
            }
        }
        #pragma unroll
        for (int j = 0; j < 16; j++) {
            int i = tid + j * 256;
            cp16(sb + SO_XA + i * 16, g_W1img + (size_t)i * 16);
        }
        CP_COMMIT(); CP_WAIT0();
    }
    __syncthreads();

    // attention GEMM: warp wid owns rows 16*wid..+15, all 128 att cols
    {
        #pragma unroll
        for (int i = 0; i < 64; i++) D[i] = 0.f;
        uint32_t hB = sb + SO_HI + (wid * 16 + rsel) * 256;
        #pragma unroll
        for (int kt = 0; kt < 8; kt++) {
            uint32_t off = ((((uint32_t)(kt * 2 + usel)) ^ xs) << 4);
            uint32_t ah[4], al[4];
            ldmx4(ah, hB + off); ldmx4(al, hB + off + H_LO);
            #pragma unroll
            for (int nt = 0; nt < 8; nt++) {
                uint32_t bh[4], bl[4];
                uint32_t ba = sb + SO_XA + (nt * 16 + rsel) * 256 + off;
                ldmx4(bh, ba); ldmx4(bl, ba + H_LO);
                #pragma unroll
                for (int e = 0; e < 2; e++) {
                    float* d = D + (nt * 2 + e) * 4;
                    mma_bf16(d, ah, bh[e], bh[2 + e]);
                    mma_bf16(d, ah, bl[e], bl[2 + e]);
                    mma_bf16(d, al, bh[e], bh[2 + e]);
                }
            }
        }
        float p0 = 0.f, p1 = 0.f;
        #pragma unroll
        for (int n8 = 0; n8 < 16; n8++) {
            float2 wv = *(const float2*)(sW2 + n8 * 8 + (lane & 3) * 2);
            p0 = fmaf(tanh_fast(D[n8 * 4 + 0]), wv.x, p0);
            p0 = fmaf(tanh_fast(D[n8 * 4 + 1]), wv.y, p0);
            p1 = fmaf(tanh_fast(D[n8 * 4 + 2]), wv.x, p1);
            p1 = fmaf(tanh_fast(D[n8 * 4 + 3]), wv.y, p1);
        }
        p0 += __shfl_xor_sync(0xffffffffu, p0, 1);
        p0 += __shfl_xor_sync(0xffffffffu, p0, 2);
        p1 += __shfl_xor_sync(0xffffffffu, p1, 1);
        p1 += __shfl_xor_sync(0xffffffffu, p1, 2);
        if ((lane & 3) == 0) {
            int r = node0 + wid * 16 + (lane >> 2);
            if (r < n) scores[r] = p0;
            if (r + 8 < n) scores[r + 8] = p1;
        }
    }
}

__global__ __launch_bounds__(128)
void pool_kernel(const float* __restrict__ H,
                 const float* __restrict__ scores,
                 const void* __restrict__ batch,
                 int n, float* __restrict__ out)
{
    const int gidx = blockIdx.x, tid = threadIdx.x;
    const int is64 = g_is64;
    int start, end;
    {
        int lo = 0, hi = n;
        while (lo < hi) { int mid = (lo + hi) >> 1; if (batch_at(batch, mid, is64) < gidx) lo = mid + 1; else hi = mid; }
        start = lo; hi = n;
        while (lo < hi) { int mid = (lo + hi) >> 1; if (batch_at(batch, mid, is64) < gidx + 1) lo = mid + 1; else hi = mid; }
        end = lo;
    }
    if (start >= end) { out[(size_t)gidx * M + tid] = 0.f; return; }
    __shared__ float red[128];
    float mx = -INFINITY;
    for (int i = start + tid; i < end; i += 128) mx = fmaxf(mx, scores[i]);
    red[tid] = mx; __syncthreads();
    #pragma unroll
    for (int s = 64; s; s >>= 1) { if (tid < s) red[tid] = fmaxf(red[tid], red[tid + s]); __syncthreads(); }
    mx = red[0]; __syncthreads();
    float sm = 0.f;
    for (int i = start + tid; i < end; i += 128) sm += expf(scores[i] - mx);
    red[tid] = sm; __syncthreads();
    #pragma unroll
    for (int s = 64; s; s >>= 1) { if (tid < s) red[tid] += red[tid + s]; __syncthreads(); }
    const float inv = 1.f / (red[0] + 1e-16f);
    float acc = 0.f;
    for (int i = start; i < end; i++)
        acc = fmaf(expf(scores[i] - mx), H[(size_t)i * M + tid], acc);
    out[(size_t)gidx * M + tid] = acc * inv;
}

extern "C" void kernel_launch(void* const* d_in, const int* in_sizes, int n_in,
                              void* d_out, int out_size)
{
    const float* x     = (const float*)d_in[0];
    const float* g     = (const float*)d_in[1];
    const float* mu    = (const float*)d_in[2];
    const float* sigma = (const float*)d_in[3];
    const float* w1    = (const float*)d_in[4];
    const float* w2    = (const float*)d_in[5];
    const void*  batch = d_in[6];

    int n = in_sizes[0] / F;
    if (n > NMAX) n = NMAX;
    int num_graphs = out_size / M;

    cudaFuncSetAttribute(node_kernel, cudaFuncAttributeMaxDynamicSharedMemorySize, SMEM_BYTES);

    float* Hg; cudaGetSymbolAddress((void**)&Hg, g_H);
    float* Sg; cudaGetSymbolAddress((void**)&Sg, g_scores);

    prep_g<<<512, 256>>>(g);
    prep_w1<<<32, 256>>>(w1);
    sniff_kernel<<<1, 1>>>((const int*)batch, n);
    node_kernel<<<(n + NB - 1) / NB, TPB, SMEM_BYTES>>>(x, mu, sigma, w2, Hg, Sg, n);
    pool_kernel<<<num_graphs, 128>>>(Hg, Sg, batch, n, (float*)d_out);
}

// round 8
// speedup vs baseline: 5.3340x; 1.2334x over previous
#include <cuda_runtime.h>
#include <math.h>
#include <stdint.h>

#define F      256
#define M      128
#define NMAX   200000
#define NB     128         // nodes per CTA
#define TPB    256

__device__ float g_H[(size_t)NMAX * M];
__device__ float g_scores[NMAX];
// B images: [q=0..31] each 32KB = bh(16KB) + b'(16KB); rows n:128 x 128B (64 bf16 k), XOR-swizzled
__device__ __align__(128) unsigned char g_Bimg[32 * 32768];
// w1 image: wh 32KB + w' 32KB; rows att:128 x 256B (128 bf16 m), XOR-swizzled
__device__ __align__(128) unsigned char g_W1img[65536];
__device__ float g_cA[1024], g_cB[1024], g_cC[1024];   // gaussian consts
__device__ int g_is64;

// smem layout (dynamic): A images then 3 B stages
#define SO_XA   0          // ah 64KB, a' at +65536 (rows node:128 x 512B swizzled)
#define XA_P    65536
#define SO_STG  131072     // 3 stages x 32768
#define STG_SZ  32768
#define B_P     16384      // b' offset within stage
#define SO_HI   131072     // attention: hh 32KB, h' +32768
#define H_P     32768
#define SMEM_BYTES 229376

__device__ __forceinline__ uint32_t smem_u32(const void* p) {
    uint32_t a;
    asm("{ .reg .u64 t; cvta.to.shared.u64 t, %1; cvt.u32.u64 %0, t; }" : "=r"(a) : "l"(p));
    return a;
}
__device__ __forceinline__ void cp16(uint32_t dst, const void* src) {
    asm volatile("cp.async.cg.shared.global [%0], [%1], 16;" :: "r"(dst), "l"(src) : "memory");
}
#define CP_COMMIT() asm volatile("cp.async.commit_group;" ::: "memory")
#define CP_WAIT0()  asm volatile("cp.async.wait_group 0;" ::: "memory")
#define CP_WAIT1()  asm volatile("cp.async.wait_group 1;" ::: "memory")

__device__ __forceinline__ void ldmx4(uint32_t r[4], uint32_t addr) {
    asm volatile("ldmatrix.sync.aligned.m8n8.x4.shared.b16 {%0,%1,%2,%3}, [%4];"
        : "=r"(r[0]), "=r"(r[1]), "=r"(r[2]), "=r"(r[3]) : "r"(addr));
}
__device__ __forceinline__ void mma_bf16(float* d, const uint32_t* a, uint32_t b0, uint32_t b1) {
    asm volatile("mma.sync.aligned.m16n8k16.row.col.f32.bf16.bf16.f32 "
        "{%0,%1,%2,%3}, {%4,%5,%6,%7}, {%8,%9}, {%0,%1,%2,%3};"
        : "+f"(d[0]), "+f"(d[1]), "+f"(d[2]), "+f"(d[3])
        : "r"(a[0]), "r"(a[1]), "r"(a[2]), "r"(a[3]), "r"(b0), "r"(b1));
}
// 2-term scaled split: ph = bf16x2(a,b); pp = bf16x2(ah+32*(a-ah), bh+32*(b-bh))
__device__ __forceinline__ void split2(float a, float b, uint32_t& ph, uint32_t& pp) {
    asm("cvt.rn.bf16x2.f32 %0, %1, %2;" : "=r"(ph) : "f"(b), "f"(a));
    float ah = __uint_as_float(ph << 16);
    float bh = __uint_as_float(ph & 0xffff0000u);
    float a2 = fmaf(32.f, a - ah, ah);
    float b2 = fmaf(32.f, b - bh, bh);
    asm("cvt.rn.bf16x2.f32 %0, %1, %2;" : "=r"(pp) : "f"(b2), "f"(a2));
}
// 2^y, y<=0, FMA pipe only
__device__ __forceinline__ float exp2p(float y) {
    y = fmaxf(y, -126.0f);
    float kf = __fadd_rn(y, 12582912.0f);
    int j = __float_as_int(kf) - 0x4B400000;
    float f = __fsub_rn(y, __fsub_rn(kf, 12582912.0f));
    float p = 1.3333558e-3f;
    p = fmaf(p, f, 9.6181291e-3f);
    p = fmaf(p, f, 5.5504109e-2f);
    p = fmaf(p, f, 2.4022651e-1f);
    p = fmaf(p, f, 6.9314718e-1f);
    p = fmaf(p, f, 1.0f);
    return p * __int_as_float((j + 127) << 23);
}
__device__ __forceinline__ float tanh_fast(float x) {
    float t = exp2p(-2.8853901f * fabsf(x));
    float a = 1.0f + t;
    float r = fmaf(-0.470588f, a, 1.411765f);
    r = r * (2.0f - a * r);
    r = r * (2.0f - a * r);
    r = r * (2.0f - a * r);
    return copysignf((1.0f - t) * r, x);
}

// ---- prep: swizzled B images of g (2-term) ----
__global__ void prep_g(const float* __restrict__ g) {
    int t = blockIdx.x * 256 + threadIdx.x;      // 131072
    int q = t >> 12, r12 = t & 4095;
    int kp = r12 >> 7, nr = r12 & 127;           // kp: k-pair 0..31
    int kb = (q & 3) * 64 + kp * 2;
    int nn = (q >> 2) * 128 + nr;
    uint32_t ph, pp;
    split2(g[(size_t)kb * 1024 + nn], g[(size_t)(kb + 1) * 1024 + nn], ph, pp);
    uint32_t off = nr * 128 + ((((uint32_t)(kp >> 2)) ^ (nr & 7)) << 4) + (kp & 3) * 4;
    unsigned char* base = g_Bimg + (size_t)q * 32768;
    *(uint32_t*)(base + off) = ph;
    *(uint32_t*)(base + B_P + off) = pp;
}
__global__ void prep_w1(const float* __restrict__ w1) {
    int t = blockIdx.x * 256 + threadIdx.x;      // 8192
    int att = t >> 6, mp = t & 63;
    uint32_t ph, pp;
    split2(w1[att * 128 + 2 * mp], w1[att * 128 + 2 * mp + 1], ph, pp);
    uint32_t off = att * 256 + ((((uint32_t)(mp >> 2)) ^ (att & 7)) << 4) + (mp & 3) * 4;
    *(uint32_t*)(g_W1img + off) = ph;
    *(uint32_t*)(g_W1img + H_P + off) = pp;
}
__global__ void prep_consts(const float* __restrict__ mu, const float* __restrict__ sigma) {
    int i = blockIdx.x * 256 + threadIdx.x;      // 1024
    float s = sigma[i], m_ = mu[i];
    float cc = -0.72134752f / fmaf(s, s, 1e-15f);
    g_cA[i] = cc; g_cB[i] = -2.f * cc * m_; g_cC[i] = cc * m_ * m_;
}
__global__ void sniff_kernel(const int* __restrict__ b32, int n) {
    g_is64 = (b32[n - 1] == 0) ? 1 : 0;
}
__device__ __forceinline__ int batch_at(const void* b, int i, int is64) {
    if (is64) return (int)((const long long*)b)[i];
    return ((const int*)b)[i];
}

__global__ __launch_bounds__(TPB, 1)
void node_kernel(const float* __restrict__ x,
                 const float* __restrict__ w2g,
                 float* __restrict__ Hout,
                 float* __restrict__ scores, int n)
{
    extern __shared__ unsigned char smem[];
    const uint32_t sb = smem_u32(smem);
    const int tid = threadIdx.x, lane = tid & 31, wid = tid >> 5;
    const int mg = wid >> 1, cw = wid & 1;       // 4 row-groups x 2 col-halves
    const int rsel = lane & 15, usel = lane >> 4;
    const uint32_t xs = (uint32_t)(rsel & 7);
    const int node0 = blockIdx.x * NB;

    // A images: x[128 nodes][256] -> bf16 2-term split, swizzled 512B rows
    #pragma unroll
    for (int j = 0; j < 64; j++) {
        int i = tid + j * 256;
        int node = i >> 7, kp = i & 127;
        int ng = node0 + node;
        float2 v = make_float2(0.f, 0.f);
        if (ng < n) v = *(const float2*)(x + (size_t)ng * F + kp * 2);
        uint32_t ph, pp; split2(v.x, v.y, ph, pp);
        uint32_t off = node * 512 + ((((uint32_t)(kp >> 2)) ^ (node & 7)) << 4) + (kp & 3) * 4;
        *(uint32_t*)(smem + SO_XA + off) = ph;
        *(uint32_t*)(smem + SO_XA + XA_P + off) = pp;
    }
    // prologue B copies: chunk0 -> stage0, chunk1 -> stage1
    {
        const unsigned char* s0 = g_Bimg + tid * 16;
        uint32_t d0 = sb + SO_STG + tid * 16;
        #pragma unroll
        for (int j2 = 0; j2 < 8; j2++) cp16(d0 + j2 * 4096, s0 + j2 * 4096);
        CP_COMMIT();
        #pragma unroll
        for (int j2 = 0; j2 < 8; j2++) cp16(d0 + STG_SZ + j2 * 4096, s0 + 32768 + j2 * 4096);
        CP_COMMIT();
    }
    __syncthreads();   // A image visible

    float H[64], D1[64], D2[64];
    #pragma unroll
    for (int i = 0; i < 64; i++) H[i] = 0.f;

    const uint32_t aBase0 = sb + SO_XA + (mg * 32 + rsel) * 512;
    const uint32_t aBase1 = aBase0 + 16 * 512;
    uint32_t bRow[4];
    #pragma unroll
    for (int nt = 0; nt < 4; nt++) bRow[nt] = (uint32_t)((cw * 64 + nt * 16 + rsel) * 128);
    const float* pa = g_cA + cw * 64 + (lane & 3) * 2;
    const float* pb = g_cB + cw * 64 + (lane & 3) * 2;
    const float* pc = g_cC + cw * 64 + (lane & 3) * 2;

    int s = 0, st2 = 2;
    #pragma unroll 1
    for (int c = 0; c < 32; c++) {
        const int kc = c & 3;
        if (c == 31) { CP_WAIT0(); } else { CP_WAIT1(); }
        __syncthreads();    // stage s full; stage st2 fully consumed (at c-1)
        if (c + 2 < 32) {   // issue copy for chunk c+2 into freed stage
            const unsigned char* src = g_Bimg + (size_t)(c + 2) * 32768 + tid * 16;
            uint32_t dst = sb + SO_STG + st2 * STG_SZ + tid * 16;
            #pragma unroll
            for (int j2 = 0; j2 < 8; j2++) cp16(dst + j2 * 4096, src + j2 * 4096);
            CP_COMMIT();
        }
        if (kc == 0) {
            #pragma unroll
            for (int i = 0; i < 64; i++) { D1[i] = 0.f; D2[i] = 0.f; }
        }
        const uint32_t sbase = sb + SO_STG + s * STG_SZ;
        #pragma unroll
        for (int kt = 0; kt < 4; kt++) {
            uint32_t offA = ((((uint32_t)(kc * 8 + kt * 2 + usel)) ^ xs) << 4);
            uint32_t offB = ((((uint32_t)(kt * 2 + usel)) ^ xs) << 4);
            uint32_t ah0[4], ap0[4], ah1[4], ap1[4];
            ldmx4(ah0, aBase0 + offA); ldmx4(ap0, aBase0 + offA + XA_P);
            ldmx4(ah1, aBase1 + offA); ldmx4(ap1, aBase1 + offA + XA_P);
            #pragma unroll
            for (int nt = 0; nt < 4; nt++) {
                uint32_t bh[4], bp[4];
                uint32_t ba = sbase + bRow[nt] + offB;
                ldmx4(bh, ba); ldmx4(bp, ba + B_P);
                #pragma unroll
                for (int e = 0; e < 2; e++) {
                    float* d1 = D1 + (nt * 2 + e) * 4;
                    float* d2 = D2 + (nt * 2 + e) * 4;
                    mma_bf16(d1, ah0, bh[e], bh[2 + e]);
                    mma_bf16(d2, ap0, bp[e], bp[2 + e]);
                    mma_bf16(d1 + 32, ah1, bh[e], bh[2 + e]);
                    mma_bf16(d2 + 32, ap1, bp[e], bp[2 + e]);
                }
            }
        }
        if (kc == 3) {
            const int p = c >> 2;
            #pragma unroll
            for (int n8 = 0; n8 < 8; n8++) {
                float2 a2 = *(const float2*)(pa + p * 128 + n8 * 8);
                float2 b2 = *(const float2*)(pb + p * 128 + n8 * 8);
                float2 c2 = *(const float2*)(pc + p * 128 + n8 * 8);
                #pragma unroll
                for (int g2 = 0; g2 < 2; g2++) {
                    float* d1 = D1 + g2 * 32 + n8 * 4;
                    float* d2 = D2 + g2 * 32 + n8 * 4;
                    float* h  = H  + g2 * 32 + n8 * 4;
                    float o;
                    o = fmaf(d2[0] - d1[0], 0.03125f, d1[0]);
                    h[0] = fmaf(o, exp2p(fmaf(fmaf(a2.x, o, b2.x), o, c2.x)), h[0]);
                    o = fmaf(d2[1] - d1[1], 0.03125f, d1[1]);
                    h[1] = fmaf(o, exp2p(fmaf(fmaf(a2.y, o, b2.y), o, c2.y)), h[1]);
                    o = fmaf(d2[2] - d1[2], 0.03125f, d1[2]);
                    h[2] = fmaf(o, exp2p(fmaf(fmaf(a2.x, o, b2.x), o, c2.x)), h[2]);
                    o = fmaf(d2[3] - d1[3], 0.03125f, d1[3]);
                    h[3] = fmaf(o, exp2p(fmaf(fmaf(a2.y, o, b2.y), o, c2.y)), h[3]);
                }
            }
        }
        s = (s == 2) ? 0 : s + 1;
        st2 = (st2 == 2) ? 0 : st2 + 1;
    }
    __syncthreads();   // all A/stage reads done

    // w1 images -> A region (async), H -> gmem, H images -> stage region
    #pragma unroll
    for (int j = 0; j < 16; j++) {
        int i = tid + j * 256;
        cp16(sb + SO_XA + i * 16, g_W1img + (size_t)i * 16);
    }
    CP_COMMIT();
    {
        #pragma unroll
        for (int g2 = 0; g2 < 2; g2++) {
            int r0 = node0 + mg * 32 + g2 * 16 + (lane >> 2);
            #pragma unroll
            for (int n8 = 0; n8 < 8; n8++) {
                int i = g2 * 32 + n8 * 4;
                int m = cw * 64 + n8 * 8 + (lane & 3) * 2;
                if (r0 < n)     *(float2*)(Hout + (size_t)r0 * M + m)       = make_float2(H[i], H[i + 1]);
                if (r0 + 8 < n) *(float2*)(Hout + (size_t)(r0 + 8) * M + m) = make_float2(H[i + 2], H[i + 3]);
            }
        }
        #pragma unroll
        for (int g2 = 0; g2 < 2; g2++) {
            int row0 = mg * 32 + g2 * 16 + (lane >> 2);
            uint32_t rx = (uint32_t)(row0 & 7);
            #pragma unroll
            for (int n8 = 0; n8 < 8; n8++) {
                int i = g2 * 32 + n8 * 4;
                uint32_t unit = (uint32_t)(cw * 8 + n8);
                uint32_t off = row0 * 256 + ((unit ^ rx) << 4) + (lane & 3) * 4;
                uint32_t ph, pp;
                split2(H[i], H[i + 1], ph, pp);
                *(uint32_t*)(smem + SO_HI + off) = ph;
                *(uint32_t*)(smem + SO_HI + H_P + off) = pp;
                split2(H[i + 2], H[i + 3], ph, pp);
                *(uint32_t*)(smem + SO_HI + off + 8 * 256) = ph;
                *(uint32_t*)(smem + SO_HI + H_P + off + 8 * 256) = pp;
            }
        }
    }
    CP_WAIT0();
    __syncthreads();

    // attention GEMM: warp wid owns rows 16*wid..+15, all 128 att cols (2-term)
    {
        #pragma unroll
        for (int i = 0; i < 64; i++) { D1[i] = 0.f; D2[i] = 0.f; }
        uint32_t hB = sb + SO_HI + (wid * 16 + rsel) * 256;
        #pragma unroll
        for (int kt = 0; kt < 8; kt++) {
            uint32_t off = ((((uint32_t)(kt * 2 + usel)) ^ xs) << 4);
            uint32_t ah[4], ap[4];
            ldmx4(ah, hB + off); ldmx4(ap, hB + off + H_P);
            #pragma unroll
            for (int nt = 0; nt < 8; nt++) {
                uint32_t bh[4], bp[4];
                uint32_t ba = sb + SO_XA + (nt * 16 + rsel) * 256 + off;
                ldmx4(bh, ba); ldmx4(bp, ba + H_P);
                #pragma unroll
                for (int e = 0; e < 2; e++) {
                    float* d1 = D1 + (nt * 2 + e) * 4;
                    float* d2 = D2 + (nt * 2 + e) * 4;
                    mma_bf16(d1, ah, bh[e], bh[2 + e]);
                    mma_bf16(d2, ap, bp[e], bp[2 + e]);
                }
            }
        }
        float p0 = 0.f, p1 = 0.f;
        #pragma unroll
        for (int n8 = 0; n8 < 16; n8++) {
            float2 wv = *(const float2*)(w2g + n8 * 8 + (lane & 3) * 2);
            float o;
            o = fmaf(D2[n8*4+0] - D1[n8*4+0], 0.03125f, D1[n8*4+0]);
            p0 = fmaf(tanh_fast(o), wv.x, p0);
            o = fmaf(D2[n8*4+1] - D1[n8*4+1], 0.03125f, D1[n8*4+1]);
            p0 = fmaf(tanh_fast(o), wv.y, p0);
            o = fmaf(D2[n8*4+2] - D1[n8*4+2], 0.03125f, D1[n8*4+2]);
            p1 = fmaf(tanh_fast(o), wv.x, p1);
            o = fmaf(D2[n8*4+3] - D1[n8*4+3], 0.03125f, D1[n8*4+3]);
            p1 = fmaf(tanh_fast(o), wv.y, p1);
        }
        p0 += __shfl_xor_sync(0xffffffffu, p0, 1);
        p0 += __shfl_xor_sync(0xffffffffu, p0, 2);
        p1 += __shfl_xor_sync(0xffffffffu, p1, 1);
        p1 += __shfl_xor_sync(0xffffffffu, p1, 2);
        if ((lane & 3) == 0) {
            int r = node0 + wid * 16 + (lane >> 2);
            if (r < n) scores[r] = p0;
            if (r + 8 < n) scores[r + 8] = p1;
        }
    }
}

__global__ __launch_bounds__(128)
void pool_kernel(const float* __restrict__ H,
                 const float* __restrict__ scores,
                 const void* __restrict__ batch,
                 int n, float* __restrict__ out)
{
    const int gidx = blockIdx.x, tid = threadIdx.x;
    const int is64 = g_is64;
    int start, end;
    {
        int lo = 0, hi = n;
        while (lo < hi) { int mid = (lo + hi) >> 1; if (batch_at(batch, mid, is64) < gidx) lo = mid + 1; else hi = mid; }
        start = lo; hi = n;
        while (lo < hi) { int mid = (lo + hi) >> 1; if (batch_at(batch, mid, is64) < gidx + 1) lo = mid + 1; else hi = mid; }
        end = lo;
    }
    if (start >= end) { out[(size_t)gidx * M + tid] = 0.f; return; }
    __shared__ float red[128];
    float mx = -INFINITY;
    for (int i = start + tid; i < end; i += 128) mx = fmaxf(mx, scores[i]);
    red[tid] = mx; __syncthreads();
    #pragma unroll
    for (int s = 64; s; s >>= 1) { if (tid < s) red[tid] = fmaxf(red[tid], red[tid + s]); __syncthreads(); }
    mx = red[0]; __syncthreads();
    float sm = 0.f;
    for (int i = start + tid; i < end; i += 128) sm += expf(scores[i] - mx);
    red[tid] = sm; __syncthreads();
    #pragma unroll
    for (int s = 64; s; s >>= 1) { if (tid < s) red[tid] += red[tid + s]; __syncthreads(); }
    const float inv = 1.f / (red[0] + 1e-16f);
    float acc = 0.f;
    for (int i = start; i < end; i++)
        acc = fmaf(expf(scores[i] - mx), H[(size_t)i * M + tid], acc);
    out[(size_t)gidx * M + tid] = acc * inv;
}

extern "C" void kernel_launch(void* const* d_in, const int* in_sizes, int n_in,
                              void* d_out, int out_size)
{
    const float* x     = (const float*)d_in[0];
    const float* g     = (const float*)d_in[1];
    const float* mu    = (const float*)d_in[2];
    const float* sigma = (const float*)d_in[3];
    const float* w1    = (const float*)d_in[4];
    const float* w2    = (const float*)d_in[5];
    const void*  batch = d_in[6];

    int n = in_sizes[0] / F;
    if (n > NMAX) n = NMAX;
    int num_graphs = out_size / M;

    cudaFuncSetAttribute(node_kernel, cudaFuncAttributeMaxDynamicSharedMemorySize, SMEM_BYTES);

    float* Hg; cudaGetSymbolAddress((void**)&Hg, g_H);
    float* Sg; cudaGetSymbolAddress((void**)&Sg, g_scores);

    prep_g<<<512, 256>>>(g);
    prep_w1<<<32, 256>>>(w1);
    prep_consts<<<4, 256>>>(mu, sigma);
    sniff_kernel<<<1, 1>>>((const int*)batch, n);
    node_kernel<<<(n + NB - 1) / NB, TPB, SMEM_BYTES>>>(x, w2, Hg, Sg, n);
    pool_kernel<<<num_graphs, 128>>>(Hg, Sg, batch, n, (float*)d_out);
}

// round 9
// speedup vs baseline: 5.6734x; 1.0636x over previous
#include <cuda_runtime.h>
#include <math.h>
#include <stdint.h>

#define F      256
#define M      128
#define NMAX   200000
#define NB     128         // nodes per CTA
#define TPB    256

__device__ float g_H[(size_t)NMAX * M];
__device__ float g_scores[NMAX];
// B images: [q=0..31] each 32KB = bh(16KB) + b'(16KB); rows n:128 x 128B (64 bf16 k), XOR-swizzled
__device__ __align__(128) unsigned char g_Bimg[32 * 32768];
// w1 image: wh 32KB + w' 32KB; rows att:128 x 256B (128 bf16 m), XOR-swizzled
__device__ __align__(128) unsigned char g_W1img[65536];
__device__ float g_cA[1024], g_cB[1024], g_cC[1024];   // gaussian consts
__device__ int g_is64;

// smem layout (dynamic): A images, 3 B stages, mbarriers
#define SO_XA   0          // ah 64KB, a' at +65536 (rows node:128 x 512B swizzled)
#define XA_P    65536
#define SO_STG  131072     // 3 stages x 32768
#define STG_SZ  32768
#define B_P     16384      // b' offset within stage
#define SO_HI   131072     // attention phase: hh 32KB, h' +32768
#define H_P     32768
#define SO_MB   229376     // mbF[3] @+0, mbE[3] @+24, mbW @+48
#define SMEM_BYTES 229440

__device__ __forceinline__ uint32_t smem_u32(const void* p) {
    uint32_t a;
    asm("{ .reg .u64 t; cvta.to.shared.u64 t, %1; cvt.u32.u64 %0, t; }" : "=r"(a) : "l"(p));
    return a;
}
#define MBAR_INIT(a, c) asm volatile("mbarrier.init.shared.b64 [%0], %1;" :: "r"((uint32_t)(a)), "r"((uint32_t)(c)) : "memory")
#define MBAR_ARRIVE(a)  asm volatile("mbarrier.arrive.shared.b64 _, [%0];" :: "r"((uint32_t)(a)) : "memory")
#define MBAR_EXPECT(a, bytes) \
    asm volatile("mbarrier.arrive.expect_tx.shared.b64 _, [%0], %1;" :: "r"((uint32_t)(a)), "r"((uint32_t)(bytes)) : "memory")
#define MBAR_WAIT(a, par) do { \
    uint32_t _m = (uint32_t)(a), _p = (uint32_t)(par), _d; \
    asm volatile("{\n\t.reg .pred p;\n\t" \
        "mbarrier.try_wait.parity.acquire.cta.shared::cta.b64 p, [%1], %2;\n\t" \
        "selp.b32 %0, 1, 0, p;\n\t}" : "=r"(_d) : "r"(_m), "r"(_p) : "memory"); \
    if (!_d) { asm volatile("{\n\t.reg .pred P1;\n\t" \
        "WL_%=:\n\t" \
        "mbarrier.try_wait.parity.acquire.cta.shared::cta.b64 P1, [%0], %1, 0x989680;\n\t" \
        "@P1 bra.uni WD_%=;\n\tbra.uni WL_%=;\n\tWD_%=:\n\t}" :: "r"(_m), "r"(_p) : "memory"); } \
    } while (0)
#define BULK_G2S(dst, src, bytes, mbar) \
    asm volatile("cp.async.bulk.shared::cta.global.mbarrier::complete_tx::bytes [%0], [%1], %2, [%3];" \
        :: "r"((uint32_t)(dst)), "l"(src), "r"((uint32_t)(bytes)), "r"((uint32_t)(mbar)) : "memory")

__device__ __forceinline__ void ldmx4(uint32_t r[4], uint32_t addr) {
    asm volatile("ldmatrix.sync.aligned.m8n8.x4.shared.b16 {%0,%1,%2,%3}, [%4];"
        : "=r"(r[0]), "=r"(r[1]), "=r"(r[2]), "=r"(r[3]) : "r"(addr));
}
__device__ __forceinline__ void mma_bf16(float* d, const uint32_t* a, uint32_t b0, uint32_t b1) {
    asm volatile("mma.sync.aligned.m16n8k16.row.col.f32.bf16.bf16.f32 "
        "{%0,%1,%2,%3}, {%4,%5,%6,%7}, {%8,%9}, {%0,%1,%2,%3};"
        : "+f"(d[0]), "+f"(d[1]), "+f"(d[2]), "+f"(d[3])
        : "r"(a[0]), "r"(a[1]), "r"(a[2]), "r"(a[3]), "r"(b0), "r"(b1));
}
// 2-term scaled split: ph = bf16x2(a,b); pp = bf16x2(ah+32*(a-ah), bh+32*(b-bh))
__device__ __forceinline__ void split2(float a, float b, uint32_t& ph, uint32_t& pp) {
    asm("cvt.rn.bf16x2.f32 %0, %1, %2;" : "=r"(ph) : "f"(b), "f"(a));
    float ah = __uint_as_float(ph << 16);
    float bh = __uint_as_float(ph & 0xffff0000u);
    float a2 = fmaf(32.f, a - ah, ah);
    float b2 = fmaf(32.f, b - bh, bh);
    asm("cvt.rn.bf16x2.f32 %0, %1, %2;" : "=r"(pp) : "f"(b2), "f"(a2));
}
// 2^y, y<=0, FMA pipe only
__device__ __forceinline__ float exp2p(float y) {
    y = fmaxf(y, -126.0f);
    float kf = __fadd_rn(y, 12582912.0f);
    int j = __float_as_int(kf) - 0x4B400000;
    float f = __fsub_rn(y, __fsub_rn(kf, 12582912.0f));
    float p = 1.3333558e-3f;
    p = fmaf(p, f, 9.6181291e-3f);
    p = fmaf(p, f, 5.5504109e-2f);
    p = fmaf(p, f, 2.4022651e-1f);
    p = fmaf(p, f, 6.9314718e-1f);
    p = fmaf(p, f, 1.0f);
    return p * __int_as_float((j + 127) << 23);
}
__device__ __forceinline__ float tanh_fast(float x) {
    float t = exp2p(-2.8853901f * fabsf(x));
    float a = 1.0f + t;
    float r = fmaf(-0.470588f, a, 1.411765f);
    r = r * (2.0f - a * r);
    r = r * (2.0f - a * r);
    r = r * (2.0f - a * r);
    return copysignf((1.0f - t) * r, x);
}

// ---- prep kernels ----
__global__ void prep_g(const float* __restrict__ g) {
    int t = blockIdx.x * 256 + threadIdx.x;      // 131072
    int q = t >> 12, r12 = t & 4095;
    int kp = r12 >> 7, nr = r12 & 127;           // kp: k-pair 0..31
    int kb = (q & 3) * 64 + kp * 2;
    int nn = (q >> 2) * 128 + nr;
    uint32_t ph, pp;
    split2(g[(size_t)kb * 1024 + nn], g[(size_t)(kb + 1) * 1024 + nn], ph, pp);
    uint32_t off = nr * 128 + ((((uint32_t)(kp >> 2)) ^ (nr & 7)) << 4) + (kp & 3) * 4;
    unsigned char* base = g_Bimg + (size_t)q * 32768;
    *(uint32_t*)(base + off) = ph;
    *(uint32_t*)(base + B_P + off) = pp;
}
__global__ void prep_w1(const float* __restrict__ w1) {
    int t = blockIdx.x * 256 + threadIdx.x;      // 8192
    int att = t >> 6, mp = t & 63;
    uint32_t ph, pp;
    split2(w1[att * 128 + 2 * mp], w1[att * 128 + 2 * mp + 1], ph, pp);
    uint32_t off = att * 256 + ((((uint32_t)(mp >> 2)) ^ (att & 7)) << 4) + (mp & 3) * 4;
    *(uint32_t*)(g_W1img + off) = ph;
    *(uint32_t*)(g_W1img + H_P + off) = pp;
}
__global__ void prep_consts(const float* __restrict__ mu, const float* __restrict__ sigma) {
    int i = blockIdx.x * 256 + threadIdx.x;      // 1024
    float s = sigma[i], m_ = mu[i];
    float cc = -0.72134752f / fmaf(s, s, 1e-15f);
    g_cA[i] = cc; g_cB[i] = -2.f * cc * m_; g_cC[i] = cc * m_ * m_;
}
__global__ void sniff_kernel(const int* __restrict__ b32, int n) {
    g_is64 = (b32[n - 1] == 0) ? 1 : 0;
}
__device__ __forceinline__ int batch_at(const void* b, int i, int is64) {
    if (is64) return (int)((const long long*)b)[i];
    return ((const int*)b)[i];
}

__global__ __launch_bounds__(TPB, 1)
void node_kernel(const float* __restrict__ x,
                 const float* __restrict__ w2g,
                 float* __restrict__ Hout,
                 float* __restrict__ scores, int n)
{
    extern __shared__ unsigned char smem[];
    const uint32_t sb = smem_u32(smem);
    const uint32_t mbF = sb + SO_MB, mbE = sb + SO_MB + 24, mbW = sb + SO_MB + 48;
    const int tid = threadIdx.x, lane = tid & 31, wid = tid >> 5;
    const int mg = wid >> 1, cw = wid & 1;       // 4 row-groups x 2 col-halves
    const int rsel = lane & 15, usel = lane >> 4;
    const uint32_t xs = (uint32_t)(rsel & 7);
    const int node0 = blockIdx.x * NB;

    if (tid == 0) {
        #pragma unroll
        for (int s2 = 0; s2 < 3; s2++) { MBAR_INIT(mbF + s2 * 8, 1); MBAR_INIT(mbE + s2 * 8, 8); }
        MBAR_INIT(mbW, 1);
    }

    // A images: x[128 nodes][256] -> bf16 2-term split, swizzled 512B rows
    #pragma unroll
    for (int j = 0; j < 64; j++) {
        int i = tid + j * 256;
        int node = i >> 7, kp = i & 127;
        int ng = node0 + node;
        float2 v = make_float2(0.f, 0.f);
        if (ng < n) v = *(const float2*)(x + (size_t)ng * F + kp * 2);
        uint32_t ph, pp; split2(v.x, v.y, ph, pp);
        uint32_t off = node * 512 + ((((uint32_t)(kp >> 2)) ^ (node & 7)) << 4) + (kp & 3) * 4;
        *(uint32_t*)(smem + SO_XA + off) = ph;
        *(uint32_t*)(smem + SO_XA + XA_P + off) = pp;
    }
    __syncthreads();   // A image + mbar init visible

    if (tid == 0) {    // prefetch chunks 0,1
        MBAR_EXPECT(mbF, 32768);
        BULK_G2S(sb + SO_STG, g_Bimg, 32768, mbF);
        MBAR_EXPECT(mbF + 8, 32768);
        BULK_G2S(sb + SO_STG + STG_SZ, g_Bimg + 32768, 32768, mbF + 8);
    }

    float H[64], D1[64], D2[64];
    #pragma unroll
    for (int i = 0; i < 64; i++) H[i] = 0.f;

    const uint32_t aBase0 = sb + SO_XA + (mg * 32 + rsel) * 512;
    const uint32_t aBase1 = aBase0 + 16 * 512;
    uint32_t bRow[4];
    #pragma unroll
    for (int nt = 0; nt < 4; nt++) bRow[nt] = (uint32_t)((cw * 64 + nt * 16 + rsel) * 128);
    const float* pa = g_cA + cw * 64 + (lane & 3) * 2;
    const float* pb = g_cB + cw * 64 + (lane & 3) * 2;
    const float* pc = g_cC + cw * 64 + (lane & 3) * 2;

    #pragma unroll 1
    for (int c = 0; c < 32; c++) {
        const int kc = c & 3;
        const int s = c % 3;
        // producer: issue chunk c+2 (warp 0 lane 0), waiting stage-empty first
        if (wid == 0 && lane == 0) {
            int q = c + 2;
            if (q < 32) {
                int sq = q % 3;
                if (q >= 3) MBAR_WAIT(mbE + sq * 8, ((q - 3) / 3) & 1);
                MBAR_EXPECT(mbF + sq * 8, 32768);
                BULK_G2S(sb + SO_STG + sq * STG_SZ, g_Bimg + (size_t)q * 32768, 32768, mbF + sq * 8);
            }
        }
        MBAR_WAIT(mbF + s * 8, (c / 3) & 1);
        if (kc == 0) {
            #pragma unroll
            for (int i = 0; i < 64; i++) { D1[i] = 0.f; D2[i] = 0.f; }
        }
        const uint32_t sbase = sb + SO_STG + s * STG_SZ;
        #pragma unroll
        for (int kt = 0; kt < 4; kt++) {
            uint32_t offA = ((((uint32_t)(kc * 8 + kt * 2 + usel)) ^ xs) << 4);
            uint32_t offB = ((((uint32_t)(kt * 2 + usel)) ^ xs) << 4);
            uint32_t ah0[4], ap0[4], ah1[4], ap1[4];
            ldmx4(ah0, aBase0 + offA); ldmx4(ap0, aBase0 + offA + XA_P);
            ldmx4(ah1, aBase1 + offA); ldmx4(ap1, aBase1 + offA + XA_P);
            #pragma unroll
            for (int nt = 0; nt < 4; nt++) {
                uint32_t bh[4], bp[4];
                uint32_t ba = sbase + bRow[nt] + offB;
                ldmx4(bh, ba); ldmx4(bp, ba + B_P);
                #pragma unroll
                for (int e = 0; e < 2; e++) {
                    float* d1 = D1 + (nt * 2 + e) * 4;
                    float* d2 = D2 + (nt * 2 + e) * 4;
                    mma_bf16(d1, ah0, bh[e], bh[2 + e]);
                    mma_bf16(d2, ap0, bp[e], bp[2 + e]);
                    mma_bf16(d1 + 32, ah1, bh[e], bh[2 + e]);
                    mma_bf16(d2 + 32, ap1, bp[e], bp[2 + e]);
                }
            }
        }
        if (lane == 0) MBAR_ARRIVE(mbE + s * 8);   // stage consumed (before epilogue!)
        if (kc == 3) {
            const int p = c >> 2;
            #pragma unroll
            for (int n8 = 0; n8 < 8; n8++) {
                float2 a2 = *(const float2*)(pa + p * 128 + n8 * 8);
                float2 b2 = *(const float2*)(pb + p * 128 + n8 * 8);
                float2 c2 = *(const float2*)(pc + p * 128 + n8 * 8);
                #pragma unroll
                for (int g2 = 0; g2 < 2; g2++) {
                    float* d1 = D1 + g2 * 32 + n8 * 4;
                    float* d2 = D2 + g2 * 32 + n8 * 4;
                    float* h  = H  + g2 * 32 + n8 * 4;
                    float o;
                    o = fmaf(d2[0] - d1[0], 0.03125f, d1[0]);
                    h[0] = fmaf(o, exp2p(fmaf(fmaf(a2.x, o, b2.x), o, c2.x)), h[0]);
                    o = fmaf(d2[1] - d1[1], 0.03125f, d1[1]);
                    h[1] = fmaf(o, exp2p(fmaf(fmaf(a2.y, o, b2.y), o, c2.y)), h[1]);
                    o = fmaf(d2[2] - d1[2], 0.03125f, d1[2]);
                    h[2] = fmaf(o, exp2p(fmaf(fmaf(a2.x, o, b2.x), o, c2.x)), h[2]);
                    o = fmaf(d2[3] - d1[3], 0.03125f, d1[3]);
                    h[3] = fmaf(o, exp2p(fmaf(fmaf(a2.y, o, b2.y), o, c2.y)), h[3]);
                }
            }
        }
    }
    __syncthreads();   // all A/stage reads done everywhere

    // w1 bulk into A region (overlaps H stores + H-image build)
    if (tid == 0) {
        MBAR_EXPECT(mbW, 65536);
        BULK_G2S(sb + SO_XA, g_W1img, 65536, mbW);
    }
    {
        #pragma unroll
        for (int g2 = 0; g2 < 2; g2++) {
            int r0 = node0 + mg * 32 + g2 * 16 + (lane >> 2);
            #pragma unroll
            for (int n8 = 0; n8 < 8; n8++) {
                int i = g2 * 32 + n8 * 4;
                int m = cw * 64 + n8 * 8 + (lane & 3) * 2;
                if (r0 < n)     *(float2*)(Hout + (size_t)r0 * M + m)       = make_float2(H[i], H[i + 1]);
                if (r0 + 8 < n) *(float2*)(Hout + (size_t)(r0 + 8) * M + m) = make_float2(H[i + 2], H[i + 3]);
            }
        }
        #pragma unroll
        for (int g2 = 0; g2 < 2; g2++) {
            int row0 = mg * 32 + g2 * 16 + (lane >> 2);
            uint32_t rx = (uint32_t)(row0 & 7);
            #pragma unroll
            for (int n8 = 0; n8 < 8; n8++) {
                int i = g2 * 32 + n8 * 4;
                uint32_t unit = (uint32_t)(cw * 8 + n8);
                uint32_t off = row0 * 256 + ((unit ^ rx) << 4) + (lane & 3) * 4;
                uint32_t ph, pp;
                split2(H[i], H[i + 1], ph, pp);
                *(uint32_t*)(smem + SO_HI + off) = ph;
                *(uint32_t*)(smem + SO_HI + H_P + off) = pp;
                split2(H[i + 2], H[i + 3], ph, pp);
                *(uint32_t*)(smem + SO_HI + off + 8 * 256) = ph;
                *(uint32_t*)(smem + SO_HI + H_P + off + 8 * 256) = pp;
            }
        }
    }
    MBAR_WAIT(mbW, 0);
    __syncthreads();

    // attention GEMM: warp wid owns rows 16*wid..+15, all 128 att cols (2-term)
    {
        #pragma unroll
        for (int i = 0; i < 64; i++) { D1[i] = 0.f; D2[i] = 0.f; }
        uint32_t hB = sb + SO_HI + (wid * 16 + rsel) * 256;
        #pragma unroll
        for (int kt = 0; kt < 8; kt++) {
            uint32_t off = ((((uint32_t)(kt * 2 + usel)) ^ xs) << 4);
            uint32_t ah[4], ap[4];
            ldmx4(ah, hB + off); ldmx4(ap, hB + off + H_P);
            #pragma unroll
            for (int nt = 0; nt < 8; nt++) {
                uint32_t bh[4], bp[4];
                uint32_t ba = sb + SO_XA + (nt * 16 + rsel) * 256 + off;
                ldmx4(bh, ba); ldmx4(bp, ba + H_P);
                #pragma unroll
                for (int e = 0; e < 2; e++) {
                    float* d1 = D1 + (nt * 2 + e) * 4;
                    float* d2 = D2 + (nt * 2 + e) * 4;
                    mma_bf16(d1, ah, bh[e], bh[2 + e]);
                    mma_bf16(d2, ap, bp[e], bp[2 + e]);
                }
            }
        }
        float p0 = 0.f, p1 = 0.f;
        #pragma unroll
        for (int n8 = 0; n8 < 16; n8++) {
            float2 wv = *(const float2*)(w2g + n8 * 8 + (lane & 3) * 2);
            float o;
            o = fmaf(D2[n8*4+0] - D1[n8*4+0], 0.03125f, D1[n8*4+0]);
            p0 = fmaf(tanh_fast(o), wv.x, p0);
            o = fmaf(D2[n8*4+1] - D1[n8*4+1], 0.03125f, D1[n8*4+1]);
            p0 = fmaf(tanh_fast(o), wv.y, p0);
            o = fmaf(D2[n8*4+2] - D1[n8*4+2], 0.03125f, D1[n8*4+2]);
            p1 = fmaf(tanh_fast(o), wv.x, p1);
            o = fmaf(D2[n8*4+3] - D1[n8*4+3], 0.03125f, D1[n8*4+3]);
            p1 = fmaf(tanh_fast(o), wv.y, p1);
        }
        p0 += __shfl_xor_sync(0xffffffffu, p0, 1);
        p0 += __shfl_xor_sync(0xffffffffu, p0, 2);
        p1 += __shfl_xor_sync(0xffffffffu, p1, 1);
        p1 += __shfl_xor_sync(0xffffffffu, p1, 2);
        if ((lane & 3) == 0) {
            int r = node0 + wid * 16 + (lane >> 2);
            if (r < n) scores[r] = p0;
            if (r + 8 < n) scores[r + 8] = p1;
        }
    }
}

__global__ __launch_bounds__(128)
void pool_kernel(const float* __restrict__ H,
                 const float* __restrict__ scores,
                 const void* __restrict__ batch,
                 int n, float* __restrict__ out)
{
    const int gidx = blockIdx.x, tid = threadIdx.x;
    const int is64 = g_is64;
    int start, end;
    {
        int lo = 0, hi = n;
        while (lo < hi) { int mid = (lo + hi) >> 1; if (batch_at(batch, mid, is64) < gidx) lo = mid + 1; else hi = mid; }
        start = lo; hi = n;
        while (lo < hi) { int mid = (lo + hi) >> 1; if (batch_at(batch, mid, is64) < gidx + 1) lo = mid + 1; else hi = mid; }
        end = lo;
    }
    if (start >= end) { out[(size_t)gidx * M + tid] = 0.f; return; }
    __shared__ float red[128];
    float mx = -INFINITY;
    for (int i = start + tid; i < end; i += 128) mx = fmaxf(mx, scores[i]);
    red[tid] = mx; __syncthreads();
    #pragma unroll
    for (int s = 64; s; s >>= 1) { if (tid < s) red[tid] = fmaxf(red[tid], red[tid + s]); __syncthreads(); }
    mx = red[0]; __syncthreads();
    float sm = 0.f;
    for (int i = start + tid; i < end; i += 128) sm += expf(scores[i] - mx);
    red[tid] = sm; __syncthreads();
    #pragma unroll
    for (int s = 64; s; s >>= 1) { if (tid < s) red[tid] += red[tid + s]; __syncthreads(); }
    const float inv = 1.f / (red[0] + 1e-16f);
    float a0 = 0.f, a1 = 0.f, a2 = 0.f, a3 = 0.f;
    int i = start;
    for (; i + 3 < end; i += 4) {
        float w0 = exp2p(1.442695f * (scores[i]     - mx));
        float w1 = exp2p(1.442695f * (scores[i + 1] - mx));
        float w2 = exp2p(1.442695f * (scores[i + 2] - mx));
        float w3 = exp2p(1.442695f * (scores[i + 3] - mx));
        a0 = fmaf(w0, H[(size_t)i * M + tid], a0);
        a1 = fmaf(w1, H[(size_t)(i + 1) * M + tid], a1);
        a2 = fmaf(w2, H[(size_t)(i + 2) * M + tid], a2);
        a3 = fmaf(w3, H[(size_t)(i + 3) * M + tid], a3);
    }
    for (; i < end; i++)
        a0 = fmaf(exp2p(1.442695f * (scores[i] - mx)), H[(size_t)i * M + tid], a0);
    out[(size_t)gidx * M + tid] = ((a0 + a1) + (a2 + a3)) * inv;
}

extern "C" void kernel_launch(void* const* d_in, const int* in_sizes, int n_in,
                              void* d_out, int out_size)
{
    const float* x     = (const float*)d_in[0];
    const float* g     = (const float*)d_in[1];
    const float* mu    = (const float*)d_in[2];
    const float* sigma = (const float*)d_in[3];
    const float* w1    = (const float*)d_in[4];
    const float* w2    = (const float*)d_in[5];
    const void*  batch = d_in[6];

    int n = in_sizes[0] / F;
    if (n > NMAX) n = NMAX;
    int num_graphs = out_size / M;

    cudaFuncSetAttribute(node_kernel, cudaFuncAttributeMaxDynamicSharedMemorySize, SMEM_BYTES);

    float* Hg; cudaGetSymbolAddress((void**)&Hg, g_H);
    float* Sg; cudaGetSymbolAddress((void**)&Sg, g_scores);

    prep_g<<<512, 256>>>(g);
    prep_w1<<<32, 256>>>(w1);
    prep_consts<<<4, 256>>>(mu, sigma);
    sniff_kernel<<<1, 1>>>((const int*)batch, n);
    node_kernel<<<(n + NB - 1) / NB, TPB, SMEM_BYTES>>>(x, w2, Hg, Sg, n);
    pool_kernel<<<num_graphs, 128>>>(Hg, Sg, batch, n, (float*)d_out);
}

// round 10
// speedup vs baseline: 5.7426x; 1.0122x over previous
#include <cuda_runtime.h>
#include <math.h>
#include <stdint.h>

#define F      256
#define M      128
#define NMAX   200000
#define NB     128         // nodes per CTA
#define TPB    512

__device__ float g_H[(size_t)NMAX * M];
__device__ float g_scores[NMAX];
// B images: [q=0..31] each 32KB = bh(16KB) + b'(16KB); rows n:128 x 128B (64 bf16 k), XOR-swizzled
__device__ __align__(128) unsigned char g_Bimg[32 * 32768];
// w1 image: wh 32KB + w' 32KB; rows att:128 x 256B (128 bf16 m), XOR-swizzled
__device__ __align__(128) unsigned char g_W1img[65536];
__device__ float g_cA[1024], g_cB[1024], g_cC[1024];   // gaussian consts
__device__ int g_is64;

// smem layout (dynamic): A images, 3 B stages, mbarriers
#define SO_XA   0          // ah 64KB, a' at +65536 (rows node:128 x 512B swizzled)
#define XA_P    65536
#define SO_STG  131072     // 3 stages x 32768
#define STG_SZ  32768
#define B_P     16384      // b' offset within stage
#define SO_HI   131072     // attention phase: hh 32KB, h' +32768
#define H_P     32768
#define SO_RED  65536      // attention partial sums (XA_P region, free then)
#define SO_MB   229376     // mbF[3] @+0, mbE[3] @+24, mbW @+48
#define SMEM_BYTES 229440

__device__ __forceinline__ uint32_t smem_u32(const void* p) {
    uint32_t a;
    asm("{ .reg .u64 t; cvta.to.shared.u64 t, %1; cvt.u32.u64 %0, t; }" : "=r"(a) : "l"(p));
    return a;
}
#define MBAR_INIT(a, c) asm volatile("mbarrier.init.shared.b64 [%0], %1;" :: "r"((uint32_t)(a)), "r"((uint32_t)(c)) : "memory")
#define MBAR_ARRIVE(a)  asm volatile("mbarrier.arrive.shared.b64 _, [%0];" :: "r"((uint32_t)(a)) : "memory")
#define MBAR_EXPECT(a, bytes) \
    asm volatile("mbarrier.arrive.expect_tx.shared.b64 _, [%0], %1;" :: "r"((uint32_t)(a)), "r"((uint32_t)(bytes)) : "memory")
#define MBAR_WAIT(a, par) do { \
    uint32_t _m = (uint32_t)(a), _p = (uint32_t)(par), _d; \
    asm volatile("{\n\t.reg .pred p;\n\t" \
        "mbarrier.try_wait.parity.acquire.cta.shared::cta.b64 p, [%1], %2;\n\t" \
        "selp.b32 %0, 1, 0, p;\n\t}" : "=r"(_d) : "r"(_m), "r"(_p) : "memory"); \
    if (!_d) { asm volatile("{\n\t.reg .pred P1;\n\t" \
        "WL_%=:\n\t" \
        "mbarrier.try_wait.parity.acquire.cta.shared::cta.b64 P1, [%0], %1, 0x989680;\n\t" \
        "@P1 bra.uni WD_%=;\n\tbra.uni WL_%=;\n\tWD_%=:\n\t}" :: "r"(_m), "r"(_p) : "memory"); } \
    } while (0)
#define BULK_G2S(dst, src, bytes, mbar) \
    asm volatile("cp.async.bulk.shared::cta.global.mbarrier::complete_tx::bytes [%0], [%1], %2, [%3];" \
        :: "r"((uint32_t)(dst)), "l"(src), "r"((uint32_t)(bytes)), "r"((uint32_t)(mbar)) : "memory")

__device__ __forceinline__ void ldmx4(uint32_t r[4], uint32_t addr) {
    asm volatile("ldmatrix.sync.aligned.m8n8.x4.shared.b16 {%0,%1,%2,%3}, [%4];"
        : "=r"(r[0]), "=r"(r[1]), "=r"(r[2]), "=r"(r[3]) : "r"(addr));
}
__device__ __forceinline__ void mma_bf16(float* d, const uint32_t* a, uint32_t b0, uint32_t b1) {
    asm volatile("mma.sync.aligned.m16n8k16.row.col.f32.bf16.bf16.f32 "
        "{%0,%1,%2,%3}, {%4,%5,%6,%7}, {%8,%9}, {%0,%1,%2,%3};"
        : "+f"(d[0]), "+f"(d[1]), "+f"(d[2]), "+f"(d[3])
        : "r"(a[0]), "r"(a[1]), "r"(a[2]), "r"(a[3]), "r"(b0), "r"(b1));
}
// 2-term scaled split: ph = bf16x2(a,b); pp = bf16x2(ah+32*(a-ah), bh+32*(b-bh))
__device__ __forceinline__ void split2(float a, float b, uint32_t& ph, uint32_t& pp) {
    asm("cvt.rn.bf16x2.f32 %0, %1, %2;" : "=r"(ph) : "f"(b), "f"(a));
    float ah = __uint_as_float(ph << 16);
    float bh = __uint_as_float(ph & 0xffff0000u);
    float a2 = fmaf(32.f, a - ah, ah);
    float b2 = fmaf(32.f, b - bh, bh);
    asm("cvt.rn.bf16x2.f32 %0, %1, %2;" : "=r"(pp) : "f"(b2), "f"(a2));
}
// 2^y, y<=0, FMA pipe only
__device__ __forceinline__ float exp2p(float y) {
    y = fmaxf(y, -126.0f);
    float kf = __fadd_rn(y, 12582912.0f);
    int j = __float_as_int(kf) - 0x4B400000;
    float f = __fsub_rn(y, __fsub_rn(kf, 12582912.0f));
    float p = 1.3333558e-3f;
    p = fmaf(p, f, 9.6181291e-3f);
    p = fmaf(p, f, 5.5504109e-2f);
    p = fmaf(p, f, 2.4022651e-1f);
    p = fmaf(p, f, 6.9314718e-1f);
    p = fmaf(p, f, 1.0f);
    return p * __int_as_float((j + 127) << 23);
}
__device__ __forceinline__ float tanh_fast(float x) {
    float t = exp2p(-2.8853901f * fabsf(x));
    float a = 1.0f + t;
    float r = fmaf(-0.470588f, a, 1.411765f);
    r = r * (2.0f - a * r);
    r = r * (2.0f - a * r);
    r = r * (2.0f - a * r);
    return copysignf((1.0f - t) * r, x);
}

// ---- prep kernels ----
__global__ void prep_g(const float* __restrict__ g) {
    int t = blockIdx.x * 256 + threadIdx.x;      // 131072
    int q = t >> 12, r12 = t & 4095;
    int kp = r12 >> 7, nr = r12 & 127;
    int kb = (q & 3) * 64 + kp * 2;
    int nn = (q >> 2) * 128 + nr;
    uint32_t ph, pp;
    split2(g[(size_t)kb * 1024 + nn], g[(size_t)(kb + 1) * 1024 + nn], ph, pp);
    uint32_t off = nr * 128 + ((((uint32_t)(kp >> 2)) ^ (nr & 7)) << 4) + (kp & 3) * 4;
    unsigned char* base = g_Bimg + (size_t)q * 32768;
    *(uint32_t*)(base + off) = ph;
    *(uint32_t*)(base + B_P + off) = pp;
}
__global__ void prep_w1(const float* __restrict__ w1) {
    int t = blockIdx.x * 256 + threadIdx.x;      // 8192
    int att = t >> 6, mp = t & 63;
    uint32_t ph, pp;
    split2(w1[att * 128 + 2 * mp], w1[att * 128 + 2 * mp + 1], ph, pp);
    uint32_t off = att * 256 + ((((uint32_t)(mp >> 2)) ^ (att & 7)) << 4) + (mp & 3) * 4;
    *(uint32_t*)(g_W1img + off) = ph;
    *(uint32_t*)(g_W1img + H_P + off) = pp;
}
__global__ void prep_consts(const float* __restrict__ mu, const float* __restrict__ sigma) {
    int i = blockIdx.x * 256 + threadIdx.x;      // 1024
    float s = sigma[i], m_ = mu[i];
    float cc = -0.72134752f / fmaf(s, s, 1e-15f);
    g_cA[i] = cc; g_cB[i] = -2.f * cc * m_; g_cC[i] = cc * m_ * m_;
}
__global__ void sniff_kernel(const int* __restrict__ b32, int n) {
    g_is64 = (b32[n - 1] == 0) ? 1 : 0;
}
__device__ __forceinline__ int batch_at(const void* b, int i, int is64) {
    if (is64) return (int)((const long long*)b)[i];
    return ((const int*)b)[i];
}

__global__ __launch_bounds__(TPB, 1)
void node_kernel(const float* __restrict__ x,
                 const float* __restrict__ w2g,
                 float* __restrict__ Hout,
                 float* __restrict__ scores, int n)
{
    extern __shared__ unsigned char smem[];
    const uint32_t sb = smem_u32(smem);
    const uint32_t mbF = sb + SO_MB, mbE = sb + SO_MB + 24, mbW = sb + SO_MB + 48;
    const int tid = threadIdx.x, lane = tid & 31, wid = tid >> 5;
    const int rg = wid >> 2, cg = wid & 3;       // 4 row-groups x 4 col-groups
    const int rsel = lane & 15, usel = lane >> 4;
    const uint32_t xs = (uint32_t)(rsel & 7);
    const int node0 = blockIdx.x * NB;

    if (tid == 0) {
        #pragma unroll
        for (int s2 = 0; s2 < 3; s2++) { MBAR_INIT(mbF + s2 * 8, 1); MBAR_INIT(mbE + s2 * 8, 16); }
        MBAR_INIT(mbW, 1);
    }

    // A images: x[128 nodes][256] -> bf16 2-term split, swizzled 512B rows
    #pragma unroll
    for (int j = 0; j < 32; j++) {
        int i = tid + j * TPB;
        int node = i >> 7, kp = i & 127;
        int ng = node0 + node;
        float2 v = make_float2(0.f, 0.f);
        if (ng < n) v = *(const float2*)(x + (size_t)ng * F + kp * 2);
        uint32_t ph, pp; split2(v.x, v.y, ph, pp);
        uint32_t off = node * 512 + ((((uint32_t)(kp >> 2)) ^ (node & 7)) << 4) + (kp & 3) * 4;
        *(uint32_t*)(smem + SO_XA + off) = ph;
        *(uint32_t*)(smem + SO_XA + XA_P + off) = pp;
    }
    __syncthreads();   // A image + mbar init visible

    if (tid == 0) {    // prefetch chunks 0,1
        MBAR_EXPECT(mbF, 32768);
        BULK_G2S(sb + SO_STG, g_Bimg, 32768, mbF);
        MBAR_EXPECT(mbF + 8, 32768);
        BULK_G2S(sb + SO_STG + STG_SZ, g_Bimg + 32768, 32768, mbF + 8);
    }

    float H[32], D1[32], D2[32];
    #pragma unroll
    for (int i = 0; i < 32; i++) H[i] = 0.f;

    const uint32_t aBase0 = sb + SO_XA + (rg * 32 + rsel) * 512;
    const uint32_t aBase1 = aBase0 + 16 * 512;
    uint32_t bRow[2];
    #pragma unroll
    for (int nt = 0; nt < 2; nt++) bRow[nt] = (uint32_t)((cg * 32 + nt * 16 + rsel) * 128);
    const float* pa = g_cA + cg * 32 + (lane & 3) * 2;
    const float* pb = g_cB + cg * 32 + (lane & 3) * 2;
    const float* pc = g_cC + cg * 32 + (lane & 3) * 2;

    #pragma unroll 1
    for (int c = 0; c < 32; c++) {
        const int kc = c & 3;
        const int s = c % 3;
        if (tid == 0) {                    // producer: chunk c+2
            int q = c + 2;
            if (q < 32) {
                int sq = q % 3;
                if (q >= 3) MBAR_WAIT(mbE + sq * 8, ((q - 3) / 3) & 1);
                MBAR_EXPECT(mbF + sq * 8, 32768);
                BULK_G2S(sb + SO_STG + sq * STG_SZ, g_Bimg + (size_t)q * 32768, 32768, mbF + sq * 8);
            }
        }
        MBAR_WAIT(mbF + s * 8, (c / 3) & 1);
        if (kc == 0) {
            #pragma unroll
            for (int i = 0; i < 32; i++) { D1[i] = 0.f; D2[i] = 0.f; }
        }
        const uint32_t sbase = sb + SO_STG + s * STG_SZ;
        #pragma unroll
        for (int kt = 0; kt < 4; kt++) {
            uint32_t offA = ((((uint32_t)(kc * 8 + kt * 2 + usel)) ^ xs) << 4);
            uint32_t offB = ((((uint32_t)(kt * 2 + usel)) ^ xs) << 4);
            uint32_t af0[4], af1[4], bf[4];
            // hi pass -> D1
            ldmx4(af0, aBase0 + offA); ldmx4(af1, aBase1 + offA);
            #pragma unroll
            for (int nt = 0; nt < 2; nt++) {
                ldmx4(bf, sbase + bRow[nt] + offB);
                #pragma unroll
                for (int e = 0; e < 2; e++) {
                    mma_bf16(D1 + (nt * 2 + e) * 4,      af0, bf[e], bf[2 + e]);
                    mma_bf16(D1 + 16 + (nt * 2 + e) * 4, af1, bf[e], bf[2 + e]);
                }
            }
            // prime pass -> D2
            ldmx4(af0, aBase0 + offA + XA_P); ldmx4(af1, aBase1 + offA + XA_P);
            #pragma unroll
            for (int nt = 0; nt < 2; nt++) {
                ldmx4(bf, sbase + bRow[nt] + offB + B_P);
                #pragma unroll
                for (int e = 0; e < 2; e++) {
                    mma_bf16(D2 + (nt * 2 + e) * 4,      af0, bf[e], bf[2 + e]);
                    mma_bf16(D2 + 16 + (nt * 2 + e) * 4, af1, bf[e], bf[2 + e]);
                }
            }
        }
        if (lane == 0) MBAR_ARRIVE(mbE + s * 8);   // stage consumed before epilogue
        if (kc == 3) {
            const int p = c >> 2;
            #pragma unroll
            for (int n8 = 0; n8 < 4; n8++) {
                float2 a2 = *(const float2*)(pa + p * 128 + n8 * 8);
                float2 b2 = *(const float2*)(pb + p * 128 + n8 * 8);
                float2 c2 = *(const float2*)(pc + p * 128 + n8 * 8);
                #pragma unroll
                for (int sub = 0; sub < 2; sub++) {
                    float* d1 = D1 + sub * 16 + n8 * 4;
                    float* d2 = D2 + sub * 16 + n8 * 4;
                    float* h  = H  + sub * 16 + n8 * 4;
                    float o;
                    o = fmaf(d2[0] - d1[0], 0.03125f, d1[0]);
                    h[0] = fmaf(o, exp2p(fmaf(fmaf(a2.x, o, b2.x), o, c2.x)), h[0]);
                    o = fmaf(d2[1] - d1[1], 0.03125f, d1[1]);
                    h[1] = fmaf(o, exp2p(fmaf(fmaf(a2.y, o, b2.y), o, c2.y)), h[1]);
                    o = fmaf(d2[2] - d1[2], 0.03125f, d1[2]);
                    h[2] = fmaf(o, exp2p(fmaf(fmaf(a2.x, o, b2.x), o, c2.x)), h[2]);
                    o = fmaf(d2[3] - d1[3], 0.03125f, d1[3]);
                    h[3] = fmaf(o, exp2p(fmaf(fmaf(a2.y, o, b2.y), o, c2.y)), h[3]);
                }
            }
        }
    }
    __syncthreads();   // all A/stage reads done everywhere

    // w1 bulk into A region (overlaps H stores + H-image build)
    if (tid == 0) {
        MBAR_EXPECT(mbW, 65536);
        BULK_G2S(sb + SO_XA, g_W1img, 65536, mbW);
    }
    {
        #pragma unroll
        for (int sub = 0; sub < 2; sub++) {
            int r0 = node0 + rg * 32 + sub * 16 + (lane >> 2);
            #pragma unroll
            for (int n8 = 0; n8 < 4; n8++) {
                int i = sub * 16 + n8 * 4;
                int m = cg * 32 + n8 * 8 + (lane & 3) * 2;
                if (r0 < n)     *(float2*)(Hout + (size_t)r0 * M + m)       = make_float2(H[i], H[i + 1]);
                if (r0 + 8 < n) *(float2*)(Hout + (size_t)(r0 + 8) * M + m) = make_float2(H[i + 2], H[i + 3]);
            }
        }
        #pragma unroll
        for (int sub = 0; sub < 2; sub++) {
            int row0 = rg * 32 + sub * 16 + (lane >> 2);
            uint32_t rx = (uint32_t)(row0 & 7);
            #pragma unroll
            for (int n8 = 0; n8 < 4; n8++) {
                int i = sub * 16 + n8 * 4;
                uint32_t unit = (uint32_t)(cg * 4 + n8);
                uint32_t off = row0 * 256 + ((unit ^ rx) << 4) + (lane & 3) * 4;
                uint32_t ph, pp;
                split2(H[i], H[i + 1], ph, pp);
                *(uint32_t*)(smem + SO_HI + off) = ph;
                *(uint32_t*)(smem + SO_HI + H_P + off) = pp;
                split2(H[i + 2], H[i + 3], ph, pp);
                *(uint32_t*)(smem + SO_HI + off + 8 * 256) = ph;
                *(uint32_t*)(smem + SO_HI + H_P + off + 8 * 256) = pp;
            }
        }
    }
    MBAR_WAIT(mbW, 0);
    __syncthreads();

    // attention GEMM: warp = (row-16-group rw, att-col-half cq)
    {
        const int rw = wid >> 1, cq = wid & 1;
        float* sred = (float*)(smem + SO_RED);
        #pragma unroll
        for (int i = 0; i < 32; i++) { D1[i] = 0.f; D2[i] = 0.f; }
        uint32_t hB = sb + SO_HI + (rw * 16 + rsel) * 256;
        #pragma unroll
        for (int kt = 0; kt < 8; kt++) {
            uint32_t off = ((((uint32_t)(kt * 2 + usel)) ^ xs) << 4);
            uint32_t ah[4], ap[4];
            ldmx4(ah, hB + off); ldmx4(ap, hB + off + H_P);
            #pragma unroll
            for (int nt = 0; nt < 4; nt++) {
                uint32_t bh[4], bp[4];
                uint32_t ba = sb + SO_XA + (cq * 64 + nt * 16 + rsel) * 256 + off;
                ldmx4(bh, ba); ldmx4(bp, ba + H_P);
                #pragma unroll
                for (int e = 0; e < 2; e++) {
                    float* d1 = D1 + (nt * 2 + e) * 4;
                    float* d2 = D2 + (nt * 2 + e) * 4;
                    mma_bf16(d1, ah, bh[e], bh[2 + e]);
                    mma_bf16(d2, ap, bp[e], bp[2 + e]);
                }
            }
        }
        float p0 = 0.f, p1 = 0.f;
        #pragma unroll
        for (int n8 = 0; n8 < 8; n8++) {
            float2 wv = *(const float2*)(w2g + cq * 64 + n8 * 8 + (lane & 3) * 2);
            float o;
            o = fmaf(D2[n8*4+0] - D1[n8*4+0], 0.03125f, D1[n8*4+0]);
            p0 = fmaf(tanh_fast(o), wv.x, p0);
            o = fmaf(D2[n8*4+1] - D1[n8*4+1], 0.03125f, D1[n8*4+1]);
            p0 = fmaf(tanh_fast(o), wv.y, p0);
            o = fmaf(D2[n8*4+2] - D1[n8*4+2], 0.03125f, D1[n8*4+2]);
            p1 = fmaf(tanh_fast(o), wv.x, p1);
            o = fmaf(D2[n8*4+3] - D1[n8*4+3], 0.03125f, D1[n8*4+3]);
            p1 = fmaf(tanh_fast(o), wv.y, p1);
        }
        p0 += __shfl_xor_sync(0xffffffffu, p0, 1);
        p0 += __shfl_xor_sync(0xffffffffu, p0, 2);
        p1 += __shfl_xor_sync(0xffffffffu, p1, 1);
        p1 += __shfl_xor_sync(0xffffffffu, p1, 2);
        if (cq == 1 && (lane & 3) == 0) {
            sred[rw * 16 + (lane >> 2)] = p0;
            sred[rw * 16 + 8 + (lane >> 2)] = p1;
        }
        __syncthreads();
        if (cq == 0 && (lane & 3) == 0) {
            int r = node0 + rw * 16 + (lane >> 2);
            if (r < n) scores[r] = p0 + sred[rw * 16 + (lane >> 2)];
            if (r + 8 < n) scores[r + 8] = p1 + sred[rw * 16 + 8 + (lane >> 2)];
        }
    }
}

__global__ __launch_bounds__(128)
void pool_kernel(const float* __restrict__ H,
                 const float* __restrict__ scores,
                 const void* __restrict__ batch,
                 int n, float* __restrict__ out)
{
    const int gidx = blockIdx.x, tid = threadIdx.x;
    const int is64 = g_is64;
    int start, end;
    {
        int lo = 0, hi = n;
        while (lo < hi) { int mid = (lo + hi) >> 1; if (batch_at(batch, mid, is64) < gidx) lo = mid + 1; else hi = mid; }
        start = lo; hi = n;
        while (lo < hi) { int mid = (lo + hi) >> 1; if (batch_at(batch, mid, is64) < gidx + 1) lo = mid + 1; else hi = mid; }
        end = lo;
    }
    if (start >= end) { out[(size_t)gidx * M + tid] = 0.f; return; }
    __shared__ float red[128];
    float mx = -INFINITY;
    for (int i = start + tid; i < end; i += 128) mx = fmaxf(mx, scores[i]);
    red[tid] = mx; __syncthreads();
    #pragma unroll
    for (int s = 64; s; s >>= 1) { if (tid < s) red[tid] = fmaxf(red[tid], red[tid + s]); __syncthreads(); }
    mx = red[0]; __syncthreads();
    float sm = 0.f;
    for (int i = start + tid; i < end; i += 128) sm += expf(scores[i] - mx);
    red[tid] = sm; __syncthreads();
    #pragma unroll
    for (int s = 64; s; s >>= 1) { if (tid < s) red[tid] += red[tid + s]; __syncthreads(); }
    const float inv = 1.f / (red[0] + 1e-16f);
    float a0 = 0.f, a1 = 0.f, a2 = 0.f, a3 = 0.f;
    int i = start;
    for (; i + 3 < end; i += 4) {
        float w0 = exp2p(1.442695f * (scores[i]     - mx));
        float w1 = exp2p(1.442695f * (scores[i + 1] - mx));
        float w2 = exp2p(1.442695f * (scores[i + 2] - mx));
        float w3 = exp2p(1.442695f * (scores[i + 3] - mx));
        a0 = fmaf(w0, H[(size_t)i * M + tid], a0);
        a1 = fmaf(w1, H[(size_t)(i + 1) * M + tid], a1);
        a2 = fmaf(w2, H[(size_t)(i + 2) * M + tid], a2);
        a3 = fmaf(w3, H[(size_t)(i + 3) * M + tid], a3);
    }
    for (; i < end; i++)
        a0 = fmaf(exp2p(1.442695f * (scores[i] - mx)), H[(size_t)i * M + tid], a0);
    out[(size_t)gidx * M + tid] = ((a0 + a1) + (a2 + a3)) * inv;
}

extern "C" void kernel_launch(void* const* d_in, const int* in_sizes, int n_in,
                              void* d_out, int out_size)
{
    const float* x     = (const float*)d_in[0];
    const float* g     = (const float*)d_in[1];
    const float* mu    = (const float*)d_in[2];
    const float* sigma = (const float*)d_in[3];
    const float* w1    = (const float*)d_in[4];
    const float* w2    = (const float*)d_in[5];
    const void*  batch = d_in[6];

    int n = in_sizes[0] / F;
    if (n > NMAX) n = NMAX;
    int num_graphs = out_size / M;

    cudaFuncSetAttribute(node_kernel, cudaFuncAttributeMaxDynamicSharedMemorySize, SMEM_BYTES);

    float* Hg; cudaGetSymbolAddress((void**)&Hg, g_H);
    float* Sg; cudaGetSymbolAddress((void**)&Sg, g_scores);

    prep_g<<<512, 256>>>(g);
    prep_w1<<<32, 256>>>(w1);
    prep_consts<<<4, 256>>>(mu, sigma);
    sniff_kernel<<<1, 1>>>((const int*)batch, n);
    node_kernel<<<(n + NB - 1) / NB, TPB, SMEM_BYTES>>>(x, w2, Hg, Sg, n);
    pool_kernel<<<num_graphs, 128>>>(Hg, Sg, batch, n, (float*)d_out);
}

// round 11
// speedup vs baseline: 6.1531x; 1.0715x over previous
#include <cuda_runtime.h>
#include <math.h>
#include <stdint.h>

#define F      256
#define M      128
#define NMAX   200000
#define NB     128         // nodes per CTA
#define TPB    512

__device__ float g_H[(size_t)NMAX * M];
__device__ float g_scores[NMAX];
// B images: [q=0..31] each 32KB = bh(16KB) + b'(16KB); rows n:128 x 128B (64 bf16 k), XOR-swizzled
__device__ __align__(128) unsigned char g_Bimg[32 * 32768];
// w1 image: wh 32KB + w' 32KB; rows att:128 x 256B (128 bf16 m), XOR-swizzled
__device__ __align__(128) unsigned char g_W1img[65536];
__device__ float g_cA[1024], g_cB[1024], g_cC[1024];   // gaussian consts
__device__ int g_is64;

// smem layout (dynamic): A images, 3 B stages, mbarriers
#define SO_XA   0          // ah 64KB, a' at +65536 (rows node:128 x 512B swizzled)
#define XA_P    65536
#define SO_STG  131072     // 3 stages x 32768
#define STG_SZ  32768
#define B_P     16384      // b' offset within stage
#define SO_HI   131072     // attention phase: hh 32KB, h' +32768
#define H_P     32768
#define SO_RED  65536      // attention partial sums (XA_P region, free then)
#define SO_MB   229376     // mbF[3] @+0, mbE[3] @+24, mbW @+48
#define SMEM_BYTES 229440

__device__ __forceinline__ uint32_t smem_u32(const void* p) {
    uint32_t a;
    asm("{ .reg .u64 t; cvta.to.shared.u64 t, %1; cvt.u32.u64 %0, t; }" : "=r"(a) : "l"(p));
    return a;
}
#define MBAR_INIT(a, c) asm volatile("mbarrier.init.shared.b64 [%0], %1;" :: "r"((uint32_t)(a)), "r"((uint32_t)(c)) : "memory")
#define MBAR_ARRIVE(a)  asm volatile("mbarrier.arrive.shared.b64 _, [%0];" :: "r"((uint32_t)(a)) : "memory")
#define MBAR_EXPECT(a, bytes) \
    asm volatile("mbarrier.arrive.expect_tx.shared.b64 _, [%0], %1;" :: "r"((uint32_t)(a)), "r"((uint32_t)(bytes)) : "memory")
#define MBAR_WAIT(a, par) do { \
    uint32_t _m = (uint32_t)(a), _p = (uint32_t)(par), _d; \
    asm volatile("{\n\t.reg .pred p;\n\t" \
        "mbarrier.try_wait.parity.acquire.cta.shared::cta.b64 p, [%1], %2;\n\t" \
        "selp.b32 %0, 1, 0, p;\n\t}" : "=r"(_d) : "r"(_m), "r"(_p) : "memory"); \
    if (!_d) { asm volatile("{\n\t.reg .pred P1;\n\t" \
        "WL_%=:\n\t" \
        "mbarrier.try_wait.parity.acquire.cta.shared::cta.b64 P1, [%0], %1, 0x989680;\n\t" \
        "@P1 bra.uni WD_%=;\n\tbra.uni WL_%=;\n\tWD_%=:\n\t}" :: "r"(_m), "r"(_p) : "memory"); } \
    } while (0)
#define BULK_G2S(dst, src, bytes, mbar) \
    asm volatile("cp.async.bulk.shared::cta.global.mbarrier::complete_tx::bytes [%0], [%1], %2, [%3];" \
        :: "r"((uint32_t)(dst)), "l"(src), "r"((uint32_t)(bytes)), "r"((uint32_t)(mbar)) : "memory")

__device__ __forceinline__ void ldmx4(uint32_t r[4], uint32_t addr) {
    asm volatile("ldmatrix.sync.aligned.m8n8.x4.shared.b16 {%0,%1,%2,%3}, [%4];"
        : "=r"(r[0]), "=r"(r[1]), "=r"(r[2]), "=r"(r[3]) : "r"(addr));
}
__device__ __forceinline__ void mma_bf16(float* d, const uint32_t* a, uint32_t b0, uint32_t b1) {
    asm volatile("mma.sync.aligned.m16n8k16.row.col.f32.bf16.bf16.f32 "
        "{%0,%1,%2,%3}, {%4,%5,%6,%7}, {%8,%9}, {%0,%1,%2,%3};"
        : "+f"(d[0]), "+f"(d[1]), "+f"(d[2]), "+f"(d[3])
        : "r"(a[0]), "r"(a[1]), "r"(a[2]), "r"(a[3]), "r"(b0), "r"(b1));
}
// 2-term scaled split: ph = bf16x2(a,b); pp = bf16x2(ah+32*(a-ah), bh+32*(b-bh))
__device__ __forceinline__ void split2(float a, float b, uint32_t& ph, uint32_t& pp) {
    asm("cvt.rn.bf16x2.f32 %0, %1, %2;" : "=r"(ph) : "f"(b), "f"(a));
    float ah = __uint_as_float(ph << 16);
    float bh = __uint_as_float(ph & 0xffff0000u);
    float a2 = fmaf(32.f, a - ah, ah);
    float b2 = fmaf(32.f, b - bh, bh);
    asm("cvt.rn.bf16x2.f32 %0, %1, %2;" : "=r"(pp) : "f"(b2), "f"(a2));
}
// MUFU-based 2^x (underflows to 0 for very negative x, incl. -inf)
__device__ __forceinline__ float ex2f(float x) {
    float y; asm("ex2.approx.ftz.f32 %0, %1;" : "=f"(y) : "f"(x)); return y;
}
__device__ __forceinline__ float tanhf_hw(float x) {
    float y; asm("tanh.approx.f32 %0, %1;" : "=f"(y) : "f"(x)); return y;
}

// ---- prep kernels ----
__global__ void prep_g(const float* __restrict__ g) {
    int t = blockIdx.x * 256 + threadIdx.x;      // 131072
    int q = t >> 12, r12 = t & 4095;
    int kp = r12 >> 7, nr = r12 & 127;
    int kb = (q & 3) * 64 + kp * 2;
    int nn = (q >> 2) * 128 + nr;
    uint32_t ph, pp;
    split2(g[(size_t)kb * 1024 + nn], g[(size_t)(kb + 1) * 1024 + nn], ph, pp);
    uint32_t off = nr * 128 + ((((uint32_t)(kp >> 2)) ^ (nr & 7)) << 4) + (kp & 3) * 4;
    unsigned char* base = g_Bimg + (size_t)q * 32768;
    *(uint32_t*)(base + off) = ph;
    *(uint32_t*)(base + B_P + off) = pp;
}
__global__ void prep_w1(const float* __restrict__ w1) {
    int t = blockIdx.x * 256 + threadIdx.x;      // 8192
    int att = t >> 6, mp = t & 63;
    uint32_t ph, pp;
    split2(w1[att * 128 + 2 * mp], w1[att * 128 + 2 * mp + 1], ph, pp);
    uint32_t off = att * 256 + ((((uint32_t)(mp >> 2)) ^ (att & 7)) << 4) + (mp & 3) * 4;
    *(uint32_t*)(g_W1img + off) = ph;
    *(uint32_t*)(g_W1img + H_P + off) = pp;
}
__global__ void prep_consts(const float* __restrict__ mu, const float* __restrict__ sigma) {
    int i = blockIdx.x * 256 + threadIdx.x;      // 1024
    float s = sigma[i], m_ = mu[i];
    float cc = -0.72134752f / fmaf(s, s, 1e-15f);
    g_cA[i] = cc; g_cB[i] = -2.f * cc * m_; g_cC[i] = cc * m_ * m_;
}
__global__ void sniff_kernel(const int* __restrict__ b32, int n) {
    g_is64 = (b32[n - 1] == 0) ? 1 : 0;
}
__device__ __forceinline__ int batch_at(const void* b, int i, int is64) {
    if (is64) return (int)((const long long*)b)[i];
    return ((const int*)b)[i];
}

__global__ __launch_bounds__(TPB, 1)
void node_kernel(const float* __restrict__ x,
                 const float* __restrict__ w2g,
                 float* __restrict__ Hout,
                 float* __restrict__ scores, int n)
{
    extern __shared__ unsigned char smem[];
    const uint32_t sb = smem_u32(smem);
    const uint32_t mbF = sb + SO_MB, mbE = sb + SO_MB + 24, mbW = sb + SO_MB + 48;
    const int tid = threadIdx.x, lane = tid & 31, wid = tid >> 5;
    const int rg = wid >> 2, cg = wid & 3;       // 4 row-groups x 4 col-groups
    const int rsel = lane & 15, usel = lane >> 4;
    const uint32_t xs = (uint32_t)(rsel & 7);
    const int node0 = blockIdx.x * NB;

    if (tid == 0) {
        #pragma unroll
        for (int s2 = 0; s2 < 3; s2++) { MBAR_INIT(mbF + s2 * 8, 1); MBAR_INIT(mbE + s2 * 8, 16); }
        MBAR_INIT(mbW, 1);
    }

    // A images: x[128 nodes][256] -> bf16 2-term split, swizzled 512B rows
    #pragma unroll
    for (int j = 0; j < 32; j++) {
        int i = tid + j * TPB;
        int node = i >> 7, kp = i & 127;
        int ng = node0 + node;
        float2 v = make_float2(0.f, 0.f);
        if (ng < n) v = *(const float2*)(x + (size_t)ng * F + kp * 2);
        uint32_t ph, pp; split2(v.x, v.y, ph, pp);
        uint32_t off = node * 512 + ((((uint32_t)(kp >> 2)) ^ (node & 7)) << 4) + (kp & 3) * 4;
        *(uint32_t*)(smem + SO_XA + off) = ph;
        *(uint32_t*)(smem + SO_XA + XA_P + off) = pp;
    }
    __syncthreads();   // A image + mbar init visible

    if (tid == 0) {    // prefetch chunks 0,1
        MBAR_EXPECT(mbF, 32768);
        BULK_G2S(sb + SO_STG, g_Bimg, 32768, mbF);
        MBAR_EXPECT(mbF + 8, 32768);
        BULK_G2S(sb + SO_STG + STG_SZ, g_Bimg + 32768, 32768, mbF + 8);
    }

    float H[32], D1[32], D2[32];
    #pragma unroll
    for (int i = 0; i < 32; i++) H[i] = 0.f;

    const uint32_t aBase0 = sb + SO_XA + (rg * 32 + rsel) * 512;
    const uint32_t aBase1 = aBase0 + 16 * 512;
    uint32_t bRow[2];
    #pragma unroll
    for (int nt = 0; nt < 2; nt++) bRow[nt] = (uint32_t)((cg * 32 + nt * 16 + rsel) * 128);
    const float* pa = g_cA + cg * 32 + (lane & 3) * 2;
    const float* pb = g_cB + cg * 32 + (lane & 3) * 2;
    const float* pc = g_cC + cg * 32 + (lane & 3) * 2;

    #pragma unroll 1
    for (int c = 0; c < 32; c++) {
        const int kc = c & 3;
        const int s = c % 3;
        if (tid == 0) {                    // producer: chunk c+2
            int q = c + 2;
            if (q < 32) {
                int sq = q % 3;
                if (q >= 3) MBAR_WAIT(mbE + sq * 8, ((q - 3) / 3) & 1);
                MBAR_EXPECT(mbF + sq * 8, 32768);
                BULK_G2S(sb + SO_STG + sq * STG_SZ, g_Bimg + (size_t)q * 32768, 32768, mbF + sq * 8);
            }
        }
        MBAR_WAIT(mbF + s * 8, (c / 3) & 1);
        if (kc == 0) {
            #pragma unroll
            for (int i = 0; i < 32; i++) { D1[i] = 0.f; D2[i] = 0.f; }
        }
        const uint32_t sbase = sb + SO_STG + s * STG_SZ;
        #pragma unroll
        for (int kt = 0; kt < 4; kt++) {
            uint32_t offA = ((((uint32_t)(kc * 8 + kt * 2 + usel)) ^ xs) << 4);
            uint32_t offB = ((((uint32_t)(kt * 2 + usel)) ^ xs) << 4);
            uint32_t af0[4], af1[4], bf[4];
            // hi pass -> D1
            ldmx4(af0, aBase0 + offA); ldmx4(af1, aBase1 + offA);
            #pragma unroll
            for (int nt = 0; nt < 2; nt++) {
                ldmx4(bf, sbase + bRow[nt] + offB);
                #pragma unroll
                for (int e = 0; e < 2; e++) {
                    mma_bf16(D1 + (nt * 2 + e) * 4,      af0, bf[e], bf[2 + e]);
                    mma_bf16(D1 + 16 + (nt * 2 + e) * 4, af1, bf[e], bf[2 + e]);
                }
            }
            // prime pass -> D2
            ldmx4(af0, aBase0 + offA + XA_P); ldmx4(af1, aBase1 + offA + XA_P);
            #pragma unroll
            for (int nt = 0; nt < 2; nt++) {
                ldmx4(bf, sbase + bRow[nt] + offB + B_P);
                #pragma unroll
                for (int e = 0; e < 2; e++) {
                    mma_bf16(D2 + (nt * 2 + e) * 4,      af0, bf[e], bf[2 + e]);
                    mma_bf16(D2 + 16 + (nt * 2 + e) * 4, af1, bf[e], bf[2 + e]);
                }
            }
        }
        if (lane == 0) MBAR_ARRIVE(mbE + s * 8);   // stage consumed before epilogue
        if (kc == 3) {
            const int p = c >> 2;
            #pragma unroll
            for (int n8 = 0; n8 < 4; n8++) {
                float2 a2 = *(const float2*)(pa + p * 128 + n8 * 8);
                float2 b2 = *(const float2*)(pb + p * 128 + n8 * 8);
                float2 c2 = *(const float2*)(pc + p * 128 + n8 * 8);
                #pragma unroll
                for (int sub = 0; sub < 2; sub++) {
                    float* d1 = D1 + sub * 16 + n8 * 4;
                    float* d2 = D2 + sub * 16 + n8 * 4;
                    float* h  = H  + sub * 16 + n8 * 4;
                    float o;
                    o = fmaf(d2[0] - d1[0], 0.03125f, d1[0]);
                    h[0] = fmaf(o, ex2f(fmaf(fmaf(a2.x, o, b2.x), o, c2.x)), h[0]);
                    o = fmaf(d2[1] - d1[1], 0.03125f, d1[1]);
                    h[1] = fmaf(o, ex2f(fmaf(fmaf(a2.y, o, b2.y), o, c2.y)), h[1]);
                    o = fmaf(d2[2] - d1[2], 0.03125f, d1[2]);
                    h[2] = fmaf(o, ex2f(fmaf(fmaf(a2.x, o, b2.x), o, c2.x)), h[2]);
                    o = fmaf(d2[3] - d1[3], 0.03125f, d1[3]);
                    h[3] = fmaf(o, ex2f(fmaf(fmaf(a2.y, o, b2.y), o, c2.y)), h[3]);
                }
            }
        }
    }
    __syncthreads();   // all A/stage reads done everywhere

    // w1 bulk into A region (overlaps H stores + H-image build)
    if (tid == 0) {
        MBAR_EXPECT(mbW, 65536);
        BULK_G2S(sb + SO_XA, g_W1img, 65536, mbW);
    }
    {
        #pragma unroll
        for (int sub = 0; sub < 2; sub++) {
            int r0 = node0 + rg * 32 + sub * 16 + (lane >> 2);
            #pragma unroll
            for (int n8 = 0; n8 < 4; n8++) {
                int i = sub * 16 + n8 * 4;
                int m = cg * 32 + n8 * 8 + (lane & 3) * 2;
                if (r0 < n)     *(float2*)(Hout + (size_t)r0 * M + m)       = make_float2(H[i], H[i + 1]);
                if (r0 + 8 < n) *(float2*)(Hout + (size_t)(r0 + 8) * M + m) = make_float2(H[i + 2], H[i + 3]);
            }
        }
        #pragma unroll
        for (int sub = 0; sub < 2; sub++) {
            int row0 = rg * 32 + sub * 16 + (lane >> 2);
            uint32_t rx = (uint32_t)(row0 & 7);
            #pragma unroll
            for (int n8 = 0; n8 < 4; n8++) {
                int i = sub * 16 + n8 * 4;
                uint32_t unit = (uint32_t)(cg * 4 + n8);
                uint32_t off = row0 * 256 + ((unit ^ rx) << 4) + (lane & 3) * 4;
                uint32_t ph, pp;
                split2(H[i], H[i + 1], ph, pp);
                *(uint32_t*)(smem + SO_HI + off) = ph;
                *(uint32_t*)(smem + SO_HI + H_P + off) = pp;
                split2(H[i + 2], H[i + 3], ph, pp);
                *(uint32_t*)(smem + SO_HI + off + 8 * 256) = ph;
                *(uint32_t*)(smem + SO_HI + H_P + off + 8 * 256) = pp;
            }
        }
    }
    MBAR_WAIT(mbW, 0);
    __syncthreads();

    // attention GEMM: warp = (row-16-group rw, att-col-half cq)
    {
        const int rw = wid >> 1, cq = wid & 1;
        float* sred = (float*)(smem + SO_RED);
        #pragma unroll
        for (int i = 0; i < 32; i++) { D1[i] = 0.f; D2[i] = 0.f; }
        uint32_t hB = sb + SO_HI + (rw * 16 + rsel) * 256;
        #pragma unroll
        for (int kt = 0; kt < 8; kt++) {
            uint32_t off = ((((uint32_t)(kt * 2 + usel)) ^ xs) << 4);
            uint32_t ah[4], ap[4];
            ldmx4(ah, hB + off); ldmx4(ap, hB + off + H_P);
            #pragma unroll
            for (int nt = 0; nt < 4; nt++) {
                uint32_t bh[4], bp[4];
                uint32_t ba = sb + SO_XA + (cq * 64 + nt * 16 + rsel) * 256 + off;
                ldmx4(bh, ba); ldmx4(bp, ba + H_P);
                #pragma unroll
                for (int e = 0; e < 2; e++) {
                    float* d1 = D1 + (nt * 2 + e) * 4;
                    float* d2 = D2 + (nt * 2 + e) * 4;
                    mma_bf16(d1, ah, bh[e], bh[2 + e]);
                    mma_bf16(d2, ap, bp[e], bp[2 + e]);
                }
            }
        }
        float p0 = 0.f, p1 = 0.f;
        #pragma unroll
        for (int n8 = 0; n8 < 8; n8++) {
            float2 wv = *(const float2*)(w2g + cq * 64 + n8 * 8 + (lane & 3) * 2);
            float o;
            o = fmaf(D2[n8*4+0] - D1[n8*4+0], 0.03125f, D1[n8*4+0]);
            p0 = fmaf(tanhf_hw(o), wv.x, p0);
            o = fmaf(D2[n8*4+1] - D1[n8*4+1], 0.03125f, D1[n8*4+1]);
            p0 = fmaf(tanhf_hw(o), wv.y, p0);
            o = fmaf(D2[n8*4+2] - D1[n8*4+2], 0.03125f, D1[n8*4+2]);
            p1 = fmaf(tanhf_hw(o), wv.x, p1);
            o = fmaf(D2[n8*4+3] - D1[n8*4+3], 0.03125f, D1[n8*4+3]);
            p1 = fmaf(tanhf_hw(o), wv.y, p1);
        }
        p0 += __shfl_xor_sync(0xffffffffu, p0, 1);
        p0 += __shfl_xor_sync(0xffffffffu, p0, 2);
        p1 += __shfl_xor_sync(0xffffffffu, p1, 1);
        p1 += __shfl_xor_sync(0xffffffffu, p1, 2);
        if (cq == 1 && (lane & 3) == 0) {
            sred[rw * 16 + (lane >> 2)] = p0;
            sred[rw * 16 + 8 + (lane >> 2)] = p1;
        }
        __syncthreads();
        if (cq == 0 && (lane & 3) == 0) {
            int r = node0 + rw * 16 + (lane >> 2);
            if (r < n) scores[r] = p0 + sred[rw * 16 + (lane >> 2)];
            if (r + 8 < n) scores[r + 8] = p1 + sred[rw * 16 + 8 + (lane >> 2)];
        }
    }
}

__global__ __launch_bounds__(128)
void pool_kernel(const float* __restrict__ H,
                 const float* __restrict__ scores,
                 const void* __restrict__ batch,
                 int n, float* __restrict__ out)
{
    const int gidx = blockIdx.x, tid = threadIdx.x;
    const int is64 = g_is64;
    int start, end;
    {
        int lo = 0, hi = n;
        while (lo < hi) { int mid = (lo + hi) >> 1; if (batch_at(batch, mid, is64) < gidx) lo = mid + 1; else hi = mid; }
        start = lo; hi = n;
        while (lo < hi) { int mid = (lo + hi) >> 1; if (batch_at(batch, mid, is64) < gidx + 1) lo = mid + 1; else hi = mid; }
        end = lo;
    }
    if (start >= end) { out[(size_t)gidx * M + tid] = 0.f; return; }
    __shared__ float red[128];
    float mx = -INFINITY;
    for (int i = start + tid; i < end; i += 128) mx = fmaxf(mx, scores[i]);
    red[tid] = mx; __syncthreads();
    #pragma unroll
    for (int s = 64; s; s >>= 1) { if (tid < s) red[tid] = fmaxf(red[tid], red[tid + s]); __syncthreads(); }
    mx = red[0]; __syncthreads();
    float sm = 0.f;
    for (int i = start + tid; i < end; i += 128) sm += ex2f(1.442695f * (scores[i] - mx));
    red[tid] = sm; __syncthreads();
    #pragma unroll
    for (int s = 64; s; s >>= 1) { if (tid < s) red[tid] += red[tid + s]; __syncthreads(); }
    const float inv = 1.f / (red[0] + 1e-16f);
    float a0 = 0.f, a1 = 0.f, a2 = 0.f, a3 = 0.f;
    int i = start;
    for (; i + 3 < end; i += 4) {
        float w0 = ex2f(1.442695f * (scores[i]     - mx));
        float w1 = ex2f(1.442695f * (scores[i + 1] - mx));
        float w2 = ex2f(1.442695f * (scores[i + 2] - mx));
        float w3 = ex2f(1.442695f * (scores[i + 3] - mx));
        a0 = fmaf(w0, H[(size_t)i * M + tid], a0);
        a1 = fmaf(w1, H[(size_t)(i + 1) * M + tid], a1);
        a2 = fmaf(w2, H[(size_t)(i + 2) * M + tid], a2);
        a3 = fmaf(w3, H[(size_t)(i + 3) * M + tid], a3);
    }
    for (; i < end; i++)
        a0 = fmaf(ex2f(1.442695f * (scores[i] - mx)), H[(size_t)i * M + tid], a0);
    out[(size_t)gidx * M + tid] = ((a0 + a1) + (a2 + a3)) * inv;
}

extern "C" void kernel_launch(void* const* d_in, const int* in_sizes, int n_in,
                              void* d_out, int out_size)
{
    const float* x     = (const float*)d_in[0];
    const float* g     = (const float*)d_in[1];
    const float* mu    = (const float*)d_in[2];
    const float* sigma = (const float*)d_in[3];
    const float* w1    = (const float*)d_in[4];
    const float* w2    = (const float*)d_in[5];
    const void*  batch = d_in[6];

    int n = in_sizes[0] / F;
    if (n > NMAX) n = NMAX;
    int num_graphs = out_size / M;

    cudaFuncSetAttribute(node_kernel, cudaFuncAttributeMaxDynamicSharedMemorySize, SMEM_BYTES);

    float* Hg; cudaGetSymbolAddress((void**)&Hg, g_H);
    float* Sg; cudaGetSymbolAddress((void**)&Sg, g_scores);

    prep_g<<<512, 256>>>(g);
    prep_w1<<<32, 256>>>(w1);
    prep_consts<<<4, 256>>>(mu, sigma);
    sniff_kernel<<<1, 1>>>((const int*)batch, n);
    node_kernel<<<(n + NB - 1) / NB, TPB, SMEM_BYTES>>>(x, w2, Hg, Sg, n);
    pool_kernel<<<num_graphs, 128>>>(Hg, Sg, batch, n, (float*)d_out);
}

// round 12
// speedup vs baseline: 6.2635x; 1.0179x over previous
#include <cuda_runtime.h>
#include <math.h>
#include <stdint.h>

#define F      256
#define M      128
#define NMAX   200000
#define NB     128         // nodes per CTA
#define TPB    512

__device__ float g_H[(size_t)NMAX * M];
__device__ float g_scores[NMAX];
// B images: [q=0..31] each 32KB = bh(16KB) + b'(16KB); rows n:128 x 128B (64 bf16 k), XOR-swizzled
__device__ __align__(128) unsigned char g_Bimg[32 * 32768];
// w1 image: wh 32KB + w' 32KB; rows att:128 x 256B (128 bf16 m), XOR-swizzled
__device__ __align__(128) unsigned char g_W1img[65536];
__device__ float g_cA[1024], g_cB[1024], g_cC[1024];   // gaussian consts
__device__ int g_is64;

// smem layout (dynamic): A images, 3 B stages, mbarriers
#define SO_XA   0          // ah 64KB, a' at +65536 (rows node:128 x 512B swizzled)
#define XA_P    65536
#define SO_STG  131072     // 3 stages x 32768
#define STG_SZ  32768
#define B_P     16384      // b' offset within stage
#define SO_HI   131072     // attention phase: hh 32KB, h' +32768
#define H_P     32768
#define SO_RED  65536      // attention partial sums (XA_P region, free then)
#define SO_MB   229376     // mbF[3] @+0, mbE[3] @+24, mbW @+48
#define SMEM_BYTES 229440

__device__ __forceinline__ uint32_t smem_u32(const void* p) {
    uint32_t a;
    asm("{ .reg .u64 t; cvta.to.shared.u64 t, %1; cvt.u32.u64 %0, t; }" : "=r"(a) : "l"(p));
    return a;
}
#define MBAR_INIT(a, c) asm volatile("mbarrier.init.shared.b64 [%0], %1;" :: "r"((uint32_t)(a)), "r"((uint32_t)(c)) : "memory")
#define MBAR_ARRIVE(a)  asm volatile("mbarrier.arrive.shared.b64 _, [%0];" :: "r"((uint32_t)(a)) : "memory")
#define MBAR_EXPECT(a, bytes) \
    asm volatile("mbarrier.arrive.expect_tx.shared.b64 _, [%0], %1;" :: "r"((uint32_t)(a)), "r"((uint32_t)(bytes)) : "memory")
#define MBAR_WAIT(a, par) do { \
    uint32_t _m = (uint32_t)(a), _p = (uint32_t)(par), _d; \
    asm volatile("{\n\t.reg .pred p;\n\t" \
        "mbarrier.try_wait.parity.acquire.cta.shared::cta.b64 p, [%1], %2;\n\t" \
        "selp.b32 %0, 1, 0, p;\n\t}" : "=r"(_d) : "r"(_m), "r"(_p) : "memory"); \
    if (!_d) { asm volatile("{\n\t.reg .pred P1;\n\t" \
        "WL_%=:\n\t" \
        "mbarrier.try_wait.parity.acquire.cta.shared::cta.b64 P1, [%0], %1, 0x989680;\n\t" \
        "@P1 bra.uni WD_%=;\n\tbra.uni WL_%=;\n\tWD_%=:\n\t}" :: "r"(_m), "r"(_p) : "memory"); } \
    } while (0)
#define BULK_G2S(dst, src, bytes, mbar) \
    asm volatile("cp.async.bulk.shared::cta.global.mbarrier::complete_tx::bytes [%0], [%1], %2, [%3];" \
        :: "r"((uint32_t)(dst)), "l"(src), "r"((uint32_t)(bytes)), "r"((uint32_t)(mbar)) : "memory")

__device__ __forceinline__ void ldmx4(uint32_t r[4], uint32_t addr) {
    asm volatile("ldmatrix.sync.aligned.m8n8.x4.shared.b16 {%0,%1,%2,%3}, [%4];"
        : "=r"(r[0]), "=r"(r[1]), "=r"(r[2]), "=r"(r[3]) : "r"(addr));
}
__device__ __forceinline__ void mma_bf16(float* d, const uint32_t* a, uint32_t b0, uint32_t b1) {
    asm volatile("mma.sync.aligned.m16n8k16.row.col.f32.bf16.bf16.f32 "
        "{%0,%1,%2,%3}, {%4,%5,%6,%7}, {%8,%9}, {%0,%1,%2,%3};"
        : "+f"(d[0]), "+f"(d[1]), "+f"(d[2]), "+f"(d[3])
        : "r"(a[0]), "r"(a[1]), "r"(a[2]), "r"(a[3]), "r"(b0), "r"(b1));
}
// 2-term scaled split: ph = bf16x2(a,b); pp = bf16x2(ah+32*(a-ah), bh+32*(b-bh))
__device__ __forceinline__ void split2(float a, float b, uint32_t& ph, uint32_t& pp) {
    asm("cvt.rn.bf16x2.f32 %0, %1, %2;" : "=r"(ph) : "f"(b), "f"(a));
    float ah = __uint_as_float(ph << 16);
    float bh = __uint_as_float(ph & 0xffff0000u);
    float a2 = fmaf(32.f, a - ah, ah);
    float b2 = fmaf(32.f, b - bh, bh);
    asm("cvt.rn.bf16x2.f32 %0, %1, %2;" : "=r"(pp) : "f"(b2), "f"(a2));
}
// MUFU-based 2^x (underflows to 0 for very negative x, incl. -inf)
__device__ __forceinline__ float ex2f(float x) {
    float y; asm("ex2.approx.ftz.f32 %0, %1;" : "=f"(y) : "f"(x)); return y;
}
__device__ __forceinline__ float tanhf_hw(float x) {
    float y; asm("tanh.approx.f32 %0, %1;" : "=f"(y) : "f"(x)); return y;
}

// ---- prep kernels ----
__global__ void prep_g(const float* __restrict__ g) {
    int t = blockIdx.x * 256 + threadIdx.x;      // 131072
    int q = t >> 12, r12 = t & 4095;
    int kp = r12 >> 7, nr = r12 & 127;
    int kb = (q & 3) * 64 + kp * 2;
    int nn = (q >> 2) * 128 + nr;
    uint32_t ph, pp;
    split2(g[(size_t)kb * 1024 + nn], g[(size_t)(kb + 1) * 1024 + nn], ph, pp);
    uint32_t off = nr * 128 + ((((uint32_t)(kp >> 2)) ^ (nr & 7)) << 4) + (kp & 3) * 4;
    unsigned char* base = g_Bimg + (size_t)q * 32768;
    *(uint32_t*)(base + off) = ph;
    *(uint32_t*)(base + B_P + off) = pp;
}
__global__ void prep_w1(const float* __restrict__ w1) {
    int t = blockIdx.x * 256 + threadIdx.x;      // 8192
    int att = t >> 6, mp = t & 63;
    uint32_t ph, pp;
    split2(w1[att * 128 + 2 * mp], w1[att * 128 + 2 * mp + 1], ph, pp);
    uint32_t off = att * 256 + ((((uint32_t)(mp >> 2)) ^ (att & 7)) << 4) + (mp & 3) * 4;
    *(uint32_t*)(g_W1img + off) = ph;
    *(uint32_t*)(g_W1img + H_P + off) = pp;
}
__global__ void prep_consts(const float* __restrict__ mu, const float* __restrict__ sigma) {
    int i = blockIdx.x * 256 + threadIdx.x;      // 1024
    float s = sigma[i], m_ = mu[i];
    float cc = -0.72134752f / fmaf(s, s, 1e-15f);
    g_cA[i] = cc; g_cB[i] = -2.f * cc * m_; g_cC[i] = cc * m_ * m_;
}
__global__ void sniff_kernel(const int* __restrict__ b32, int n) {
    g_is64 = (b32[n - 1] == 0) ? 1 : 0;
}
__device__ __forceinline__ int batch_at(const void* b, int i, int is64) {
    if (is64) return (int)((const long long*)b)[i];
    return ((const int*)b)[i];
}

// half-pass gaussian epilogue: process 16 elements (sub half), then zero them
__device__ __forceinline__ void epi_half(float* D1, float* D2, float* H,
                                         const float* pa, const float* pb, const float* pc,
                                         int pofs, int sub)
{
    #pragma unroll
    for (int n8 = 0; n8 < 4; n8++) {
        float2 a2 = *(const float2*)(pa + pofs + n8 * 8);
        float2 b2 = *(const float2*)(pb + pofs + n8 * 8);
        float2 c2 = *(const float2*)(pc + pofs + n8 * 8);
        float* d1 = D1 + sub * 16 + n8 * 4;
        float* d2 = D2 + sub * 16 + n8 * 4;
        float* h  = H  + sub * 16 + n8 * 4;
        float o;
        o = fmaf(d2[0] - d1[0], 0.03125f, d1[0]);
        h[0] = fmaf(o, ex2f(fmaf(fmaf(a2.x, o, b2.x), o, c2.x)), h[0]);
        o = fmaf(d2[1] - d1[1], 0.03125f, d1[1]);
        h[1] = fmaf(o, ex2f(fmaf(fmaf(a2.y, o, b2.y), o, c2.y)), h[1]);
        o = fmaf(d2[2] - d1[2], 0.03125f, d1[2]);
        h[2] = fmaf(o, ex2f(fmaf(fmaf(a2.x, o, b2.x), o, c2.x)), h[2]);
        o = fmaf(d2[3] - d1[3], 0.03125f, d1[3]);
        h[3] = fmaf(o, ex2f(fmaf(fmaf(a2.y, o, b2.y), o, c2.y)), h[3]);
        d1[0] = 0.f; d1[1] = 0.f; d1[2] = 0.f; d1[3] = 0.f;
        d2[0] = 0.f; d2[1] = 0.f; d2[2] = 0.f; d2[3] = 0.f;
    }
}

__global__ __launch_bounds__(TPB, 1)
void node_kernel(const float* __restrict__ x,
                 const float* __restrict__ w2g,
                 float* __restrict__ Hout,
                 float* __restrict__ scores, int n)
{
    extern __shared__ unsigned char smem[];
    const uint32_t sb = smem_u32(smem);
    const uint32_t mbF = sb + SO_MB, mbE = sb + SO_MB + 24, mbW = sb + SO_MB + 48;
    const int tid = threadIdx.x, lane = tid & 31, wid = tid >> 5;
    const int rg = wid >> 2, cg = wid & 3;       // 4 row-groups x 4 col-groups
    const int rsel = lane & 15, usel = lane >> 4;
    const uint32_t xs = (uint32_t)(rsel & 7);
    const int node0 = blockIdx.x * NB;

    if (tid == 0) {
        #pragma unroll
        for (int s2 = 0; s2 < 3; s2++) { MBAR_INIT(mbF + s2 * 8, 1); MBAR_INIT(mbE + s2 * 8, 16); }
        MBAR_INIT(mbW, 1);
    }

    // A images: x[128 nodes][256] -> bf16 2-term split, swizzled 512B rows
    #pragma unroll
    for (int j = 0; j < 32; j++) {
        int i = tid + j * TPB;
        int node = i >> 7, kp = i & 127;
        int ng = node0 + node;
        float2 v = make_float2(0.f, 0.f);
        if (ng < n) v = *(const float2*)(x + (size_t)ng * F + kp * 2);
        uint32_t ph, pp; split2(v.x, v.y, ph, pp);
        uint32_t off = node * 512 + ((((uint32_t)(kp >> 2)) ^ (node & 7)) << 4) + (kp & 3) * 4;
        *(uint32_t*)(smem + SO_XA + off) = ph;
        *(uint32_t*)(smem + SO_XA + XA_P + off) = pp;
    }
    __syncthreads();   // A image + mbar init visible

    if (tid == 0) {    // prefetch chunks 0,1
        MBAR_EXPECT(mbF, 32768);
        BULK_G2S(sb + SO_STG, g_Bimg, 32768, mbF);
        MBAR_EXPECT(mbF + 8, 32768);
        BULK_G2S(sb + SO_STG + STG_SZ, g_Bimg + 32768, 32768, mbF + 8);
    }

    float H[32], D1[32], D2[32];
    #pragma unroll
    for (int i = 0; i < 32; i++) { H[i] = 0.f; D1[i] = 0.f; D2[i] = 0.f; }

    const uint32_t aBase0 = sb + SO_XA + (rg * 32 + rsel) * 512;
    const uint32_t aBase1 = aBase0 + 16 * 512;
    uint32_t bRow[2];
    #pragma unroll
    for (int nt = 0; nt < 2; nt++) bRow[nt] = (uint32_t)((cg * 32 + nt * 16 + rsel) * 128);
    const float* pa = g_cA + cg * 32 + (lane & 3) * 2;
    const float* pb = g_cB + cg * 32 + (lane & 3) * 2;
    const float* pc = g_cC + cg * 32 + (lane & 3) * 2;

    int s = 0;
    #pragma unroll 1
    for (int p8 = 0; p8 < 8; p8++) {
        #pragma unroll
        for (int kc = 0; kc < 4; kc++) {
            const int c = p8 * 4 + kc;
            if (tid == 0) {                    // producer: chunk c+2
                int q = c + 2;
                if (q < 32) {
                    int sq = q % 3;
                    if (q >= 3) MBAR_WAIT(mbE + sq * 8, ((q - 3) / 3) & 1);
                    MBAR_EXPECT(mbF + sq * 8, 32768);
                    BULK_G2S(sb + SO_STG + sq * STG_SZ, g_Bimg + (size_t)q * 32768, 32768, mbF + sq * 8);
                }
            }
            // deferred second-half epilogue of previous pass (overlaps DMA wait)
            if (kc == 0 && p8 > 0)
                epi_half(D1, D2, H, pa, pb, pc, (p8 - 1) * 128, 1);
            MBAR_WAIT(mbF + s * 8, (c / 3) & 1);
            const uint32_t sbase = sb + SO_STG + s * STG_SZ;
            #pragma unroll
            for (int kt = 0; kt < 4; kt++) {
                uint32_t offA = ((((uint32_t)(kc * 8 + kt * 2 + usel)) ^ xs) << 4);
                uint32_t offB = ((((uint32_t)(kt * 2 + usel)) ^ xs) << 4);
                uint32_t af0[4], af1[4], bf[4];
                // hi pass -> D1
                ldmx4(af0, aBase0 + offA); ldmx4(af1, aBase1 + offA);
                #pragma unroll
                for (int nt = 0; nt < 2; nt++) {
                    ldmx4(bf, sbase + bRow[nt] + offB);
                    #pragma unroll
                    for (int e = 0; e < 2; e++) {
                        mma_bf16(D1 + (nt * 2 + e) * 4,      af0, bf[e], bf[2 + e]);
                        mma_bf16(D1 + 16 + (nt * 2 + e) * 4, af1, bf[e], bf[2 + e]);
                    }
                }
                // prime pass -> D2
                ldmx4(af0, aBase0 + offA + XA_P); ldmx4(af1, aBase1 + offA + XA_P);
                #pragma unroll
                for (int nt = 0; nt < 2; nt++) {
                    ldmx4(bf, sbase + bRow[nt] + offB + B_P);
                    #pragma unroll
                    for (int e = 0; e < 2; e++) {
                        mma_bf16(D2 + (nt * 2 + e) * 4,      af0, bf[e], bf[2 + e]);
                        mma_bf16(D2 + 16 + (nt * 2 + e) * 4, af1, bf[e], bf[2 + e]);
                    }
                }
            }
            if (lane == 0) MBAR_ARRIVE(mbE + s * 8);   // stage consumed
            // first-half epilogue right after the pass completes
            if (kc == 3)
                epi_half(D1, D2, H, pa, pb, pc, p8 * 128, 0);
            s = (s == 2) ? 0 : s + 1;
        }
    }
    // w1 bulk into A region; final pass second-half epilogue overlaps it
    __syncthreads();   // all A/stage reads done everywhere
    if (tid == 0) {
        MBAR_EXPECT(mbW, 65536);
        BULK_G2S(sb + SO_XA, g_W1img, 65536, mbW);
    }
    epi_half(D1, D2, H, pa, pb, pc, 7 * 128, 1);
    {
        #pragma unroll
        for (int sub = 0; sub < 2; sub++) {
            int r0 = node0 + rg * 32 + sub * 16 + (lane >> 2);
            #pragma unroll
            for (int n8 = 0; n8 < 4; n8++) {
                int i = sub * 16 + n8 * 4;
                int m = cg * 32 + n8 * 8 + (lane & 3) * 2;
                if (r0 < n)     *(float2*)(Hout + (size_t)r0 * M + m)       = make_float2(H[i], H[i + 1]);
                if (r0 + 8 < n) *(float2*)(Hout + (size_t)(r0 + 8) * M + m) = make_float2(H[i + 2], H[i + 3]);
            }
        }
        #pragma unroll
        for (int sub = 0; sub < 2; sub++) {
            int row0 = rg * 32 + sub * 16 + (lane >> 2);
            uint32_t rx = (uint32_t)(row0 & 7);
            #pragma unroll
            for (int n8 = 0; n8 < 4; n8++) {
                int i = sub * 16 + n8 * 4;
                uint32_t unit = (uint32_t)(cg * 4 + n8);
                uint32_t off = row0 * 256 + ((unit ^ rx) << 4) + (lane & 3) * 4;
                uint32_t ph, pp;
                split2(H[i], H[i + 1], ph, pp);
                *(uint32_t*)(smem + SO_HI + off) = ph;
                *(uint32_t*)(smem + SO_HI + H_P + off) = pp;
                split2(H[i + 2], H[i + 3], ph, pp);
                *(uint32_t*)(smem + SO_HI + off + 8 * 256) = ph;
                *(uint32_t*)(smem + SO_HI + H_P + off + 8 * 256) = pp;
            }
        }
    }
    MBAR_WAIT(mbW, 0);
    __syncthreads();

    // attention GEMM: warp = (row-16-group rw, att-col-half cq)
    {
        const int rw = wid >> 1, cq = wid & 1;
        float* sred = (float*)(smem + SO_RED);
        #pragma unroll
        for (int i = 0; i < 32; i++) { D1[i] = 0.f; D2[i] = 0.f; }
        uint32_t hB = sb + SO_HI + (rw * 16 + rsel) * 256;
        #pragma unroll
        for (int kt = 0; kt < 8; kt++) {
            uint32_t off = ((((uint32_t)(kt * 2 + usel)) ^ xs) << 4);
            uint32_t ah[4], ap[4];
            ldmx4(ah, hB + off); ldmx4(ap, hB + off + H_P);
            #pragma unroll
            for (int nt = 0; nt < 4; nt++) {
                uint32_t bh[4], bp[4];
                uint32_t ba = sb + SO_XA + (cq * 64 + nt * 16 + rsel) * 256 + off;
                ldmx4(bh, ba); ldmx4(bp, ba + H_P);
                #pragma unroll
                for (int e = 0; e < 2; e++) {
                    float* d1 = D1 + (nt * 2 + e) * 4;
                    float* d2 = D2 + (nt * 2 + e) * 4;
                    mma_bf16(d1, ah, bh[e], bh[2 + e]);
                    mma_bf16(d2, ap, bp[e], bp[2 + e]);
                }
            }
        }
        float p0 = 0.f, p1 = 0.f;
        #pragma unroll
        for (int n8 = 0; n8 < 8; n8++) {
            float2 wv = *(const float2*)(w2g + cq * 64 + n8 * 8 + (lane & 3) * 2);
            float o;
            o = fmaf(D2[n8*4+0] - D1[n8*4+0], 0.03125f, D1[n8*4+0]);
            p0 = fmaf(tanhf_hw(o), wv.x, p0);
            o = fmaf(D2[n8*4+1] - D1[n8*4+1], 0.03125f, D1[n8*4+1]);
            p0 = fmaf(tanhf_hw(o), wv.y, p0);
            o = fmaf(D2[n8*4+2] - D1[n8*4+2], 0.03125f, D1[n8*4+2]);
            p1 = fmaf(tanhf_hw(o), wv.x, p1);
            o = fmaf(D2[n8*4+3] - D1[n8*4+3], 0.03125f, D1[n8*4+3]);
            p1 = fmaf(tanhf_hw(o), wv.y, p1);
        }
        p0 += __shfl_xor_sync(0xffffffffu, p0, 1);
        p0 += __shfl_xor_sync(0xffffffffu, p0, 2);
        p1 += __shfl_xor_sync(0xffffffffu, p1, 1);
        p1 += __shfl_xor_sync(0xffffffffu, p1, 2);
        if (cq == 1 && (lane & 3) == 0) {
            sred[rw * 16 + (lane >> 2)] = p0;
            sred[rw * 16 + 8 + (lane >> 2)] = p1;
        }
        __syncthreads();
        if (cq == 0 && (lane & 3) == 0) {
            int r = node0 + rw * 16 + (lane >> 2);
            if (r < n) scores[r] = p0 + sred[rw * 16 + (lane >> 2)];
            if (r + 8 < n) scores[r + 8] = p1 + sred[rw * 16 + 8 + (lane >> 2)];
        }
    }
}

__global__ __launch_bounds__(128)
void pool_kernel(const float* __restrict__ H,
                 const float* __restrict__ scores,
                 const void* __restrict__ batch,
                 int n, float* __restrict__ out)
{
    const int gidx = blockIdx.x, tid = threadIdx.x;
    const int is64 = g_is64;
    int start, end;
    {
        int lo = 0, hi = n;
        while (lo < hi) { int mid = (lo + hi) >> 1; if (batch_at(batch, mid, is64) < gidx) lo = mid + 1; else hi = mid; }
        start = lo; hi = n;
        while (lo < hi) { int mid = (lo + hi) >> 1; if (batch_at(batch, mid, is64) < gidx + 1) lo = mid + 1; else hi = mid; }
        end = lo;
    }
    if (start >= end) { out[(size_t)gidx * M + tid] = 0.f; return; }
    __shared__ float red[128];
    float mx = -INFINITY;
    for (int i = start + tid; i < end; i += 128) mx = fmaxf(mx, scores[i]);
    red[tid] = mx; __syncthreads();
    #pragma unroll
    for (int s = 64; s; s >>= 1) { if (tid < s) red[tid] = fmaxf(red[tid], red[tid + s]); __syncthreads(); }
    mx = red[0]; __syncthreads();
    float sm = 0.f;
    for (int i = start + tid; i < end; i += 128) sm += ex2f(1.442695f * (scores[i] - mx));
    red[tid] = sm; __syncthreads();
    #pragma unroll
    for (int s = 64; s; s >>= 1) { if (tid < s) red[tid] += red[tid + s]; __syncthreads(); }
    const float inv = 1.f / (red[0] + 1e-16f);
    float a0 = 0.f, a1 = 0.f, a2 = 0.f, a3 = 0.f;
    int i = start;
    for (; i + 3 < end; i += 4) {
        float w0 = ex2f(1.442695f * (scores[i]     - mx));
        float w1 = ex2f(1.442695f * (scores[i + 1] - mx));
        float w2 = ex2f(1.442695f * (scores[i + 2] - mx));
        float w3 = ex2f(1.442695f * (scores[i + 3] - mx));
        a0 = fmaf(w0, H[(size_t)i * M + tid], a0);
        a1 = fmaf(w1, H[(size_t)(i + 1) * M + tid], a1);
        a2 = fmaf(w2, H[(size_t)(i + 2) * M + tid], a2);
        a3 = fmaf(w3, H[(size_t)(i + 3) * M + tid], a3);
    }
    for (; i < end; i++)
        a0 = fmaf(ex2f(1.442695f * (scores[i] - mx)), H[(size_t)i * M + tid], a0);
    out[(size_t)gidx * M + tid] = ((a0 + a1) + (a2 + a3)) * inv;
}

extern "C" void kernel_launch(void* const* d_in, const int* in_sizes, int n_in,
                              void* d_out, int out_size)
{
    const float* x     = (const float*)d_in[0];
    const float* g     = (const float*)d_in[1];
    const float* mu    = (const float*)d_in[2];
    const float* sigma = (const float*)d_in[3];
    const float* w1    = (const float*)d_in[4];
    const float* w2    = (const float*)d_in[5];
    const void*  batch = d_in[6];

    int n = in_sizes[0] / F;
    if (n > NMAX) n = NMAX;
    int num_graphs = out_size / M;

    cudaFuncSetAttribute(node_kernel, cudaFuncAttributeMaxDynamicSharedMemorySize, SMEM_BYTES);

    float* Hg; cudaGetSymbolAddress((void**)&Hg, g_H);
    float* Sg; cudaGetSymbolAddress((void**)&Sg, g_scores);

    prep_g<<<512, 256>>>(g);
    prep_w1<<<32, 256>>>(w1);
    prep_consts<<<4, 256>>>(mu, sigma);
    sniff_kernel<<<1, 1>>>((const int*)batch, n);
    node_kernel<<<(n + NB - 1) / NB, TPB, SMEM_BYTES>>>(x, w2, Hg, Sg, n);
    pool_kernel<<<num_graphs, 128>>>(Hg, Sg, batch, n, (float*)d_out);
}

// round 13
// speedup vs baseline: 6.3134x; 1.0080x over previous
#include <cuda_runtime.h>
#include <math.h>
#include <stdint.h>

#define F      256
#define M      128
#define NMAX   200000
#define NB     64          // nodes per CTA (2 CTAs/SM)
#define TPB    256

__device__ float g_H[(size_t)NMAX * M];
__device__ float g_scores[NMAX];
// B images: [q=0..63] each 16KB = bh(8KB) + b'(8KB); rows n:128 x 64B (32 bf16 k), rotation-swizzled
__device__ __align__(128) unsigned char g_Bimg[64 * 16384];
// w1 image: wh 32KB + w' 32KB; rows att:128 x 256B (128 bf16 m), XOR-swizzled
__device__ __align__(128) unsigned char g_W1img[65536];
__device__ float g_cA[1024], g_cB[1024], g_cC[1024];   // gaussian consts
__device__ int g_is64;

// smem layout (per CTA, 2 CTAs/SM)
#define SO_XA   0          // A: ah 32KB, a' at +32768 (rows node:64 x 512B swizzled)
#define XA_P    32768
#define SO_STG  65536      // 3 stages x 16384
#define STG_SZ  16384
#define B_P     8192       // b' offset within stage
#define SO_HI   65536      // attention phase: hh 16KB, h' +16384
#define H_P     16384
#define SO_RED  102400     // 64 floats (stage region tail)
#define SO_MB   114688     // mbF[3] @+0, mbE[3] @+24, mbW @+48
#define SMEM_BYTES 114752

__device__ __forceinline__ uint32_t smem_u32(const void* p) {
    uint32_t a;
    asm("{ .reg .u64 t; cvta.to.shared.u64 t, %1; cvt.u32.u64 %0, t; }" : "=r"(a) : "l"(p));
    return a;
}
#define MBAR_INIT(a, c) asm volatile("mbarrier.init.shared.b64 [%0], %1;" :: "r"((uint32_t)(a)), "r"((uint32_t)(c)) : "memory")
#define MBAR_ARRIVE(a)  asm volatile("mbarrier.arrive.shared.b64 _, [%0];" :: "r"((uint32_t)(a)) : "memory")
#define MBAR_EXPECT(a, bytes) \
    asm volatile("mbarrier.arrive.expect_tx.shared.b64 _, [%0], %1;" :: "r"((uint32_t)(a)), "r"((uint32_t)(bytes)) : "memory")
#define MBAR_WAIT(a, par) do { \
    uint32_t _m = (uint32_t)(a), _p = (uint32_t)(par), _d; \
    asm volatile("{\n\t.reg .pred p;\n\t" \
        "mbarrier.try_wait.parity.acquire.cta.shared::cta.b64 p, [%1], %2;\n\t" \
        "selp.b32 %0, 1, 0, p;\n\t}" : "=r"(_d) : "r"(_m), "r"(_p) : "memory"); \
    if (!_d) { asm volatile("{\n\t.reg .pred P1;\n\t" \
        "WL_%=:\n\t" \
        "mbarrier.try_wait.parity.acquire.cta.shared::cta.b64 P1, [%0], %1, 0x989680;\n\t" \
        "@P1 bra.uni WD_%=;\n\tbra.uni WL_%=;\n\tWD_%=:\n\t}" :: "r"(_m), "r"(_p) : "memory"); } \
    } while (0)
#define BULK_G2S(dst, src, bytes, mbar) \
    asm volatile("cp.async.bulk.shared::cta.global.mbarrier::complete_tx::bytes [%0], [%1], %2, [%3];" \
        :: "r"((uint32_t)(dst)), "l"(src), "r"((uint32_t)(bytes)), "r"((uint32_t)(mbar)) : "memory")

__device__ __forceinline__ void ldmx4(uint32_t r[4], uint32_t addr) {
    asm volatile("ldmatrix.sync.aligned.m8n8.x4.shared.b16 {%0,%1,%2,%3}, [%4];"
        : "=r"(r[0]), "=r"(r[1]), "=r"(r[2]), "=r"(r[3]) : "r"(addr));
}
__device__ __forceinline__ void mma_bf16(float* d, const uint32_t* a, uint32_t b0, uint32_t b1) {
    asm volatile("mma.sync.aligned.m16n8k16.row.col.f32.bf16.bf16.f32 "
        "{%0,%1,%2,%3}, {%4,%5,%6,%7}, {%8,%9}, {%0,%1,%2,%3};"
        : "+f"(d[0]), "+f"(d[1]), "+f"(d[2]), "+f"(d[3])
        : "r"(a[0]), "r"(a[1]), "r"(a[2]), "r"(a[3]), "r"(b0), "r"(b1));
}
// 2-term scaled split: ph = bf16x2(a,b); pp = bf16x2(ah+32*(a-ah), bh+32*(b-bh))
__device__ __forceinline__ void split2(float a, float b, uint32_t& ph, uint32_t& pp) {
    asm("cvt.rn.bf16x2.f32 %0, %1, %2;" : "=r"(ph) : "f"(b), "f"(a));
    float ah = __uint_as_float(ph << 16);
    float bh = __uint_as_float(ph & 0xffff0000u);
    float a2 = fmaf(32.f, a - ah, ah);
    float b2 = fmaf(32.f, b - bh, bh);
    asm("cvt.rn.bf16x2.f32 %0, %1, %2;" : "=r"(pp) : "f"(b2), "f"(a2));
}
__device__ __forceinline__ float ex2f(float x) {
    float y; asm("ex2.approx.ftz.f32 %0, %1;" : "=f"(y) : "f"(x)); return y;
}
__device__ __forceinline__ float tanhf_hw(float x) {
    float y; asm("tanh.approx.f32 %0, %1;" : "=f"(y) : "f"(x)); return y;
}

// ---- prep: B images, k32 chunks, rotation swizzle on 64B rows ----
__global__ void prep_g(const float* __restrict__ g) {
    int t = blockIdx.x * 256 + threadIdx.x;      // 131072
    int q = t >> 11;                             // chunk 0..63
    int r11 = t & 2047;
    int kp2 = r11 >> 7, nr = r11 & 127;          // k-pair 0..15, n row
    int kb = (q & 7) * 32 + kp2 * 2;             // k within pass
    int nn = (q >> 3) * 128 + nr;
    uint32_t ph, pp;
    split2(g[(size_t)kb * 1024 + nn], g[(size_t)(kb + 1) * 1024 + nn], ph, pp);
    uint32_t off = nr * 64 + ((((uint32_t)(kp2 >> 2) + (uint32_t)(nr >> 1)) & 3) << 4) + (kp2 & 3) * 4;
    unsigned char* base = g_Bimg + (size_t)q * 16384;
    *(uint32_t*)(base + off) = ph;
    *(uint32_t*)(base + B_P + off) = pp;
}
__global__ void prep_w1(const float* __restrict__ w1) {
    int t = blockIdx.x * 256 + threadIdx.x;      // 8192
    int att = t >> 6, mp = t & 63;
    uint32_t ph, pp;
    split2(w1[att * 128 + 2 * mp], w1[att * 128 + 2 * mp + 1], ph, pp);
    uint32_t off = att * 256 + ((((uint32_t)(mp >> 2)) ^ (att & 7)) << 4) + (mp & 3) * 4;
    *(uint32_t*)(g_W1img + off) = ph;
    *(uint32_t*)(g_W1img + 32768 + off) = pp;
}
__global__ void prep_consts(const float* __restrict__ mu, const float* __restrict__ sigma) {
    int i = blockIdx.x * 256 + threadIdx.x;      // 1024
    float s = sigma[i], m_ = mu[i];
    float cc = -0.72134752f / fmaf(s, s, 1e-15f);
    g_cA[i] = cc; g_cB[i] = -2.f * cc * m_; g_cC[i] = cc * m_ * m_;
}
__global__ void sniff_kernel(const int* __restrict__ b32, int n) {
    g_is64 = (b32[n - 1] == 0) ? 1 : 0;
}
__device__ __forceinline__ int batch_at(const void* b, int i, int is64) {
    if (is64) return (int)((const long long*)b)[i];
    return ((const int*)b)[i];
}

// half-pass gaussian epilogue: 16 elements (sub half), then zero
__device__ __forceinline__ void epi_half(float* D1, float* D2, float* H,
                                         const float* pa, const float* pb, const float* pc,
                                         int pofs, int sub)
{
    #pragma unroll
    for (int n8 = 0; n8 < 4; n8++) {
        float2 a2 = *(const float2*)(pa + pofs + n8 * 8);
        float2 b2 = *(const float2*)(pb + pofs + n8 * 8);
        float2 c2 = *(const float2*)(pc + pofs + n8 * 8);
        float* d1 = D1 + sub * 16 + n8 * 4;
        float* d2 = D2 + sub * 16 + n8 * 4;
        float* h  = H  + sub * 16 + n8 * 4;
        float o;
        o = fmaf(d2[0] - d1[0], 0.03125f, d1[0]);
        h[0] = fmaf(o, ex2f(fmaf(fmaf(a2.x, o, b2.x), o, c2.x)), h[0]);
        o = fmaf(d2[1] - d1[1], 0.03125f, d1[1]);
        h[1] = fmaf(o, ex2f(fmaf(fmaf(a2.y, o, b2.y), o, c2.y)), h[1]);
        o = fmaf(d2[2] - d1[2], 0.03125f, d1[2]);
        h[2] = fmaf(o, ex2f(fmaf(fmaf(a2.x, o, b2.x), o, c2.x)), h[2]);
        o = fmaf(d2[3] - d1[3], 0.03125f, d1[3]);
        h[3] = fmaf(o, ex2f(fmaf(fmaf(a2.y, o, b2.y), o, c2.y)), h[3]);
        d1[0] = 0.f; d1[1] = 0.f; d1[2] = 0.f; d1[3] = 0.f;
        d2[0] = 0.f; d2[1] = 0.f; d2[2] = 0.f; d2[3] = 0.f;
    }
}

__global__ __launch_bounds__(TPB, 2)
void node_kernel(const float* __restrict__ x,
                 const float* __restrict__ w2g,
                 float* __restrict__ Hout,
                 float* __restrict__ scores, int n)
{
    extern __shared__ unsigned char smem[];
    const uint32_t sb = smem_u32(smem);
    const uint32_t mbF = sb + SO_MB, mbE = sb + SO_MB + 24, mbW = sb + SO_MB + 48;
    const int tid = threadIdx.x, lane = tid & 31, wid = tid >> 5;
    const int rg = wid >> 2, cg = wid & 3;       // 2 row-groups x 4 col-groups
    const int rsel = lane & 15, usel = lane >> 4;
    const uint32_t xs = (uint32_t)(rsel & 7);
    const int node0 = blockIdx.x * NB;

    if (tid == 0) {
        #pragma unroll
        for (int s2 = 0; s2 < 3; s2++) { MBAR_INIT(mbF + s2 * 8, 1); MBAR_INIT(mbE + s2 * 8, 8); }
        MBAR_INIT(mbW, 1);
    }
    __syncthreads();   // mbar init visible
    if (tid == 0) {    // prefetch chunks 0,1 (overlaps A-image build)
        MBAR_EXPECT(mbF, 16384);
        BULK_G2S(sb + SO_STG, g_Bimg, 16384, mbF);
        MBAR_EXPECT(mbF + 8, 16384);
        BULK_G2S(sb + SO_STG + STG_SZ, g_Bimg + 16384, 16384, mbF + 8);
    }

    // A images: x[64 nodes][256] -> bf16 2-term split, swizzled 512B rows
    #pragma unroll
    for (int j = 0; j < 32; j++) {
        int i = tid + j * TPB;
        int node = i >> 7, kp = i & 127;
        int ng = node0 + node;
        float2 v = make_float2(0.f, 0.f);
        if (ng < n) v = *(const float2*)(x + (size_t)ng * F + kp * 2);
        uint32_t ph, pp; split2(v.x, v.y, ph, pp);
        uint32_t off = node * 512 + ((((uint32_t)(kp >> 2)) ^ (node & 7)) << 4) + (kp & 3) * 4;
        *(uint32_t*)(smem + SO_XA + off) = ph;
        *(uint32_t*)(smem + SO_XA + XA_P + off) = pp;
    }
    __syncthreads();   // A image visible

    float H[32], D1[32], D2[32];
    #pragma unroll
    for (int i = 0; i < 32; i++) { H[i] = 0.f; D1[i] = 0.f; D2[i] = 0.f; }

    const uint32_t aBase0 = sb + SO_XA + (rg * 32 + rsel) * 512;
    const uint32_t aBase1 = aBase0 + 16 * 512;
    uint32_t bRow[2], bSh[2];
    #pragma unroll
    for (int nt = 0; nt < 2; nt++) {
        int rowB = cg * 32 + nt * 16 + rsel;
        bRow[nt] = (uint32_t)(rowB * 64);
        bSh[nt]  = (uint32_t)((rowB >> 1) & 3);
    }
    const float* pa = g_cA + cg * 32 + (lane & 3) * 2;
    const float* pb = g_cB + cg * 32 + (lane & 3) * 2;
    const float* pc = g_cC + cg * 32 + (lane & 3) * 2;

    int s = 0;
    #pragma unroll 1
    for (int p8 = 0; p8 < 8; p8++) {
        #pragma unroll
        for (int kc = 0; kc < 8; kc++) {
            const int c = p8 * 8 + kc;
            if (tid == 0) {                    // producer: chunk c+2
                int q = c + 2;
                if (q < 64) {
                    int sq = q % 3;
                    if (q >= 3) MBAR_WAIT(mbE + sq * 8, ((q - 3) / 3) & 1);
                    MBAR_EXPECT(mbF + sq * 8, 16384);
                    BULK_G2S(sb + SO_STG + sq * STG_SZ, g_Bimg + (size_t)q * 16384, 16384, mbF + sq * 8);
                }
            }
            // deferred second-half epilogue of previous pass (overlaps DMA wait)
            if (kc == 0 && p8 > 0)
                epi_half(D1, D2, H, pa, pb, pc, (p8 - 1) * 128, 1);
            MBAR_WAIT(mbF + s * 8, (c / 3) & 1);
            const uint32_t sbase = sb + SO_STG + s * STG_SZ;
            #pragma unroll
            for (int kt = 0; kt < 2; kt++) {
                const uint32_t u = (uint32_t)(kt * 2) + (uint32_t)usel;
                uint32_t offA = ((((uint32_t)(kc * 4) + u) ^ xs) << 4);
                uint32_t af0[4], af1[4], bf[4];
                // hi -> D1
                ldmx4(af0, aBase0 + offA); ldmx4(af1, aBase1 + offA);
                #pragma unroll
                for (int nt = 0; nt < 2; nt++) {
                    uint32_t ba = sbase + bRow[nt] + (((u + bSh[nt]) & 3) << 4);
                    ldmx4(bf, ba);
                    #pragma unroll
                    for (int e = 0; e < 2; e++) {
                        mma_bf16(D1 + (nt * 2 + e) * 4,      af0, bf[e], bf[2 + e]);
                        mma_bf16(D1 + 16 + (nt * 2 + e) * 4, af1, bf[e], bf[2 + e]);
                    }
                }
                // prime -> D2
                ldmx4(af0, aBase0 + offA + XA_P); ldmx4(af1, aBase1 + offA + XA_P);
                #pragma unroll
                for (int nt = 0; nt < 2; nt++) {
                    uint32_t ba = sbase + bRow[nt] + (((u + bSh[nt]) & 3) << 4) + B_P;
                    ldmx4(bf, ba);
                    #pragma unroll
                    for (int e = 0; e < 2; e++) {
                        mma_bf16(D2 + (nt * 2 + e) * 4,      af0, bf[e], bf[2 + e]);
                        mma_bf16(D2 + 16 + (nt * 2 + e) * 4, af1, bf[e], bf[2 + e]);
                    }
                }
            }
            if (lane == 0) MBAR_ARRIVE(mbE + s * 8);   // stage consumed
            if (kc == 7)
                epi_half(D1, D2, H, pa, pb, pc, p8 * 128, 0);
            s = (s == 2) ? 0 : s + 1;
        }
    }
    __syncthreads();   // all A/stage reads done

    // w1 bulk into A region; final pass second-half epilogue overlaps it
    if (tid == 0) {
        MBAR_EXPECT(mbW, 65536);
        BULK_G2S(sb + SO_XA, g_W1img, 65536, mbW);
    }
    epi_half(D1, D2, H, pa, pb, pc, 7 * 128, 1);
    {
        #pragma unroll
        for (int sub = 0; sub < 2; sub++) {
            int r0 = node0 + rg * 32 + sub * 16 + (lane >> 2);
            #pragma unroll
            for (int n8 = 0; n8 < 4; n8++) {
                int i = sub * 16 + n8 * 4;
                int m = cg * 32 + n8 * 8 + (lane & 3) * 2;
                if (r0 < n)     *(float2*)(Hout + (size_t)r0 * M + m)       = make_float2(H[i], H[i + 1]);
                if (r0 + 8 < n) *(float2*)(Hout + (size_t)(r0 + 8) * M + m) = make_float2(H[i + 2], H[i + 3]);
            }
        }
        #pragma unroll
        for (int sub = 0; sub < 2; sub++) {
            int row0 = rg * 32 + sub * 16 + (lane >> 2);
            uint32_t rx = (uint32_t)(row0 & 7);
            #pragma unroll
            for (int n8 = 0; n8 < 4; n8++) {
                int i = sub * 16 + n8 * 4;
                uint32_t unit = (uint32_t)(cg * 4 + n8);
                uint32_t off = row0 * 256 + ((unit ^ rx) << 4) + (lane & 3) * 4;
                uint32_t ph, pp;
                split2(H[i], H[i + 1], ph, pp);
                *(uint32_t*)(smem + SO_HI + off) = ph;
                *(uint32_t*)(smem + SO_HI + H_P + off) = pp;
                split2(H[i + 2], H[i + 3], ph, pp);
                *(uint32_t*)(smem + SO_HI + off + 8 * 256) = ph;
                *(uint32_t*)(smem + SO_HI + H_P + off + 8 * 256) = pp;
            }
        }
    }
    MBAR_WAIT(mbW, 0);
    __syncthreads();

    // attention GEMM: warp = (row-16-group rw 0..3, att-col-half cq)
    {
        const int rw = wid >> 1, cq = wid & 1;
        float* sred = (float*)(smem + SO_RED);
        #pragma unroll
        for (int i = 0; i < 32; i++) { D1[i] = 0.f; D2[i] = 0.f; }
        uint32_t hB = sb + SO_HI + (rw * 16 + rsel) * 256;
        #pragma unroll
        for (int kt = 0; kt < 8; kt++) {
            uint32_t off = ((((uint32_t)(kt * 2 + usel)) ^ xs) << 4);
            uint32_t ah[4], ap[4];
            ldmx4(ah, hB + off); ldmx4(ap, hB + off + H_P);
            #pragma unroll
            for (int nt = 0; nt < 4; nt++) {
                uint32_t bh[4], bp[4];
                uint32_t ba = sb + SO_XA + (cq * 64 + nt * 16 + rsel) * 256 + off;
                ldmx4(bh, ba); ldmx4(bp, ba + 32768);
                #pragma unroll
                for (int e = 0; e < 2; e++) {
                    float* d1 = D1 + (nt * 2 + e) * 4;
                    float* d2 = D2 + (nt * 2 + e) * 4;
                    mma_bf16(d1, ah, bh[e], bh[2 + e]);
                    mma_bf16(d2, ap, bp[e], bp[2 + e]);
                }
            }
        }
        float p0 = 0.f, p1 = 0.f;
        #pragma unroll
        for (int n8 = 0; n8 < 8; n8++) {
            float2 wv = *(const float2*)(w2g + cq * 64 + n8 * 8 + (lane & 3) * 2);
            float o;
            o = fmaf(D2[n8*4+0] - D1[n8*4+0], 0.03125f, D1[n8*4+0]);
            p0 = fmaf(tanhf_hw(o), wv.x, p0);
            o = fmaf(D2[n8*4+1] - D1[n8*4+1], 0.03125f, D1[n8*4+1]);
            p0 = fmaf(tanhf_hw(o), wv.y, p0);
            o = fmaf(D2[n8*4+2] - D1[n8*4+2], 0.03125f, D1[n8*4+2]);
            p1 = fmaf(tanhf_hw(o), wv.x, p1);
            o = fmaf(D2[n8*4+3] - D1[n8*4+3], 0.03125f, D1[n8*4+3]);
            p1 = fmaf(tanhf_hw(o), wv.y, p1);
        }
        p0 += __shfl_xor_sync(0xffffffffu, p0, 1);
        p0 += __shfl_xor_sync(0xffffffffu, p0, 2);
        p1 += __shfl_xor_sync(0xffffffffu, p1, 1);
        p1 += __shfl_xor_sync(0xffffffffu, p1, 2);
        if (cq == 1 && (lane & 3) == 0) {
            sred[rw * 16 + (lane >> 2)] = p0;
            sred[rw * 16 + 8 + (lane >> 2)] = p1;
        }
        __syncthreads();
        if (cq == 0 && (lane & 3) == 0) {
            int r = node0 + rw * 16 + (lane >> 2);
            if (r < n) scores[r] = p0 + sred[rw * 16 + (lane >> 2)];
            if (r + 8 < n) scores[r + 8] = p1 + sred[rw * 16 + 8 + (lane >> 2)];
        }
    }
}

__global__ __launch_bounds__(128)
void pool_kernel(const float* __restrict__ H,
                 const float* __restrict__ scores,
                 const void* __restrict__ batch,
                 int n, float* __restrict__ out)
{
    const int gidx = blockIdx.x, tid = threadIdx.x;
    const int is64 = g_is64;
    int start, end;
    {
        int lo = 0, hi = n;
        while (lo < hi) { int mid = (lo + hi) >> 1; if (batch_at(batch, mid, is64) < gidx) lo = mid + 1; else hi = mid; }
        start = lo; hi = n;
        while (lo < hi) { int mid = (lo + hi) >> 1; if (batch_at(batch, mid, is64) < gidx + 1) lo = mid + 1; else hi = mid; }
        end = lo;
    }
    if (start >= end) { out[(size_t)gidx * M + tid] = 0.f; return; }
    __shared__ float red[128];
    float mx = -INFINITY;
    for (int i = start + tid; i < end; i += 128) mx = fmaxf(mx, scores[i]);
    red[tid] = mx; __syncthreads();
    #pragma unroll
    for (int s = 64; s; s >>= 1) { if (tid < s) red[tid] = fmaxf(red[tid], red[tid + s]); __syncthreads(); }
    mx = red[0]; __syncthreads();
    float sm = 0.f;
    for (int i = start + tid; i < end; i += 128) sm += ex2f(1.442695f * (scores[i] - mx));
    red[tid] = sm; __syncthreads();
    #pragma unroll
    for (int s = 64; s; s >>= 1) { if (tid < s) red[tid] += red[tid + s]; __syncthreads(); }
    const float inv = 1.f / (red[0] + 1e-16f);
    float a0 = 0.f, a1 = 0.f, a2 = 0.f, a3 = 0.f;
    int i = start;
    for (; i + 3 < end; i += 4) {
        float w0 = ex2f(1.442695f * (scores[i]     - mx));
        float w1 = ex2f(1.442695f * (scores[i + 1] - mx));
        float w2 = ex2f(1.442695f * (scores[i + 2] - mx));
        float w3 = ex2f(1.442695f * (scores[i + 3] - mx));
        a0 = fmaf(w0, H[(size_t)i * M + tid], a0);
        a1 = fmaf(w1, H[(size_t)(i + 1) * M + tid], a1);
        a2 = fmaf(w2, H[(size_t)(i + 2) * M + tid], a2);
        a3 = fmaf(w3, H[(size_t)(i + 3) * M + tid], a3);
    }
    for (; i < end; i++)
        a0 = fmaf(ex2f(1.442695f * (scores[i] - mx)), H[(size_t)i * M + tid], a0);
    out[(size_t)gidx * M + tid] = ((a0 + a1) + (a2 + a3)) * inv;
}

extern "C" void kernel_launch(void* const* d_in, const int* in_sizes, int n_in,
                              void* d_out, int out_size)
{
    const float* x     = (const float*)d_in[0];
    const float* g     = (const float*)d_in[1];
    const float* mu    = (const float*)d_in[2];
    const float* sigma = (const float*)d_in[3];
    const float* w1    = (const float*)d_in[4];
    const float* w2    = (const float*)d_in[5];
    const void*  batch = d_in[6];

    int n = in_sizes[0] / F;
    if (n > NMAX) n = NMAX;
    int num_graphs = out_size / M;

    cudaFuncSetAttribute(node_kernel, cudaFuncAttributeMaxDynamicSharedMemorySize, SMEM_BYTES);

    float* Hg; cudaGetSymbolAddress((void**)&Hg, g_H);
    float* Sg; cudaGetSymbolAddress((void**)&Sg, g_scores);

    prep_g<<<512, 256>>>(g);
    prep_w1<<<32, 256>>>(w1);
    prep_consts<<<4, 256>>>(mu, sigma);
    sniff_kernel<<<1, 1>>>((const int*)batch, n);
    node_kernel<<<(n + NB - 1) / NB, TPB, SMEM_BYTES>>>(x, w2, Hg, Sg, n);
    pool_kernel<<<num_graphs, 128>>>(Hg, Sg, batch, n, (float*)d_out);
}

// round 14
// speedup vs baseline: 6.6363x; 1.0511x over previous
#include <cuda_runtime.h>
#include <math.h>
#include <stdint.h>

#define F      256
#define M      128
#define NMAX   200000
#define NB     64          // nodes per CTA (2 CTAs/SM)
#define TPB    256

__device__ float g_H[(size_t)NMAX * M];
__device__ float g_scores[NMAX];
// B images: [q=0..63] each 16KB = bh(8KB) + b'(8KB); rows n:128 x 64B (32 bf16 k), rotation-swizzled
__device__ __align__(128) unsigned char g_Bimg[64 * 16384];
// w1 image: wh 32KB + w' 32KB; rows att:128 x 256B (128 bf16 m), XOR-swizzled
__device__ __align__(128) unsigned char g_W1img[65536];
__device__ float g_cA[1024], g_cB[1024], g_cC[1024];   // gaussian consts
__device__ int g_is64;

// smem layout (per CTA, 2 CTAs/SM)
#define SO_XA   0          // A: ah 32KB, a' at +32768 (rows node:64 x 512B swizzled)
#define XA_P    32768
#define SO_STG  65536      // 3 stages x 16384
#define STG_SZ  16384
#define B_P     8192       // b' offset within stage
#define SO_HI   65536      // attention phase: hh 16KB, h' +16384
#define H_P     16384
#define SO_RED  102400     // 64 floats (stage region tail)
#define SO_MB   114688     // mbF[3] @+0, mbE[3] @+24, mbW @+48
#define SMEM_BYTES 114752

__device__ __forceinline__ uint32_t smem_u32(const void* p) {
    uint32_t a;
    asm("{ .reg .u64 t; cvta.to.shared.u64 t, %1; cvt.u32.u64 %0, t; }" : "=r"(a) : "l"(p));
    return a;
}
#define MBAR_INIT(a, c) asm volatile("mbarrier.init.shared.b64 [%0], %1;" :: "r"((uint32_t)(a)), "r"((uint32_t)(c)) : "memory")
#define MBAR_ARRIVE(a)  asm volatile("mbarrier.arrive.shared.b64 _, [%0];" :: "r"((uint32_t)(a)) : "memory")
#define MBAR_EXPECT(a, bytes) \
    asm volatile("mbarrier.arrive.expect_tx.shared.b64 _, [%0], %1;" :: "r"((uint32_t)(a)), "r"((uint32_t)(bytes)) : "memory")
#define MBAR_WAIT(a, par) do { \
    uint32_t _m = (uint32_t)(a), _p = (uint32_t)(par), _d; \
    asm volatile("{\n\t.reg .pred p;\n\t" \
        "mbarrier.try_wait.parity.acquire.cta.shared::cta.b64 p, [%1], %2;\n\t" \
        "selp.b32 %0, 1, 0, p;\n\t}" : "=r"(_d) : "r"(_m), "r"(_p) : "memory"); \
    if (!_d) { asm volatile("{\n\t.reg .pred P1;\n\t" \
        "WL_%=:\n\t" \
        "mbarrier.try_wait.parity.acquire.cta.shared::cta.b64 P1, [%0], %1, 0x989680;\n\t" \
        "@P1 bra.uni WD_%=;\n\tbra.uni WL_%=;\n\tWD_%=:\n\t}" :: "r"(_m), "r"(_p) : "memory"); } \
    } while (0)
#define BULK_G2S(dst, src, bytes, mbar) \
    asm volatile("cp.async.bulk.shared::cta.global.mbarrier::complete_tx::bytes [%0], [%1], %2, [%3];" \
        :: "r"((uint32_t)(dst)), "l"(src), "r"((uint32_t)(bytes)), "r"((uint32_t)(mbar)) : "memory")

__device__ __forceinline__ void ldmx4(uint32_t r[4], uint32_t addr) {
    asm volatile("ldmatrix.sync.aligned.m8n8.x4.shared.b16 {%0,%1,%2,%3}, [%4];"
        : "=r"(r[0]), "=r"(r[1]), "=r"(r[2]), "=r"(r[3]) : "r"(addr));
}
__device__ __forceinline__ void mma_bf16(float* d, const uint32_t* a, uint32_t b0, uint32_t b1) {
    asm volatile("mma.sync.aligned.m16n8k16.row.col.f32.bf16.bf16.f32 "
        "{%0,%1,%2,%3}, {%4,%5,%6,%7}, {%8,%9}, {%0,%1,%2,%3};"
        : "+f"(d[0]), "+f"(d[1]), "+f"(d[2]), "+f"(d[3])
        : "r"(a[0]), "r"(a[1]), "r"(a[2]), "r"(a[3]), "r"(b0), "r"(b1));
}
// 2-term scaled split: ph = bf16x2(a,b); pp = bf16x2(ah+32*(a-ah), bh+32*(b-bh))
__device__ __forceinline__ void split2(float a, float b, uint32_t& ph, uint32_t& pp) {
    asm("cvt.rn.bf16x2.f32 %0, %1, %2;" : "=r"(ph) : "f"(b), "f"(a));
    float ah = __uint_as_float(ph << 16);
    float bh = __uint_as_float(ph & 0xffff0000u);
    float a2 = fmaf(32.f, a - ah, ah);
    float b2 = fmaf(32.f, b - bh, bh);
    asm("cvt.rn.bf16x2.f32 %0, %1, %2;" : "=r"(pp) : "f"(b2), "f"(a2));
}
__device__ __forceinline__ float ex2f(float x) {
    float y; asm("ex2.approx.ftz.f32 %0, %1;" : "=f"(y) : "f"(x)); return y;
}
__device__ __forceinline__ float tanhf_hw(float x) {
    float y; asm("tanh.approx.f32 %0, %1;" : "=f"(y) : "f"(x)); return y;
}

// ---- prep: B images, k32 chunks, rotation swizzle on 64B rows ----
__global__ void prep_g(const float* __restrict__ g) {
    int t = blockIdx.x * 256 + threadIdx.x;      // 131072
    int q = t >> 11;                             // chunk 0..63
    int r11 = t & 2047;
    int kp2 = r11 >> 7, nr = r11 & 127;          // k-pair 0..15, n row
    int kb = (q & 7) * 32 + kp2 * 2;             // k within pass
    int nn = (q >> 3) * 128 + nr;
    uint32_t ph, pp;
    split2(g[(size_t)kb * 1024 + nn], g[(size_t)(kb + 1) * 1024 + nn], ph, pp);
    uint32_t off = nr * 64 + ((((uint32_t)(kp2 >> 2) + (uint32_t)(nr >> 1)) & 3) << 4) + (kp2 & 3) * 4;
    unsigned char* base = g_Bimg + (size_t)q * 16384;
    *(uint32_t*)(base + off) = ph;
    *(uint32_t*)(base + B_P + off) = pp;
}
__global__ void prep_w1(const float* __restrict__ w1) {
    int t = blockIdx.x * 256 + threadIdx.x;      // 8192
    int att = t >> 6, mp = t & 63;
    uint32_t ph, pp;
    split2(w1[att * 128 + 2 * mp], w1[att * 128 + 2 * mp + 1], ph, pp);
    uint32_t off = att * 256 + ((((uint32_t)(mp >> 2)) ^ (att & 7)) << 4) + (mp & 3) * 4;
    *(uint32_t*)(g_W1img + off) = ph;
    *(uint32_t*)(g_W1img + 32768 + off) = pp;
}
// consts + batch-dtype sniff merged (keeps node_kernel as the 4th launch for ncu)
__global__ void prep_misc(const float* __restrict__ mu, const float* __restrict__ sigma,
                          const int* __restrict__ b32, int n) {
    int i = blockIdx.x * 256 + threadIdx.x;      // 1024
    float s = sigma[i], m_ = mu[i];
    float cc = -0.72134752f / fmaf(s, s, 1e-15f);
    g_cA[i] = cc; g_cB[i] = -2.f * cc * m_; g_cC[i] = cc * m_ * m_;
    if (i == 0) g_is64 = (b32[n - 1] == 0) ? 1 : 0;
}
__device__ __forceinline__ int batch_at(const void* b, int i, int is64) {
    if (is64) return (int)((const long long*)b)[i];
    return ((const int*)b)[i];
}

// half-pass gaussian epilogue: 16 elements (sub half), then zero
__device__ __forceinline__ void epi_half(float* D1, float* D2, float* H,
                                         const float* pa, const float* pb, const float* pc,
                                         int pofs, int sub)
{
    #pragma unroll
    for (int n8 = 0; n8 < 4; n8++) {
        float2 a2 = *(const float2*)(pa + pofs + n8 * 8);
        float2 b2 = *(const float2*)(pb + pofs + n8 * 8);
        float2 c2 = *(const float2*)(pc + pofs + n8 * 8);
        float* d1 = D1 + sub * 16 + n8 * 4;
        float* d2 = D2 + sub * 16 + n8 * 4;
        float* h  = H  + sub * 16 + n8 * 4;
        float o;
        o = fmaf(d2[0] - d1[0], 0.03125f, d1[0]);
        h[0] = fmaf(o, ex2f(fmaf(fmaf(a2.x, o, b2.x), o, c2.x)), h[0]);
        o = fmaf(d2[1] - d1[1], 0.03125f, d1[1]);
        h[1] = fmaf(o, ex2f(fmaf(fmaf(a2.y, o, b2.y), o, c2.y)), h[1]);
        o = fmaf(d2[2] - d1[2], 0.03125f, d1[2]);
        h[2] = fmaf(o, ex2f(fmaf(fmaf(a2.x, o, b2.x), o, c2.x)), h[2]);
        o = fmaf(d2[3] - d1[3], 0.03125f, d1[3]);
        h[3] = fmaf(o, ex2f(fmaf(fmaf(a2.y, o, b2.y), o, c2.y)), h[3]);
        d1[0] = 0.f; d1[1] = 0.f; d1[2] = 0.f; d1[3] = 0.f;
        d2[0] = 0.f; d2[1] = 0.f; d2[2] = 0.f; d2[3] = 0.f;
    }
}

__global__ __launch_bounds__(TPB, 2)
void node_kernel(const float* __restrict__ x,
                 const float* __restrict__ w2g,
                 float* __restrict__ Hout,
                 float* __restrict__ scores, int n)
{
    extern __shared__ unsigned char smem[];
    const uint32_t sb = smem_u32(smem);
    const uint32_t mbF = sb + SO_MB, mbE = sb + SO_MB + 24, mbW = sb + SO_MB + 48;
    const int tid = threadIdx.x, lane = tid & 31, wid = tid >> 5;
    const int rg = wid >> 2, cg = wid & 3;       // 2 row-groups x 4 col-groups
    const int rsel = lane & 15, usel = lane >> 4;
    const uint32_t xs = (uint32_t)(rsel & 7);
    const int node0 = blockIdx.x * NB;

    if (tid == 0) {
        #pragma unroll
        for (int s2 = 0; s2 < 3; s2++) { MBAR_INIT(mbF + s2 * 8, 1); MBAR_INIT(mbE + s2 * 8, 8); }
        MBAR_INIT(mbW, 1);
    }
    __syncthreads();   // mbar init visible
    if (tid == 0) {    // prefetch chunks 0,1 (overlaps A-image build)
        MBAR_EXPECT(mbF, 16384);
        BULK_G2S(sb + SO_STG, g_Bimg, 16384, mbF);
        MBAR_EXPECT(mbF + 8, 16384);
        BULK_G2S(sb + SO_STG + STG_SZ, g_Bimg + 16384, 16384, mbF + 8);
    }

    // A images: x[64 nodes][256] -> bf16 2-term split, swizzled 512B rows
    #pragma unroll
    for (int j = 0; j < 32; j++) {
        int i = tid + j * TPB;
        int node = i >> 7, kp = i & 127;
        int ng = node0 + node;
        float2 v = make_float2(0.f, 0.f);
        if (ng < n) v = *(const float2*)(x + (size_t)ng * F + kp * 2);
        uint32_t ph, pp; split2(v.x, v.y, ph, pp);
        uint32_t off = node * 512 + ((((uint32_t)(kp >> 2)) ^ (node & 7)) << 4) + (kp & 3) * 4;
        *(uint32_t*)(smem + SO_XA + off) = ph;
        *(uint32_t*)(smem + SO_XA + XA_P + off) = pp;
    }
    __syncthreads();   // A image visible

    float H[32], D1[32], D2[32];
    #pragma unroll
    for (int i = 0; i < 32; i++) { H[i] = 0.f; D1[i] = 0.f; D2[i] = 0.f; }

    const uint32_t aBase0 = sb + SO_XA + (rg * 32 + rsel) * 512;
    const uint32_t aBase1 = aBase0 + 16 * 512;
    uint32_t bRow[2], bSh[2];
    #pragma unroll
    for (int nt = 0; nt < 2; nt++) {
        int rowB = cg * 32 + nt * 16 + rsel;
        bRow[nt] = (uint32_t)(rowB * 64);
        bSh[nt]  = (uint32_t)((rowB >> 1) & 3);
    }
    const float* pa = g_cA + cg * 32 + (lane & 3) * 2;
    const float* pb = g_cB + cg * 32 + (lane & 3) * 2;
    const float* pc = g_cC + cg * 32 + (lane & 3) * 2;

    // incremental parity state (consumer + producer), replaces per-chunk /3
    int s = 0, fpar = 0;
    int sq = 2, epar = 0, ecnt = 0;   // producer: stage of q=c+2; mbE parity counter
    #pragma unroll 1
    for (int p8 = 0; p8 < 8; p8++) {
        #pragma unroll
        for (int kc = 0; kc < 8; kc++) {
            const int c = p8 * 8 + kc;
            if (tid == 0) {                    // producer: chunk c+2
                int q = c + 2;
                if (q < 64) {
                    if (q >= 3) MBAR_WAIT(mbE + sq * 8, epar);
                    MBAR_EXPECT(mbF + sq * 8, 16384);
                    BULK_G2S(sb + SO_STG + sq * STG_SZ, g_Bimg + (size_t)q * 16384, 16384, mbF + sq * 8);
                }
            }
            // deferred second-half epilogue of previous pass (overlaps DMA wait)
            if (kc == 0 && p8 > 0)
                epi_half(D1, D2, H, pa, pb, pc, (p8 - 1) * 128, 1);
            MBAR_WAIT(mbF + s * 8, fpar);
            const uint32_t sbase = sb + SO_STG + s * STG_SZ;
            #pragma unroll
            for (int kt = 0; kt < 2; kt++) {
                const uint32_t u = (uint32_t)(kt * 2) + (uint32_t)usel;
                uint32_t offA = ((((uint32_t)(kc * 4) + u) ^ xs) << 4);
                uint32_t af0[4], af1[4], bf[4];
                // hi -> D1
                ldmx4(af0, aBase0 + offA); ldmx4(af1, aBase1 + offA);
                #pragma unroll
                for (int nt = 0; nt < 2; nt++) {
                    uint32_t ba = sbase + bRow[nt] + (((u + bSh[nt]) & 3) << 4);
                    ldmx4(bf, ba);
                    #pragma unroll
                    for (int e = 0; e < 2; e++) {
                        mma_bf16(D1 + (nt * 2 + e) * 4,      af0, bf[e], bf[2 + e]);
                        mma_bf16(D1 + 16 + (nt * 2 + e) * 4, af1, bf[e], bf[2 + e]);
                    }
                }
                // prime -> D2
                ldmx4(af0, aBase0 + offA + XA_P); ldmx4(af1, aBase1 + offA + XA_P);
                #pragma unroll
                for (int nt = 0; nt < 2; nt++) {
                    uint32_t ba = sbase + bRow[nt] + (((u + bSh[nt]) & 3) << 4) + B_P;
                    ldmx4(bf, ba);
                    #pragma unroll
                    for (int e = 0; e < 2; e++) {
                        mma_bf16(D2 + (nt * 2 + e) * 4,      af0, bf[e], bf[2 + e]);
                        mma_bf16(D2 + 16 + (nt * 2 + e) * 4, af1, bf[e], bf[2 + e]);
                    }
                }
            }
            if (lane == 0) MBAR_ARRIVE(mbE + s * 8);   // stage consumed
            if (kc == 7)
                epi_half(D1, D2, H, pa, pb, pc, p8 * 128, 0);
            // advance consumer stage + parity
            if (s == 2) { s = 0; fpar ^= 1; } else s++;
            // advance producer stage + mbE parity (parity flips every 3 chunks past q>=3)
            if (tid == 0) {
                if (c + 2 >= 3) { if (++ecnt == 3) { ecnt = 0; epar ^= 1; } }
                sq = (sq == 2) ? 0 : sq + 1;
            }
        }
    }
    __syncthreads();   // all A/stage reads done

    // w1 bulk into A region; final pass second-half epilogue overlaps it
    if (tid == 0) {
        MBAR_EXPECT(mbW, 65536);
        BULK_G2S(sb + SO_XA, g_W1img, 65536, mbW);
    }
    epi_half(D1, D2, H, pa, pb, pc, 7 * 128, 1);
    {
        #pragma unroll
        for (int sub = 0; sub < 2; sub++) {
            int r0 = node0 + rg * 32 + sub * 16 + (lane >> 2);
            #pragma unroll
            for (int n8 = 0; n8 < 4; n8++) {
                int i = sub * 16 + n8 * 4;
                int m = cg * 32 + n8 * 8 + (lane & 3) * 2;
                if (r0 < n)     *(float2*)(Hout + (size_t)r0 * M + m)       = make_float2(H[i], H[i + 1]);
                if (r0 + 8 < n) *(float2*)(Hout + (size_t)(r0 + 8) * M + m) = make_float2(H[i + 2], H[i + 3]);
            }
        }
        #pragma unroll
        for (int sub = 0; sub < 2; sub++) {
            int row0 = rg * 32 + sub * 16 + (lane >> 2);
            uint32_t rx = (uint32_t)(row0 & 7);
            #pragma unroll
            for (int n8 = 0; n8 < 4; n8++) {
                int i = sub * 16 + n8 * 4;
                uint32_t unit = (uint32_t)(cg * 4 + n8);
                uint32_t off = row0 * 256 + ((unit ^ rx) << 4) + (lane & 3) * 4;
                uint32_t ph, pp;
                split2(H[i], H[i + 1], ph, pp);
                *(uint32_t*)(smem + SO_HI + off) = ph;
                *(uint32_t*)(smem + SO_HI + H_P + off) = pp;
                split2(H[i + 2], H[i + 3], ph, pp);
                *(uint32_t*)(smem + SO_HI + off + 8 * 256) = ph;
                *(uint32_t*)(smem + SO_HI + H_P + off + 8 * 256) = pp;
            }
        }
    }
    MBAR_WAIT(mbW, 0);
    __syncthreads();

    // attention GEMM: warp = (row-16-group rw 0..3, att-col-half cq)
    {
        const int rw = wid >> 1, cq = wid & 1;
        float* sred = (float*)(smem + SO_RED);
        #pragma unroll
        for (int i = 0; i < 32; i++) { D1[i] = 0.f; D2[i] = 0.f; }
        uint32_t hB = sb + SO_HI + (rw * 16 + rsel) * 256;
        #pragma unroll
        for (int kt = 0; kt < 8; kt++) {
            uint32_t off = ((((uint32_t)(kt * 2 + usel)) ^ xs) << 4);
            uint32_t ah[4], ap[4];
            ldmx4(ah, hB + off); ldmx4(ap, hB + off + H_P);
            #pragma unroll
            for (int nt = 0; nt < 4; nt++) {
                uint32_t bh[4], bp[4];
                uint32_t ba = sb + SO_XA + (cq * 64 + nt * 16 + rsel) * 256 + off;
                ldmx4(bh, ba); ldmx4(bp, ba + 32768);
                #pragma unroll
                for (int e = 0; e < 2; e++) {
                    float* d1 = D1 + (nt * 2 + e) * 4;
                    float* d2 = D2 + (nt * 2 + e) * 4;
                    mma_bf16(d1, ah, bh[e], bh[2 + e]);
                    mma_bf16(d2, ap, bp[e], bp[2 + e]);
                }
            }
        }
        float p0 = 0.f, p1 = 0.f;
        #pragma unroll
        for (int n8 = 0; n8 < 8; n8++) {
            float2 wv = *(const float2*)(w2g + cq * 64 + n8 * 8 + (lane & 3) * 2);
            float o;
            o = fmaf(D2[n8*4+0] - D1[n8*4+0], 0.03125f, D1[n8*4+0]);
            p0 = fmaf(tanhf_hw(o), wv.x, p0);
            o = fmaf(D2[n8*4+1] - D1[n8*4+1], 0.03125f, D1[n8*4+1]);
            p0 = fmaf(tanhf_hw(o), wv.y, p0);
            o = fmaf(D2[n8*4+2] - D1[n8*4+2], 0.03125f, D1[n8*4+2]);
            p1 = fmaf(tanhf_hw(o), wv.x, p1);
            o = fmaf(D2[n8*4+3] - D1[n8*4+3], 0.03125f, D1[n8*4+3]);
            p1 = fmaf(tanhf_hw(o), wv.y, p1);
        }
        p0 += __shfl_xor_sync(0xffffffffu, p0, 1);
        p0 += __shfl_xor_sync(0xffffffffu, p0, 2);
        p1 += __shfl_xor_sync(0xffffffffu, p1, 1);
        p1 += __shfl_xor_sync(0xffffffffu, p1, 2);
        if (cq == 1 && (lane & 3) == 0) {
            sred[rw * 16 + (lane >> 2)] = p0;
            sred[rw * 16 + 8 + (lane >> 2)] = p1;
        }
        __syncthreads();
        if (cq == 0 && (lane & 3) == 0) {
            int r = node0 + rw * 16 + (lane >> 2);
            if (r < n) scores[r] = p0 + sred[rw * 16 + (lane >> 2)];
            if (r + 8 < n) scores[r + 8] = p1 + sred[rw * 16 + 8 + (lane >> 2)];
        }
    }
}

__global__ __launch_bounds__(256)
void pool_kernel(const float* __restrict__ H,
                 const float* __restrict__ scores,
                 const void* __restrict__ batch,
                 int n, float* __restrict__ out)
{
    const int gidx = blockIdx.x, tid = threadIdx.x;
    const int m = tid & 127, half = tid >> 7;
    const int is64 = g_is64;
    int start, end;
    {
        int lo = 0, hi = n;
        while (lo < hi) { int mid = (lo + hi) >> 1; if (batch_at(batch, mid, is64) < gidx) lo = mid + 1; else hi = mid; }
        start = lo; hi = n;
        while (lo < hi) { int mid = (lo + hi) >> 1; if (batch_at(batch, mid, is64) < gidx + 1) lo = mid + 1; else hi = mid; }
        end = lo;
    }
    if (start >= end) { if (half == 0) out[(size_t)gidx * M + m] = 0.f; return; }
    __shared__ float red[256];
    float mx = -INFINITY;
    for (int i = start + tid; i < end; i += 256) mx = fmaxf(mx, scores[i]);
    red[tid] = mx; __syncthreads();
    #pragma unroll
    for (int s = 128; s; s >>= 1) { if (tid < s) red[tid] = fmaxf(red[tid], red[tid + s]); __syncthreads(); }
    mx = red[0]; __syncthreads();
    float sm = 0.f;
    for (int i = start + tid; i < end; i += 256) sm += ex2f(1.442695f * (scores[i] - mx));
    red[tid] = sm; __syncthreads();
    #pragma unroll
    for (int s = 128; s; s >>= 1) { if (tid < s) red[tid] += red[tid + s]; __syncthreads(); }
    const float inv = 1.f / (red[0] + 1e-16f);
    __syncthreads();   // done reading red before reuse
    // weighted sum: two halves interleave rows (stride 2), 4-way unroll each
    float a0 = 0.f, a1 = 0.f, a2 = 0.f, a3 = 0.f;
    int i = start + half;
    for (; i + 6 < end; i += 8) {
        float w0 = ex2f(1.442695f * (scores[i]     - mx));
        float w1 = ex2f(1.442695f * (scores[i + 2] - mx));
        float w2 = ex2f(1.442695f * (scores[i + 4] - mx));
        float w3 = ex2f(1.442695f * (scores[i + 6] - mx));
        a0 = fmaf(w0, H[(size_t)i * M + m], a0);
        a1 = fmaf(w1, H[(size_t)(i + 2) * M + m], a1);
        a2 = fmaf(w2, H[(size_t)(i + 4) * M + m], a2);
        a3 = fmaf(w3, H[(size_t)(i + 6) * M + m], a3);
    }
    for (; i < end; i += 2)
        a0 = fmaf(ex2f(1.442695f * (scores[i] - mx)), H[(size_t)i * M + m], a0);
    red[tid] = (a0 + a1) + (a2 + a3);
    __syncthreads();
    if (half == 0)
        out[(size_t)gidx * M + m] = (red[m] + red[m + 128]) * inv;
}

extern "C" void kernel_launch(void* const* d_in, const int* in_sizes, int n_in,
                              void* d_out, int out_size)
{
    const float* x     = (const float*)d_in[0];
    const float* g     = (const float*)d_in[1];
    const float* mu    = (const float*)d_in[2];
    const float* sigma = (const float*)d_in[3];
    const float* w1    = (const float*)d_in[4];
    const float* w2    = (const float*)d_in[5];
    const void*  batch = d_in[6];

    int n = in_sizes[0] / F;
    if (n > NMAX) n = NMAX;
    int num_graphs = out_size / M;

    cudaFuncSetAttribute(node_kernel, cudaFuncAttributeMaxDynamicSharedMemorySize, SMEM_BYTES);

    float* Hg; cudaGetSymbolAddress((void**)&Hg, g_H);
    float* Sg; cudaGetSymbolAddress((void**)&Sg, g_scores);

    prep_g<<<512, 256>>>(g);
    prep_w1<<<32, 256>>>(w1);
    prep_misc<<<4, 256>>>(mu, sigma, (const int*)batch, n);
    node_kernel<<<(n + NB - 1) / NB, TPB, SMEM_BYTES>>>(x, w2, Hg, Sg, n);   // 4th launch -> ncu capture
    pool_kernel<<<num_graphs, 256>>>(Hg, Sg, batch, n, (float*)d_out);
}